// round 8
// baseline (speedup 1.0000x reference)
#include <cuda_runtime.h>
#include <math.h>
#include <stdint.h>

#define N_NODES 50000
#define N_EDGES 600000
#define N_GRAPHS 64
#define HID 128
#define IN_DIM 16
#define OUT_DIM 256
#define N_LAYERS 3
#define NT_E 9375            // 600000 / 64
#define NT_N 782             // ceil(50000/64)

// ---------------- device scratch ----------------
__device__ float d_h[N_NODES * HID];
__device__ float d_A[N_NODES * HID];
__device__ float d_B[N_NODES * HID];
__device__ float d_T[N_NODES * HID];
__device__ float d_magg[N_NODES * HID];
__device__ float d_cagg[N_NODES * 3];
__device__ float d_coord[N_NODES * 3];
__device__ float d_deg[N_NODES];
__device__ float d_gsum[N_GRAPHS * HID];
__device__ float d_gcnt[N_GRAPHS];

__device__ __forceinline__ float silu_f(float x) {
    return x / (1.0f + __expf(-x));
}
__device__ __forceinline__ uint32_t smem_u32(const void* p) {
    uint32_t a;
    asm("{ .reg .u64 t; cvta.to.shared.u64 t, %1; cvt.u32.u64 %0, t; }" : "=r"(a) : "l"(p));
    return a;
}
__device__ __forceinline__ uint32_t to_tf32(float f) {
    uint32_t o;
    asm("cvt.rna.tf32.f32 %0, %1;" : "=r"(o) : "f"(f));
    return o;
}
__device__ __forceinline__ void ldsm_x4(uint32_t a[4], uint32_t addr) {
    asm volatile("ldmatrix.sync.aligned.m8n8.x4.shared.b16 {%0,%1,%2,%3}, [%4];"
        : "=r"(a[0]), "=r"(a[1]), "=r"(a[2]), "=r"(a[3]) : "r"(addr));
}
__device__ __forceinline__ void ldsm_x2(uint32_t b[2], uint32_t addr) {
    asm volatile("ldmatrix.sync.aligned.m8n8.x2.shared.b16 {%0,%1}, [%2];"
        : "=r"(b[0]), "=r"(b[1]) : "r"(addr));
}
__device__ __forceinline__ void mma_tf32(float d[4], const uint32_t a[4], const uint32_t b[2]) {
    asm volatile("mma.sync.aligned.m16n8k8.row.col.f32.tf32.tf32.f32 "
        "{%0,%1,%2,%3}, {%4,%5,%6,%7}, {%8,%9}, {%0,%1,%2,%3};"
        : "+f"(d[0]), "+f"(d[1]), "+f"(d[2]), "+f"(d[3])
        : "r"(a[0]), "r"(a[1]), "r"(a[2]), "r"(a[3]), "r"(b[0]), "r"(b[1]));
}

// ---------------- small kernels ----------------
__global__ void init_kernel(const float* __restrict__ coord_in) {
    int idx = blockIdx.x * blockDim.x + threadIdx.x;
    if (idx < N_NODES * HID) d_magg[idx] = 0.0f;
    if (idx < N_NODES * 3) { d_cagg[idx] = 0.0f; d_coord[idx] = coord_in[idx]; }
    if (idx < N_NODES) d_deg[idx] = 0.0f;
    if (idx < N_GRAPHS * HID) d_gsum[idx] = 0.0f;
    if (idx < N_GRAPHS) d_gcnt[idx] = 0.0f;
}

__global__ void deg_kernel(const int* __restrict__ row) {
    int e = blockIdx.x * blockDim.x + threadIdx.x;
    if (e < N_EDGES) atomicAdd(&d_deg[row[e]], 1.0f);
}

__global__ void emb_in_kernel(const float* __restrict__ x,
                              const float* __restrict__ w,
                              const float* __restrict__ b) {
    int idx = blockIdx.x * blockDim.x + threadIdx.x;
    if (idx >= N_NODES * HID) return;
    int n = idx >> 7, ch = idx & 127;
    float acc = b[ch];
#pragma unroll
    for (int k = 0; k < IN_DIM; k++) acc += x[n * IN_DIM + k] * w[k * HID + ch];
    d_h[idx] = acc;
}

// store W[k][c] (row-major) transposed+tf32 into Ws[c][k] (132-stride)
__device__ __forceinline__ void load_w_trans(const float* __restrict__ W, float* __restrict__ Ws,
                                             int tid) {
    for (int idx = tid; idx < 4096; idx += 256) {
        int k = idx >> 5, c0 = (idx & 31) * 4;
        float4 v = reinterpret_cast<const float4*>(W)[idx];
        *(uint32_t*)&Ws[(c0 + 0) * 132 + k] = to_tf32(v.x);
        *(uint32_t*)&Ws[(c0 + 1) * 132 + k] = to_tf32(v.y);
        *(uint32_t*)&Ws[(c0 + 2) * 132 + k] = to_tf32(v.z);
        *(uint32_t*)&Ws[(c0 + 3) * 132 + k] = to_tf32(v.w);
    }
}

// ---------------- mma node GEMM: Y = op(X@W (+bias) (+Y)) ----------------
// smem: Wts [128][132] @0, Xs [64][132] @16896, bs @25344
#define GEMM_SMEM ((16896 + 8448 + 128) * 4)
#define GM_BIAS 1
#define GM_ACC 2
#define GM_SILU 4
#define GM_CLEARX 8

__global__ void __launch_bounds__(256, 1)
gemm_mma(float* __restrict__ X, const float* __restrict__ W,
         const float* __restrict__ bias, float* __restrict__ Y, int mode) {
    extern __shared__ float sm[];
    float* Wts = sm;
    float* Xs = sm + 16896;
    float* bs = sm + 25344;
    int tid = threadIdx.x;

    load_w_trans(W, Wts, tid);
    if (tid < 128) bs[tid] = (mode & GM_BIAS) ? bias[tid] : 0.0f;
    __syncthreads();

    uint32_t XsA = smem_u32(Xs), WtA = smem_u32(Wts);
    int L = tid & 31, w = tid >> 5;
    int mw = w & 1, nwg = w >> 1;
    int aRow = ((L >> 3) & 1) * 8 + (L & 7);
    uint32_t aBase0 = XsA + (uint32_t)(mw * 32 + aRow) * 528 + (uint32_t)(L >> 4) * 16;
    uint32_t aBase1 = aBase0 + 16 * 528;
    int Ln = L & 15;
    uint32_t bBase[4];
#pragma unroll
    for (int j = 0; j < 4; j++)
        bBase[j] = WtA + (uint32_t)((nwg * 4 + j) * 8 + (Ln & 7)) * 528 + (uint32_t)(Ln >> 3) * 16;

    for (int tile = blockIdx.x; tile < NT_N; tile += gridDim.x) {
        int r0 = tile * 64;
        for (int idx = tid; idx < 2048; idx += 256) {
            int r = idx >> 5, k4 = (idx & 31) * 4;
            int gr = r0 + r;
            float4 v = make_float4(0.f, 0.f, 0.f, 0.f);
            if (gr < N_NODES) {
                v = *reinterpret_cast<const float4*>(&X[gr * HID + k4]);
                if (mode & GM_CLEARX)
                    *reinterpret_cast<float4*>(&X[gr * HID + k4]) = make_float4(0.f, 0.f, 0.f, 0.f);
            }
            uint4 t;
            t.x = to_tf32(v.x); t.y = to_tf32(v.y); t.z = to_tf32(v.z); t.w = to_tf32(v.w);
            *reinterpret_cast<uint4*>(&Xs[r * 132 + k4]) = t;
        }
        __syncthreads();

        float acc[2][4][4];
#pragma unroll
        for (int i = 0; i < 2; i++)
#pragma unroll
            for (int j = 0; j < 4; j++)
#pragma unroll
                for (int e = 0; e < 4; e++) acc[i][j][e] = 0.0f;

#pragma unroll
        for (int kc = 0; kc < 16; kc++) {
            uint32_t a0[4], a1[4];
            ldsm_x4(a0, aBase0 + kc * 32);
            ldsm_x4(a1, aBase1 + kc * 32);
#pragma unroll
            for (int j = 0; j < 4; j++) {
                uint32_t b[2];
                ldsm_x2(b, bBase[j] + kc * 32);
                mma_tf32(acc[0][j], a0, b);
                mma_tf32(acc[1][j], a1, b);
            }
        }

#pragma unroll
        for (int i = 0; i < 2; i++) {
#pragma unroll
            for (int half = 0; half < 2; half++) {
                int gr = r0 + mw * 32 + i * 16 + half * 8 + (L >> 2);
                if (gr < N_NODES) {
#pragma unroll
                    for (int j = 0; j < 4; j++) {
                        int c = nwg * 32 + j * 8 + (L & 3) * 2;
                        float2 res;
                        res.x = acc[i][j][half * 2 + 0] + bs[c];
                        res.y = acc[i][j][half * 2 + 1] + bs[c + 1];
                        float* yp = &Y[gr * HID + c];
                        if (mode & GM_ACC) {
                            float2 o = *reinterpret_cast<float2*>(yp);
                            res.x += o.x; res.y += o.y;
                        }
                        if (mode & GM_SILU) { res.x = silu_f(res.x); res.y = silu_f(res.y); }
                        *reinterpret_cast<float2*>(yp) = res;
                    }
                }
            }
        }
        __syncthreads();
    }
}

// ---------------- mma edge kernel ----------------
// smem floats: W2s@0 [128][132], Wc1s@16896, tS@33792 [64][132], mS@42240,
// b2s@50688, bc1s@50816, wc2s@50944, wrs@51072, wes@51200,
// diffs@51328 (192), cw_part@51520 (256), rows_s@51776 (64 int)
#define EDGE_SMEM (51840 * 4)

__global__ void __launch_bounds__(256, 1)
edge_mma(const int* __restrict__ row, const int* __restrict__ col,
         const float* __restrict__ ea,
         const float* __restrict__ W2, const float* __restrict__ b2,
         const float* __restrict__ Wc1, const float* __restrict__ bc1,
         const float* __restrict__ wc2,
         const float* __restrict__ wr, const float* __restrict__ we) {
    extern __shared__ float sm[];
    float* W2s = sm;
    float* Wc1s = sm + 16896;
    float* tS = sm + 33792;
    float* mS = sm + 42240;
    float* b2s = sm + 50688;
    float* bc1s = sm + 50816;
    float* wc2s = sm + 50944;
    float* wrs = sm + 51072;
    float* wes = sm + 51200;
    float* diffs = sm + 51328;
    float* cw_part = sm + 51520;
    int* rows_s = (int*)(sm + 51776);

    int tid = threadIdx.x;
    load_w_trans(W2, W2s, tid);
    load_w_trans(Wc1, Wc1s, tid);
    if (tid < 128) {
        b2s[tid] = b2[tid]; bc1s[tid] = bc1[tid]; wc2s[tid] = wc2[tid];
        wrs[tid] = wr[tid]; wes[tid] = we[tid];
    }
    __syncthreads();

    uint32_t tSA = smem_u32(tS), mSA = smem_u32(mS);
    uint32_t W2A = smem_u32(W2s), Wc1A = smem_u32(Wc1s);
    int L = tid & 31, w = tid >> 5;
    int mw = w & 1, nwg = w >> 1;
    int aRow = ((L >> 3) & 1) * 8 + (L & 7);
    uint32_t aOff = (uint32_t)(mw * 32 + aRow) * 528 + (uint32_t)(L >> 4) * 16;
    int Ln = L & 15;
    uint32_t bOff[4];
#pragma unroll
    for (int j = 0; j < 4; j++)
        bOff[j] = (uint32_t)((nwg * 4 + j) * 8 + (Ln & 7)) * 528 + (uint32_t)(Ln >> 3) * 16;

    int e_loc = tid & 63, q = tid >> 6;

    for (int tile = blockIdx.x; tile < NT_E; tile += gridDim.x) {
        int e0 = tile * 64;
        // ---- gather: tS = tf32(silu(A[r] + B[c] + radial*wr + ea*we)) ----
        {
            int e = e0 + e_loc;
            int r = row[e], c = col[e];
            float dx = d_coord[r * 3 + 0] - d_coord[c * 3 + 0];
            float dy = d_coord[r * 3 + 1] - d_coord[c * 3 + 1];
            float dz = d_coord[r * 3 + 2] - d_coord[c * 3 + 2];
            float radial = dx * dx + dy * dy + dz * dz;
            float eav = ea[e];
            if (q == 0) {
                rows_s[e_loc] = r;
                diffs[e_loc * 3 + 0] = dx; diffs[e_loc * 3 + 1] = dy; diffs[e_loc * 3 + 2] = dz;
            }
#pragma unroll
            for (int jj = 0; jj < 8; jj++) {
                int ch = q * 32 + jj * 4;
                float4 av = *reinterpret_cast<const float4*>(&d_A[r * HID + ch]);
                float4 bv = *reinterpret_cast<const float4*>(&d_B[c * HID + ch]);
                float4 w1 = *reinterpret_cast<const float4*>(&wrs[ch]);
                float4 w2v = *reinterpret_cast<const float4*>(&wes[ch]);
                uint4 t;
                t.x = to_tf32(silu_f(av.x + bv.x + radial * w1.x + eav * w2v.x));
                t.y = to_tf32(silu_f(av.y + bv.y + radial * w1.y + eav * w2v.y));
                t.z = to_tf32(silu_f(av.z + bv.z + radial * w1.z + eav * w2v.z));
                t.w = to_tf32(silu_f(av.w + bv.w + radial * w1.w + eav * w2v.w));
                *reinterpret_cast<uint4*>(&tS[e_loc * 132 + ch]) = t;
            }
        }
        __syncthreads();

        // ---- MMA1: D1 = tS @ W2^T ----
        float acc[2][4][4];
#pragma unroll
        for (int i = 0; i < 2; i++)
#pragma unroll
            for (int j = 0; j < 4; j++)
#pragma unroll
                for (int e = 0; e < 4; e++) acc[i][j][e] = 0.0f;
#pragma unroll
        for (int kc = 0; kc < 16; kc++) {
            uint32_t a0[4], a1[4];
            ldsm_x4(a0, tSA + aOff + kc * 32);
            ldsm_x4(a1, tSA + aOff + 16 * 528 + kc * 32);
#pragma unroll
            for (int j = 0; j < 4; j++) {
                uint32_t b[2];
                ldsm_x2(b, W2A + bOff[j] + kc * 32);
                mma_tf32(acc[0][j], a0, b);
                mma_tf32(acc[1][j], a1, b);
            }
        }

        // ---- epilogue1: m = silu(D1 + b2); stash for deferred atomics; mS <- tf32(m) ----
        float mreg[32];
        int rns[4];
#pragma unroll
        for (int i = 0; i < 2; i++) {
#pragma unroll
            for (int half = 0; half < 2; half++) {
                int rowl = mw * 32 + i * 16 + half * 8 + (L >> 2);
                rns[i * 2 + half] = rows_s[rowl];
#pragma unroll
                for (int j = 0; j < 4; j++) {
                    int c = nwg * 32 + j * 8 + (L & 3) * 2;
                    float m0 = silu_f(acc[i][j][half * 2 + 0] + b2s[c]);
                    float m1 = silu_f(acc[i][j][half * 2 + 1] + b2s[c + 1]);
                    mreg[((i * 2 + half) * 4 + j) * 2 + 0] = m0;
                    mreg[((i * 2 + half) * 4 + j) * 2 + 1] = m1;
                    uint2 t;
                    t.x = to_tf32(m0); t.y = to_tf32(m1);
                    *reinterpret_cast<uint2*>(&mS[rowl * 132 + c]) = t;
                }
            }
        }
        __syncthreads();

        // ---- MMA2: D2 = mS @ Wc1^T, with magg REDs interleaved (2 per k-step) ----
#pragma unroll
        for (int i = 0; i < 2; i++)
#pragma unroll
            for (int j = 0; j < 4; j++)
#pragma unroll
                for (int e = 0; e < 4; e++) acc[i][j][e] = 0.0f;
#pragma unroll
        for (int kc = 0; kc < 16; kc++) {
            uint32_t a0[4], a1[4];
            ldsm_x4(a0, mSA + aOff + kc * 32);
            ldsm_x4(a1, mSA + aOff + 16 * 528 + kc * 32);
#pragma unroll
            for (int j = 0; j < 4; j++) {
                uint32_t b[2];
                ldsm_x2(b, Wc1A + bOff[j] + kc * 32);
                mma_tf32(acc[0][j], a0, b);
                mma_tf32(acc[1][j], a1, b);
            }
            // deferred magg atomics: t = 2*kc, 2*kc+1
#pragma unroll
            for (int u = 0; u < 2; u++) {
                int t = kc * 2 + u;
                int ih = t >> 3, j = (t >> 1) & 3, e = t & 1;
                atomicAdd(&d_magg[rns[ih] * HID + nwg * 32 + j * 8 + (L & 3) * 2 + e], mreg[t]);
            }
        }

        // ---- epilogue2: cw = sum_c silu(D2 + bc1)*wc2 ----
#pragma unroll
        for (int i = 0; i < 2; i++) {
#pragma unroll
            for (int half = 0; half < 2; half++) {
                float p = 0.0f;
#pragma unroll
                for (int j = 0; j < 4; j++) {
                    int c = nwg * 32 + j * 8 + (L & 3) * 2;
                    p += silu_f(acc[i][j][half * 2 + 0] + bc1s[c]) * wc2s[c];
                    p += silu_f(acc[i][j][half * 2 + 1] + bc1s[c + 1]) * wc2s[c + 1];
                }
                p += __shfl_xor_sync(0xffffffff, p, 1);
                p += __shfl_xor_sync(0xffffffff, p, 2);
                if ((L & 3) == 0) {
                    int rowl = mw * 32 + i * 16 + half * 8 + (L >> 2);
                    cw_part[nwg * 64 + rowl] = p;
                }
            }
        }
        __syncthreads();
        if (tid < 64) {
            float cw = cw_part[tid] + cw_part[64 + tid] + cw_part[128 + tid] + cw_part[192 + tid];
            int rn = rows_s[tid];
            atomicAdd(&d_cagg[rn * 3 + 0], diffs[tid * 3 + 0] * cw);
            atomicAdd(&d_cagg[rn * 3 + 1], diffs[tid * 3 + 1] * cw);
            atomicAdd(&d_cagg[rn * 3 + 2], diffs[tid * 3 + 2] * cw);
        }
        __syncthreads();
    }
}

// ---------------- coord update ----------------
__global__ void coord_kernel() {
    int n = blockIdx.x * blockDim.x + threadIdx.x;
    if (n < N_NODES) {
        float inv = 1.0f / fmaxf(d_deg[n], 1.0f);
#pragma unroll
        for (int dd = 0; dd < 3; dd++) {
            d_coord[n * 3 + dd] += d_cagg[n * 3 + dd] * inv;
            d_cagg[n * 3 + dd] = 0.0f;
        }
    }
}

// ---------------- global mean pool ----------------
__global__ void pool_kernel(const int* __restrict__ batch) {
    int n0 = blockIdx.x * 512;
    int ch = threadIdx.x;
    if (n0 >= N_NODES) return;
    int nend = min(n0 + 512, N_NODES);
    int cur = batch[n0];
    float acc = 0.0f, cnt = 0.0f;
    for (int n = n0; n < nend; n++) {
        int g = batch[n];
        if (g != cur) {
            atomicAdd(&d_gsum[cur * HID + ch], acc);
            if (ch == 0) atomicAdd(&d_gcnt[cur], cnt);
            acc = 0.0f; cnt = 0.0f; cur = g;
        }
        acc += d_A[n * HID + ch];
        cnt += 1.0f;
    }
    atomicAdd(&d_gsum[cur * HID + ch], acc);
    if (ch == 0) atomicAdd(&d_gcnt[cur], cnt);
}

// ---------------- final fc ----------------
__global__ void fc_kernel(const float* __restrict__ fcw, const float* __restrict__ fcb,
                          float* __restrict__ out) {
    int g = blockIdx.x;
    int ch = threadIdx.x;
    float inv = 1.0f / fmaxf(d_gcnt[g], 1.0f);
    float acc = fcb[ch];
    for (int k = 0; k < HID; k++)
        acc += d_gsum[g * HID + k] * inv * fcw[k * OUT_DIM + ch];
    out[g * OUT_DIM + ch] = acc;
}

// ---------------- launch ----------------
#define GRID_G 148
#define GRID_E 148

extern "C" void kernel_launch(void* const* d_in, const int* in_sizes, int n_in,
                              void* d_out, int out_size) {
    const float* x = (const float*)d_in[0];
    const int* eidx = (const int*)d_in[1];
    const float* coord = (const float*)d_in[2];
    const float* ea = (const float*)d_in[3];
    const int* batch = (const int*)d_in[4];
    const float* emb_in_w = (const float*)d_in[5];
    const float* emb_in_b = (const float*)d_in[6];
    const float* edge_w1 = (const float*)d_in[7];
    const float* edge_b1 = (const float*)d_in[8];
    const float* edge_w2 = (const float*)d_in[9];
    const float* edge_b2 = (const float*)d_in[10];
    const float* node_w1 = (const float*)d_in[11];
    const float* node_b1 = (const float*)d_in[12];
    const float* node_w2 = (const float*)d_in[13];
    const float* node_b2 = (const float*)d_in[14];
    const float* coord_w1 = (const float*)d_in[15];
    const float* coord_b1 = (const float*)d_in[16];
    const float* coord_w2 = (const float*)d_in[17];
    const float* emb_out_w = (const float*)d_in[18];
    const float* emb_out_b = (const float*)d_in[19];
    const float* fc_w = (const float*)d_in[20];
    const float* fc_b = (const float*)d_in[21];
    float* out = (float*)d_out;

    const int* row = eidx;
    const int* col = eidx + N_EDGES;

    float *ph, *pA, *pB, *pT, *pmagg;
    cudaGetSymbolAddress((void**)&ph, d_h);
    cudaGetSymbolAddress((void**)&pA, d_A);
    cudaGetSymbolAddress((void**)&pB, d_B);
    cudaGetSymbolAddress((void**)&pT, d_T);
    cudaGetSymbolAddress((void**)&pmagg, d_magg);

    cudaFuncSetAttribute(edge_mma, cudaFuncAttributeMaxDynamicSharedMemorySize, EDGE_SMEM);
    cudaFuncSetAttribute(gemm_mma, cudaFuncAttributeMaxDynamicSharedMemorySize, GEMM_SMEM);

    init_kernel<<<(N_NODES * HID + 255) / 256, 256>>>(coord);
    deg_kernel<<<(N_EDGES + 255) / 256, 256>>>(row);
    emb_in_kernel<<<(N_NODES * HID + 255) / 256, 256>>>(x, emb_in_w, emb_in_b);

    for (int l = 0; l < N_LAYERS; l++) {
        const float* W1 = edge_w1 + l * 258 * HID;
        // A = h@W1a + b1 ; B = h@W1b   (launches 4 and 5 on layer 0)
        gemm_mma<<<GRID_G, 256, GEMM_SMEM>>>(ph, W1, edge_b1 + l * HID, pA, GM_BIAS);
        gemm_mma<<<GRID_G, 256, GEMM_SMEM>>>(ph, W1 + 128 * HID, nullptr, pB, 0);
        // fused edge MLP (launch 6 on layer 0 -> ncu -s 5 -c 1 captures this)
        edge_mma<<<GRID_E, 256, EDGE_SMEM>>>(row, col, ea,
            edge_w2 + l * HID * HID, edge_b2 + l * HID,
            coord_w1 + l * HID * HID, coord_b1 + l * HID, coord_w2 + l * HID,
            W1 + 256 * HID, W1 + 257 * HID);
        coord_kernel<<<(N_NODES + 255) / 256, 256>>>();
        // node update
        gemm_mma<<<GRID_G, 256, GEMM_SMEM>>>(ph, node_w1 + l * 256 * HID,
                                             node_b1 + l * HID, pT, GM_BIAS);
        gemm_mma<<<GRID_G, 256, GEMM_SMEM>>>(pmagg, node_w1 + l * 256 * HID + 128 * HID,
                                             nullptr, pT, GM_ACC | GM_SILU | GM_CLEARX);
        gemm_mma<<<GRID_G, 256, GEMM_SMEM>>>(pT, node_w2 + l * HID * HID,
                                             node_b2 + l * HID, ph, GM_BIAS | GM_ACC);
    }

    gemm_mma<<<GRID_G, 256, GEMM_SMEM>>>(ph, emb_out_w, emb_out_b, pA, GM_BIAS);
    pool_kernel<<<(N_NODES + 511) / 512, 128>>>(batch);
    fc_kernel<<<N_GRAPHS, 256>>>(fc_w, fc_b, out);
}

// round 9
// speedup vs baseline: 1.2617x; 1.2617x over previous
#include <cuda_runtime.h>
#include <math.h>
#include <stdint.h>

#define N_NODES 50000
#define N_EDGES 600000
#define N_GRAPHS 64
#define HID 128
#define IN_DIM 16
#define OUT_DIM 256
#define N_LAYERS 3
#define NT_E 4688            // ceil(600000/128)
#define NT_N 782             // ceil(50000/64)

// ---------------- device scratch ----------------
__device__ float d_h[N_NODES * HID];
__device__ float d_A[N_NODES * HID];
__device__ float d_B[N_NODES * HID];
__device__ float d_T[N_NODES * HID];
__device__ float d_magg[N_NODES * HID];
__device__ float d_cagg[N_NODES * 3];
__device__ float d_coord[N_NODES * 3];
__device__ float d_deg[N_NODES];
__device__ float d_gsum[N_GRAPHS * HID];
__device__ float d_gcnt[N_GRAPHS];

__device__ __forceinline__ float silu_f(float x) {
    return x / (1.0f + __expf(-x));
}
__device__ __forceinline__ uint32_t smem_u32(const void* p) {
    uint32_t a;
    asm("{ .reg .u64 t; cvta.to.shared.u64 t, %1; cvt.u32.u64 %0, t; }" : "=r"(a) : "l"(p));
    return a;
}
__device__ __forceinline__ uint32_t to_tf32(float f) {
    uint32_t o;
    asm("cvt.rna.tf32.f32 %0, %1;" : "=r"(o) : "f"(f));
    return o;
}
__device__ __forceinline__ void ldsm_x4(uint32_t a[4], uint32_t addr) {
    asm volatile("ldmatrix.sync.aligned.m8n8.x4.shared.b16 {%0,%1,%2,%3}, [%4];"
        : "=r"(a[0]), "=r"(a[1]), "=r"(a[2]), "=r"(a[3]) : "r"(addr));
}
__device__ __forceinline__ void ldsm_x2(uint32_t b[2], uint32_t addr) {
    asm volatile("ldmatrix.sync.aligned.m8n8.x2.shared.b16 {%0,%1}, [%2];"
        : "=r"(b[0]), "=r"(b[1]) : "r"(addr));
}
__device__ __forceinline__ void mma_tf32(float d[4], const uint32_t a[4], const uint32_t b[2]) {
    asm volatile("mma.sync.aligned.m16n8k8.row.col.f32.tf32.tf32.f32 "
        "{%0,%1,%2,%3}, {%4,%5,%6,%7}, {%8,%9}, {%0,%1,%2,%3};"
        : "+f"(d[0]), "+f"(d[1]), "+f"(d[2]), "+f"(d[3])
        : "r"(a[0]), "r"(a[1]), "r"(a[2]), "r"(a[3]), "r"(b[0]), "r"(b[1]));
}

// ---------------- small kernels ----------------
__global__ void init_kernel(const float* __restrict__ coord_in) {
    int idx = blockIdx.x * blockDim.x + threadIdx.x;
    if (idx < N_NODES * HID) d_magg[idx] = 0.0f;
    if (idx < N_NODES * 3) { d_cagg[idx] = 0.0f; d_coord[idx] = coord_in[idx]; }
    if (idx < N_NODES) d_deg[idx] = 0.0f;
    if (idx < N_GRAPHS * HID) d_gsum[idx] = 0.0f;
    if (idx < N_GRAPHS) d_gcnt[idx] = 0.0f;
}

__global__ void deg_kernel(const int* __restrict__ row) {
    int e = blockIdx.x * blockDim.x + threadIdx.x;
    if (e < N_EDGES) atomicAdd(&d_deg[row[e]], 1.0f);
}

__global__ void emb_in_kernel(const float* __restrict__ x,
                              const float* __restrict__ w,
                              const float* __restrict__ b) {
    int idx = blockIdx.x * blockDim.x + threadIdx.x;
    if (idx >= N_NODES * HID) return;
    int n = idx >> 7, ch = idx & 127;
    float acc = b[ch];
#pragma unroll
    for (int k = 0; k < IN_DIM; k++) acc += x[n * IN_DIM + k] * w[k * HID + ch];
    d_h[idx] = acc;
}

// store W[k][c] (row-major) transposed+tf32 into Ws[c][k] (132-stride)
__device__ __forceinline__ void load_w_trans(const float* __restrict__ W, float* __restrict__ Ws,
                                             int tid, int nthreads) {
    for (int idx = tid; idx < 4096; idx += nthreads) {
        int k = idx >> 5, c0 = (idx & 31) * 4;
        float4 v = reinterpret_cast<const float4*>(W)[idx];
        *(uint32_t*)&Ws[(c0 + 0) * 132 + k] = to_tf32(v.x);
        *(uint32_t*)&Ws[(c0 + 1) * 132 + k] = to_tf32(v.y);
        *(uint32_t*)&Ws[(c0 + 2) * 132 + k] = to_tf32(v.z);
        *(uint32_t*)&Ws[(c0 + 3) * 132 + k] = to_tf32(v.w);
    }
}

// ---------------- mma node GEMM: Y = op(X@W (+bias) (+Y)) ----------------
// smem: Wts [128][132] @0, Xs [64][132] @16896, bs @25344
#define GEMM_SMEM ((16896 + 8448 + 128) * 4)
#define GM_BIAS 1
#define GM_ACC 2
#define GM_SILU 4
#define GM_CLEARX 8

__global__ void __launch_bounds__(256, 2)
gemm_mma(float* __restrict__ X, const float* __restrict__ W,
         const float* __restrict__ bias, float* __restrict__ Y, int mode) {
    extern __shared__ float sm[];
    float* Wts = sm;
    float* Xs = sm + 16896;
    float* bs = sm + 25344;
    int tid = threadIdx.x;

    load_w_trans(W, Wts, tid, 256);
    if (tid < 128) bs[tid] = (mode & GM_BIAS) ? bias[tid] : 0.0f;
    __syncthreads();

    uint32_t XsA = smem_u32(Xs), WtA = smem_u32(Wts);
    int L = tid & 31, w = tid >> 5;
    int mw = w & 1, nwg = w >> 1;
    int aRow = ((L >> 3) & 1) * 8 + (L & 7);
    uint32_t aBase0 = XsA + (uint32_t)(mw * 32 + aRow) * 528 + (uint32_t)(L >> 4) * 16;
    uint32_t aBase1 = aBase0 + 16 * 528;
    int Ln = L & 15;
    uint32_t bBase[4];
#pragma unroll
    for (int j = 0; j < 4; j++)
        bBase[j] = WtA + (uint32_t)((nwg * 4 + j) * 8 + (Ln & 7)) * 528 + (uint32_t)(Ln >> 3) * 16;

    for (int tile = blockIdx.x; tile < NT_N; tile += gridDim.x) {
        int r0 = tile * 64;
        for (int idx = tid; idx < 2048; idx += 256) {
            int r = idx >> 5, k4 = (idx & 31) * 4;
            int gr = r0 + r;
            float4 v = make_float4(0.f, 0.f, 0.f, 0.f);
            if (gr < N_NODES) {
                v = *reinterpret_cast<const float4*>(&X[gr * HID + k4]);
                if (mode & GM_CLEARX)
                    *reinterpret_cast<float4*>(&X[gr * HID + k4]) = make_float4(0.f, 0.f, 0.f, 0.f);
            }
            uint4 t;
            t.x = to_tf32(v.x); t.y = to_tf32(v.y); t.z = to_tf32(v.z); t.w = to_tf32(v.w);
            *reinterpret_cast<uint4*>(&Xs[r * 132 + k4]) = t;
        }
        __syncthreads();

        float acc[2][4][4];
#pragma unroll
        for (int i = 0; i < 2; i++)
#pragma unroll
            for (int j = 0; j < 4; j++)
#pragma unroll
                for (int e = 0; e < 4; e++) acc[i][j][e] = 0.0f;

#pragma unroll
        for (int kc = 0; kc < 16; kc++) {
            uint32_t a0[4], a1[4];
            ldsm_x4(a0, aBase0 + kc * 32);
            ldsm_x4(a1, aBase1 + kc * 32);
#pragma unroll
            for (int j = 0; j < 4; j++) {
                uint32_t b[2];
                ldsm_x2(b, bBase[j] + kc * 32);
                mma_tf32(acc[0][j], a0, b);
                mma_tf32(acc[1][j], a1, b);
            }
        }

#pragma unroll
        for (int i = 0; i < 2; i++) {
#pragma unroll
            for (int half = 0; half < 2; half++) {
                int gr = r0 + mw * 32 + i * 16 + half * 8 + (L >> 2);
                if (gr < N_NODES) {
#pragma unroll
                    for (int j = 0; j < 4; j++) {
                        int c = nwg * 32 + j * 8 + (L & 3) * 2;
                        float2 res;
                        res.x = acc[i][j][half * 2 + 0] + bs[c];
                        res.y = acc[i][j][half * 2 + 1] + bs[c + 1];
                        float* yp = &Y[gr * HID + c];
                        if (mode & GM_ACC) {
                            float2 o = *reinterpret_cast<float2*>(yp);
                            res.x += o.x; res.y += o.y;
                        }
                        if (mode & GM_SILU) { res.x = silu_f(res.x); res.y = silu_f(res.y); }
                        *reinterpret_cast<float2*>(yp) = res;
                    }
                }
            }
        }
        __syncthreads();
    }
}

// ---------------- mma edge kernel: 128-edge tiles, 512 threads ----------------
// smem floats: W2s@0 [128][132], Wc1s@16896, tS@33792 [128][132] (reused as mS),
// b2s@50688, bc1s@50816, wc2s@50944, wrs@51072, wes@51200,
// diffs@51328 (384), cw_part@51712 (512), rows_s@52224 (128 int)  -> 52352 floats
#define EDGE_SMEM (52352 * 4)

__global__ void __launch_bounds__(512, 1)
edge_mma(const int* __restrict__ row, const int* __restrict__ col,
         const float* __restrict__ ea,
         const float* __restrict__ W2, const float* __restrict__ b2,
         const float* __restrict__ Wc1, const float* __restrict__ bc1,
         const float* __restrict__ wc2,
         const float* __restrict__ wr, const float* __restrict__ we) {
    extern __shared__ float sm[];
    float* W2s = sm;
    float* Wc1s = sm + 16896;
    float* tS = sm + 33792;
    float* b2s = sm + 50688;
    float* bc1s = sm + 50816;
    float* wc2s = sm + 50944;
    float* wrs = sm + 51072;
    float* wes = sm + 51200;
    float* diffs = sm + 51328;
    float* cw_part = sm + 51712;
    int* rows_s = (int*)(sm + 52224);

    int tid = threadIdx.x;
    load_w_trans(W2, W2s, tid, 512);
    load_w_trans(Wc1, Wc1s, tid, 512);
    if (tid < 128) {
        b2s[tid] = b2[tid]; bc1s[tid] = bc1[tid]; wc2s[tid] = wc2[tid];
        wrs[tid] = wr[tid]; wes[tid] = we[tid];
    }
    __syncthreads();

    uint32_t tSA = smem_u32(tS);
    uint32_t W2A = smem_u32(W2s), Wc1A = smem_u32(Wc1s);
    int L = tid & 31, w = tid >> 5;           // 16 warps
    int mw = w >> 2, nwg = w & 3;             // 4 m-bands of 32 rows, 4 n-groups of 32 cols
    int aRow = ((L >> 3) & 1) * 8 + (L & 7);
    uint32_t aOff = (uint32_t)(mw * 32 + aRow) * 528 + (uint32_t)(L >> 4) * 16;
    int Ln = L & 15;
    uint32_t bOff[4];
#pragma unroll
    for (int j = 0; j < 4; j++)
        bOff[j] = (uint32_t)((nwg * 4 + j) * 8 + (Ln & 7)) * 528 + (uint32_t)(Ln >> 3) * 16;

    int e_loc = tid >> 2, q = tid & 3;        // 128 edges, 4 channel-quarters

    for (int tile = blockIdx.x; tile < NT_E; tile += gridDim.x) {
        int e0 = tile * 128;
        // ---- gather: tS = tf32(silu(A[r] + B[c] + radial*wr + ea*we)) ----
        {
            int e = e0 + e_loc;
            if (e < N_EDGES) {
                int r = row[e], c = col[e];
                float dx = d_coord[r * 3 + 0] - d_coord[c * 3 + 0];
                float dy = d_coord[r * 3 + 1] - d_coord[c * 3 + 1];
                float dz = d_coord[r * 3 + 2] - d_coord[c * 3 + 2];
                float radial = dx * dx + dy * dy + dz * dz;
                float eav = ea[e];
                if (q == 0) {
                    rows_s[e_loc] = r;
                    diffs[e_loc * 3 + 0] = dx; diffs[e_loc * 3 + 1] = dy; diffs[e_loc * 3 + 2] = dz;
                }
#pragma unroll
                for (int jj = 0; jj < 8; jj++) {
                    int ch = q * 32 + jj * 4;
                    float4 av = *reinterpret_cast<const float4*>(&d_A[r * HID + ch]);
                    float4 bv = *reinterpret_cast<const float4*>(&d_B[c * HID + ch]);
                    float4 w1 = *reinterpret_cast<const float4*>(&wrs[ch]);
                    float4 w2v = *reinterpret_cast<const float4*>(&wes[ch]);
                    uint4 t;
                    t.x = to_tf32(silu_f(av.x + bv.x + radial * w1.x + eav * w2v.x));
                    t.y = to_tf32(silu_f(av.y + bv.y + radial * w1.y + eav * w2v.y));
                    t.z = to_tf32(silu_f(av.z + bv.z + radial * w1.z + eav * w2v.z));
                    t.w = to_tf32(silu_f(av.w + bv.w + radial * w1.w + eav * w2v.w));
                    *reinterpret_cast<uint4*>(&tS[e_loc * 132 + ch]) = t;
                }
            } else {
                if (q == 0) {
                    rows_s[e_loc] = -1;
                    diffs[e_loc * 3 + 0] = 0.f; diffs[e_loc * 3 + 1] = 0.f; diffs[e_loc * 3 + 2] = 0.f;
                }
#pragma unroll
                for (int jj = 0; jj < 8; jj++) {
                    int ch = q * 32 + jj * 4;
                    *reinterpret_cast<uint4*>(&tS[e_loc * 132 + ch]) = make_uint4(0, 0, 0, 0);
                }
            }
        }
        __syncthreads();

        // ---- MMA1: D1 = tS @ W2^T  (each warp reads only its own 32-row band) ----
        float acc[2][4][4];
#pragma unroll
        for (int i = 0; i < 2; i++)
#pragma unroll
            for (int j = 0; j < 4; j++)
#pragma unroll
                for (int e = 0; e < 4; e++) acc[i][j][e] = 0.0f;
#pragma unroll
        for (int kc = 0; kc < 16; kc++) {
            uint32_t a0[4], a1[4];
            ldsm_x4(a0, tSA + aOff + kc * 32);
            ldsm_x4(a1, tSA + aOff + 16 * 528 + kc * 32);
#pragma unroll
            for (int j = 0; j < 4; j++) {
                uint32_t b[2];
                ldsm_x2(b, W2A + bOff[j] + kc * 32);
                mma_tf32(acc[0][j], a0, b);
                mma_tf32(acc[1][j], a1, b);
            }
        }

        // ---- epilogue1: m = silu(D1 + b2); magg atomics; tS <- tf32(m) ----
        // No syncthreads needed: each warp reads/writes only its own row band.
#pragma unroll
        for (int i = 0; i < 2; i++) {
#pragma unroll
            for (int half = 0; half < 2; half++) {
                int rowl = mw * 32 + i * 16 + half * 8 + (L >> 2);
                int rn = rows_s[rowl];
#pragma unroll
                for (int j = 0; j < 4; j++) {
                    int c = nwg * 32 + j * 8 + (L & 3) * 2;
                    float m0 = silu_f(acc[i][j][half * 2 + 0] + b2s[c]);
                    float m1 = silu_f(acc[i][j][half * 2 + 1] + b2s[c + 1]);
                    if (rn >= 0) {
                        atomicAdd(&d_magg[rn * HID + c + 0], m0);
                        atomicAdd(&d_magg[rn * HID + c + 1], m1);
                    }
                    uint2 t;
                    t.x = to_tf32(m0); t.y = to_tf32(m1);
                    *reinterpret_cast<uint2*>(&tS[rowl * 132 + c]) = t;
                }
            }
        }

        // ---- MMA2: D2 = mS @ Wc1^T ----
#pragma unroll
        for (int i = 0; i < 2; i++)
#pragma unroll
            for (int j = 0; j < 4; j++)
#pragma unroll
                for (int e = 0; e < 4; e++) acc[i][j][e] = 0.0f;
#pragma unroll
        for (int kc = 0; kc < 16; kc++) {
            uint32_t a0[4], a1[4];
            ldsm_x4(a0, tSA + aOff + kc * 32);
            ldsm_x4(a1, tSA + aOff + 16 * 528 + kc * 32);
#pragma unroll
            for (int j = 0; j < 4; j++) {
                uint32_t b[2];
                ldsm_x2(b, Wc1A + bOff[j] + kc * 32);
                mma_tf32(acc[0][j], a0, b);
                mma_tf32(acc[1][j], a1, b);
            }
        }

        // ---- epilogue2: cw = sum_c silu(D2 + bc1)*wc2 ----
#pragma unroll
        for (int i = 0; i < 2; i++) {
#pragma unroll
            for (int half = 0; half < 2; half++) {
                float p = 0.0f;
#pragma unroll
                for (int j = 0; j < 4; j++) {
                    int c = nwg * 32 + j * 8 + (L & 3) * 2;
                    p += silu_f(acc[i][j][half * 2 + 0] + bc1s[c]) * wc2s[c];
                    p += silu_f(acc[i][j][half * 2 + 1] + bc1s[c + 1]) * wc2s[c + 1];
                }
                p += __shfl_xor_sync(0xffffffff, p, 1);
                p += __shfl_xor_sync(0xffffffff, p, 2);
                if ((L & 3) == 0) {
                    int rowl = mw * 32 + i * 16 + half * 8 + (L >> 2);
                    cw_part[nwg * 128 + rowl] = p;
                }
            }
        }
        __syncthreads();
        if (tid < 128) {
            int rn = rows_s[tid];
            if (rn >= 0) {
                float cw = cw_part[tid] + cw_part[128 + tid] + cw_part[256 + tid] + cw_part[384 + tid];
                atomicAdd(&d_cagg[rn * 3 + 0], diffs[tid * 3 + 0] * cw);
                atomicAdd(&d_cagg[rn * 3 + 1], diffs[tid * 3 + 1] * cw);
                atomicAdd(&d_cagg[rn * 3 + 2], diffs[tid * 3 + 2] * cw);
            }
        }
        __syncthreads();
    }
}

// ---------------- coord update ----------------
__global__ void coord_kernel() {
    int n = blockIdx.x * blockDim.x + threadIdx.x;
    if (n < N_NODES) {
        float inv = 1.0f / fmaxf(d_deg[n], 1.0f);
#pragma unroll
        for (int dd = 0; dd < 3; dd++) {
            d_coord[n * 3 + dd] += d_cagg[n * 3 + dd] * inv;
            d_cagg[n * 3 + dd] = 0.0f;
        }
    }
}

// ---------------- global mean pool ----------------
__global__ void pool_kernel(const int* __restrict__ batch) {
    int n0 = blockIdx.x * 512;
    int ch = threadIdx.x;
    if (n0 >= N_NODES) return;
    int nend = min(n0 + 512, N_NODES);
    int cur = batch[n0];
    float acc = 0.0f, cnt = 0.0f;
    for (int n = n0; n < nend; n++) {
        int g = batch[n];
        if (g != cur) {
            atomicAdd(&d_gsum[cur * HID + ch], acc);
            if (ch == 0) atomicAdd(&d_gcnt[cur], cnt);
            acc = 0.0f; cnt = 0.0f; cur = g;
        }
        acc += d_A[n * HID + ch];
        cnt += 1.0f;
    }
    atomicAdd(&d_gsum[cur * HID + ch], acc);
    if (ch == 0) atomicAdd(&d_gcnt[cur], cnt);
}

// ---------------- final fc ----------------
__global__ void fc_kernel(const float* __restrict__ fcw, const float* __restrict__ fcb,
                          float* __restrict__ out) {
    int g = blockIdx.x;
    int ch = threadIdx.x;
    float inv = 1.0f / fmaxf(d_gcnt[g], 1.0f);
    float acc = fcb[ch];
    for (int k = 0; k < HID; k++)
        acc += d_gsum[g * HID + k] * inv * fcw[k * OUT_DIM + ch];
    out[g * OUT_DIM + ch] = acc;
}

// ---------------- launch ----------------
#define GRID_G 296
#define GRID_E 148

extern "C" void kernel_launch(void* const* d_in, const int* in_sizes, int n_in,
                              void* d_out, int out_size) {
    const float* x = (const float*)d_in[0];
    const int* eidx = (const int*)d_in[1];
    const float* coord = (const float*)d_in[2];
    const float* ea = (const float*)d_in[3];
    const int* batch = (const int*)d_in[4];
    const float* emb_in_w = (const float*)d_in[5];
    const float* emb_in_b = (const float*)d_in[6];
    const float* edge_w1 = (const float*)d_in[7];
    const float* edge_b1 = (const float*)d_in[8];
    const float* edge_w2 = (const float*)d_in[9];
    const float* edge_b2 = (const float*)d_in[10];
    const float* node_w1 = (const float*)d_in[11];
    const float* node_b1 = (const float*)d_in[12];
    const float* node_w2 = (const float*)d_in[13];
    const float* node_b2 = (const float*)d_in[14];
    const float* coord_w1 = (const float*)d_in[15];
    const float* coord_b1 = (const float*)d_in[16];
    const float* coord_w2 = (const float*)d_in[17];
    const float* emb_out_w = (const float*)d_in[18];
    const float* emb_out_b = (const float*)d_in[19];
    const float* fc_w = (const float*)d_in[20];
    const float* fc_b = (const float*)d_in[21];
    float* out = (float*)d_out;

    const int* row = eidx;
    const int* col = eidx + N_EDGES;

    float *ph, *pA, *pB, *pT, *pmagg;
    cudaGetSymbolAddress((void**)&ph, d_h);
    cudaGetSymbolAddress((void**)&pA, d_A);
    cudaGetSymbolAddress((void**)&pB, d_B);
    cudaGetSymbolAddress((void**)&pT, d_T);
    cudaGetSymbolAddress((void**)&pmagg, d_magg);

    cudaFuncSetAttribute(edge_mma, cudaFuncAttributeMaxDynamicSharedMemorySize, EDGE_SMEM);
    cudaFuncSetAttribute(gemm_mma, cudaFuncAttributeMaxDynamicSharedMemorySize, GEMM_SMEM);

    init_kernel<<<(N_NODES * HID + 255) / 256, 256>>>(coord);
    deg_kernel<<<(N_EDGES + 255) / 256, 256>>>(row);
    emb_in_kernel<<<(N_NODES * HID + 255) / 256, 256>>>(x, emb_in_w, emb_in_b);

    for (int l = 0; l < N_LAYERS; l++) {
        const float* W1 = edge_w1 + l * 258 * HID;
        // A = h@W1a + b1 ; B = h@W1b
        gemm_mma<<<GRID_G, 256, GEMM_SMEM>>>(ph, W1, edge_b1 + l * HID, pA, GM_BIAS);
        gemm_mma<<<GRID_G, 256, GEMM_SMEM>>>(ph, W1 + 128 * HID, nullptr, pB, 0);
        // fused edge MLP (launch #6 on layer 0 -> ncu captures this)
        edge_mma<<<GRID_E, 512, EDGE_SMEM>>>(row, col, ea,
            edge_w2 + l * HID * HID, edge_b2 + l * HID,
            coord_w1 + l * HID * HID, coord_b1 + l * HID, coord_w2 + l * HID,
            W1 + 256 * HID, W1 + 257 * HID);
        coord_kernel<<<(N_NODES + 255) / 256, 256>>>();
        // node update
        gemm_mma<<<GRID_G, 256, GEMM_SMEM>>>(ph, node_w1 + l * 256 * HID,
                                             node_b1 + l * HID, pT, GM_BIAS);
        gemm_mma<<<GRID_G, 256, GEMM_SMEM>>>(pmagg, node_w1 + l * 256 * HID + 128 * HID,
                                             nullptr, pT, GM_ACC | GM_SILU | GM_CLEARX);
        gemm_mma<<<GRID_G, 256, GEMM_SMEM>>>(pT, node_w2 + l * HID * HID,
                                             node_b2 + l * HID, ph, GM_BIAS | GM_ACC);
    }

    gemm_mma<<<GRID_G, 256, GEMM_SMEM>>>(ph, emb_out_w, emb_out_b, pA, GM_BIAS);
    pool_kernel<<<(N_NODES + 511) / 512, 128>>>(batch);
    fc_kernel<<<N_GRAPHS, 256>>>(fc_w, fc_b, out);
}

// round 10
// speedup vs baseline: 1.4469x; 1.1468x over previous
#include <cuda_runtime.h>
#include <math.h>
#include <stdint.h>

#define N_NODES 50000
#define N_EDGES 600000
#define N_GRAPHS 64
#define HID 128
#define IN_DIM 16
#define OUT_DIM 256
#define N_LAYERS 3
#define NT_E 4688            // ceil(600000/128)
#define NT_N 782             // ceil(50000/64)

// ---------------- device scratch ----------------
__device__ float d_h[N_NODES * HID];
__device__ float d_A[N_NODES * HID];
__device__ float d_B[N_NODES * HID];
__device__ float d_T[N_NODES * HID];
__device__ float d_magg[N_NODES * HID];
__device__ float d_cagg[N_NODES * 3];
__device__ float d_coord[N_NODES * 3];
__device__ float d_deg[N_NODES];
__device__ float d_gsum[N_GRAPHS * HID];
__device__ float d_gcnt[N_GRAPHS];

// silu via tanh.approx: 1 MUFU instead of EX2+RCP (2 MUFU)
__device__ __forceinline__ float silu_f(float x) {
    float t;
    asm("tanh.approx.f32 %0, %1;" : "=f"(t) : "f"(x * 0.5f));
    return 0.5f * x * (1.0f + t);
}
__device__ __forceinline__ uint32_t smem_u32(const void* p) {
    uint32_t a;
    asm("{ .reg .u64 t; cvta.to.shared.u64 t, %1; cvt.u32.u64 %0, t; }" : "=r"(a) : "l"(p));
    return a;
}
__device__ __forceinline__ uint32_t to_tf32(float f) {
    uint32_t o;
    asm("cvt.rna.tf32.f32 %0, %1;" : "=r"(o) : "f"(f));
    return o;
}
__device__ __forceinline__ void ldsm_x4(uint32_t a[4], uint32_t addr) {
    asm volatile("ldmatrix.sync.aligned.m8n8.x4.shared.b16 {%0,%1,%2,%3}, [%4];"
        : "=r"(a[0]), "=r"(a[1]), "=r"(a[2]), "=r"(a[3]) : "r"(addr));
}
__device__ __forceinline__ void ldsm_x2(uint32_t b[2], uint32_t addr) {
    asm volatile("ldmatrix.sync.aligned.m8n8.x2.shared.b16 {%0,%1}, [%2];"
        : "=r"(b[0]), "=r"(b[1]) : "r"(addr));
}
__device__ __forceinline__ void mma_tf32(float d[4], const uint32_t a[4], const uint32_t b[2]) {
    asm volatile("mma.sync.aligned.m16n8k8.row.col.f32.tf32.tf32.f32 "
        "{%0,%1,%2,%3}, {%4,%5,%6,%7}, {%8,%9}, {%0,%1,%2,%3};"
        : "+f"(d[0]), "+f"(d[1]), "+f"(d[2]), "+f"(d[3])
        : "r"(a[0]), "r"(a[1]), "r"(a[2]), "r"(a[3]), "r"(b[0]), "r"(b[1]));
}

// ---------------- small kernels ----------------
__global__ void init_kernel(const float* __restrict__ coord_in) {
    int idx = blockIdx.x * blockDim.x + threadIdx.x;
    if (idx < N_NODES * HID) d_magg[idx] = 0.0f;
    if (idx < N_NODES * 3) { d_cagg[idx] = 0.0f; d_coord[idx] = coord_in[idx]; }
    if (idx < N_NODES) d_deg[idx] = 0.0f;
    if (idx < N_GRAPHS * HID) d_gsum[idx] = 0.0f;
    if (idx < N_GRAPHS) d_gcnt[idx] = 0.0f;
}

__global__ void deg_kernel(const int* __restrict__ row) {
    int e = blockIdx.x * blockDim.x + threadIdx.x;
    if (e < N_EDGES) atomicAdd(&d_deg[row[e]], 1.0f);
}

__global__ void emb_in_kernel(const float* __restrict__ x,
                              const float* __restrict__ w,
                              const float* __restrict__ b) {
    int idx = blockIdx.x * blockDim.x + threadIdx.x;
    if (idx >= N_NODES * HID) return;
    int n = idx >> 7, ch = idx & 127;
    float acc = b[ch];
#pragma unroll
    for (int k = 0; k < IN_DIM; k++) acc += x[n * IN_DIM + k] * w[k * HID + ch];
    d_h[idx] = acc;
}

// store W[k][c] (row-major, 128x128) transposed+tf32 into Ws[c][k] (stride floats)
__device__ __forceinline__ void load_w_trans(const float* __restrict__ W, float* __restrict__ Ws,
                                             int tid, int nthreads, int stride) {
    for (int idx = tid; idx < 4096; idx += nthreads) {
        int k = idx >> 5, c0 = (idx & 31) * 4;
        float4 v = reinterpret_cast<const float4*>(W)[idx];
        *(uint32_t*)&Ws[(c0 + 0) * stride + k] = to_tf32(v.x);
        *(uint32_t*)&Ws[(c0 + 1) * stride + k] = to_tf32(v.y);
        *(uint32_t*)&Ws[(c0 + 2) * stride + k] = to_tf32(v.z);
        *(uint32_t*)&Ws[(c0 + 3) * stride + k] = to_tf32(v.w);
    }
}

// ---------------- gemm_mma: Y = op(X@W (+bias) (+Y)) ----------------
#define GEMM_SMEM ((16896 + 8448 + 128) * 4)
#define GM_BIAS 1
#define GM_ACC 2
#define GM_SILU 4

__global__ void __launch_bounds__(256, 2)
gemm_mma(float* __restrict__ X, const float* __restrict__ W,
         const float* __restrict__ bias, float* __restrict__ Y, int mode) {
    extern __shared__ float sm[];
    float* Wts = sm;
    float* Xs = sm + 16896;
    float* bs = sm + 25344;
    int tid = threadIdx.x;

    load_w_trans(W, Wts, tid, 256, 132);
    if (tid < 128) bs[tid] = (mode & GM_BIAS) ? bias[tid] : 0.0f;
    __syncthreads();

    uint32_t XsA = smem_u32(Xs), WtA = smem_u32(Wts);
    int L = tid & 31, w = tid >> 5;
    int mw = w & 1, nwg = w >> 1;
    int aRow = ((L >> 3) & 1) * 8 + (L & 7);
    uint32_t aBase0 = XsA + (uint32_t)(mw * 32 + aRow) * 528 + (uint32_t)(L >> 4) * 16;
    uint32_t aBase1 = aBase0 + 16 * 528;
    int Ln = L & 15;
    uint32_t bBase[4];
#pragma unroll
    for (int j = 0; j < 4; j++)
        bBase[j] = WtA + (uint32_t)((nwg * 4 + j) * 8 + (Ln & 7)) * 528 + (uint32_t)(Ln >> 3) * 16;

    for (int tile = blockIdx.x; tile < NT_N; tile += gridDim.x) {
        int r0 = tile * 64;
        for (int idx = tid; idx < 2048; idx += 256) {
            int r = idx >> 5, k4 = (idx & 31) * 4;
            int gr = r0 + r;
            float4 v = make_float4(0.f, 0.f, 0.f, 0.f);
            if (gr < N_NODES) v = *reinterpret_cast<const float4*>(&X[gr * HID + k4]);
            uint4 t;
            t.x = to_tf32(v.x); t.y = to_tf32(v.y); t.z = to_tf32(v.z); t.w = to_tf32(v.w);
            *reinterpret_cast<uint4*>(&Xs[r * 132 + k4]) = t;
        }
        __syncthreads();

        float acc[2][4][4];
#pragma unroll
        for (int i = 0; i < 2; i++)
#pragma unroll
            for (int j = 0; j < 4; j++)
#pragma unroll
                for (int e = 0; e < 4; e++) acc[i][j][e] = 0.0f;

#pragma unroll
        for (int kc = 0; kc < 16; kc++) {
            uint32_t a0[4], a1[4];
            ldsm_x4(a0, aBase0 + kc * 32);
            ldsm_x4(a1, aBase1 + kc * 32);
#pragma unroll
            for (int j = 0; j < 4; j++) {
                uint32_t b[2];
                ldsm_x2(b, bBase[j] + kc * 32);
                mma_tf32(acc[0][j], a0, b);
                mma_tf32(acc[1][j], a1, b);
            }
        }

#pragma unroll
        for (int i = 0; i < 2; i++) {
#pragma unroll
            for (int half = 0; half < 2; half++) {
                int gr = r0 + mw * 32 + i * 16 + half * 8 + (L >> 2);
                if (gr < N_NODES) {
#pragma unroll
                    for (int j = 0; j < 4; j++) {
                        int c = nwg * 32 + j * 8 + (L & 3) * 2;
                        float2 res;
                        res.x = acc[i][j][half * 2 + 0] + bs[c];
                        res.y = acc[i][j][half * 2 + 1] + bs[c + 1];
                        float* yp = &Y[gr * HID + c];
                        if (mode & GM_ACC) {
                            float2 o = *reinterpret_cast<float2*>(yp);
                            res.x += o.x; res.y += o.y;
                        }
                        if (mode & GM_SILU) { res.x = silu_f(res.x); res.y = silu_f(res.y); }
                        *reinterpret_cast<float2*>(yp) = res;
                    }
                }
            }
        }
        __syncthreads();
    }
}

// ---------------- gemm_ab: Y1 = X@Wa + b, Y2 = X@Wb  (one X pass, N=256) ----------------
// smem: Wts [256][132] @0, Xs [64][132] @33792, bs @42240
#define AB_SMEM ((33792 + 8448 + 128) * 4)

__global__ void __launch_bounds__(256, 1)
gemm_ab(const float* __restrict__ X, const float* __restrict__ Wa, const float* __restrict__ Wb,
        const float* __restrict__ bias, float* __restrict__ Y1, float* __restrict__ Y2) {
    extern __shared__ float sm[];
    float* Wts = sm;
    float* Xs = sm + 33792;
    float* bs = sm + 42240;
    int tid = threadIdx.x;

    load_w_trans(Wa, Wts, tid, 256, 132);
    load_w_trans(Wb, Wts + 128 * 132, tid, 256, 132);
    if (tid < 128) bs[tid] = bias[tid];
    __syncthreads();

    uint32_t XsA = smem_u32(Xs), WtA = smem_u32(Wts);
    int L = tid & 31, w = tid >> 5;
    int mw = w & 1, nwg = w >> 1;
    int aRow = ((L >> 3) & 1) * 8 + (L & 7);
    uint32_t aBase0 = XsA + (uint32_t)(mw * 32 + aRow) * 528 + (uint32_t)(L >> 4) * 16;
    uint32_t aBase1 = aBase0 + 16 * 528;
    int Ln = L & 15;
    uint32_t bBase[8];
#pragma unroll
    for (int j = 0; j < 8; j++) {
        int blk = (j < 4) ? (nwg * 4 + j) : (16 + nwg * 4 + (j - 4));
        bBase[j] = WtA + (uint32_t)(blk * 8 + (Ln & 7)) * 528 + (uint32_t)(Ln >> 3) * 16;
    }

    for (int tile = blockIdx.x; tile < NT_N; tile += gridDim.x) {
        int r0 = tile * 64;
        for (int idx = tid; idx < 2048; idx += 256) {
            int r = idx >> 5, k4 = (idx & 31) * 4;
            int gr = r0 + r;
            float4 v = make_float4(0.f, 0.f, 0.f, 0.f);
            if (gr < N_NODES) v = *reinterpret_cast<const float4*>(&X[gr * HID + k4]);
            uint4 t;
            t.x = to_tf32(v.x); t.y = to_tf32(v.y); t.z = to_tf32(v.z); t.w = to_tf32(v.w);
            *reinterpret_cast<uint4*>(&Xs[r * 132 + k4]) = t;
        }
        __syncthreads();

        float acc[2][8][4];
#pragma unroll
        for (int i = 0; i < 2; i++)
#pragma unroll
            for (int j = 0; j < 8; j++)
#pragma unroll
                for (int e = 0; e < 4; e++) acc[i][j][e] = 0.0f;

#pragma unroll
        for (int kc = 0; kc < 16; kc++) {
            uint32_t a0[4], a1[4];
            ldsm_x4(a0, aBase0 + kc * 32);
            ldsm_x4(a1, aBase1 + kc * 32);
#pragma unroll
            for (int j = 0; j < 8; j++) {
                uint32_t b[2];
                ldsm_x2(b, bBase[j] + kc * 32);
                mma_tf32(acc[0][j], a0, b);
                mma_tf32(acc[1][j], a1, b);
            }
        }

#pragma unroll
        for (int i = 0; i < 2; i++) {
#pragma unroll
            for (int half = 0; half < 2; half++) {
                int gr = r0 + mw * 32 + i * 16 + half * 8 + (L >> 2);
                if (gr < N_NODES) {
#pragma unroll
                    for (int j = 0; j < 8; j++) {
                        int c = nwg * 32 + (j & 3) * 8 + (L & 3) * 2;
                        float2 res;
                        res.x = acc[i][j][half * 2 + 0];
                        res.y = acc[i][j][half * 2 + 1];
                        if (j < 4) {
                            res.x += bs[c]; res.y += bs[c + 1];
                            *reinterpret_cast<float2*>(&Y1[gr * HID + c]) = res;
                        } else {
                            *reinterpret_cast<float2*>(&Y2[gr * HID + c]) = res;
                        }
                    }
                }
            }
        }
        __syncthreads();
    }
}

// ---------------- gemm_k256: Y = silu([X1, X2]@W + b), clears X2 ----------------
// W is [256][128] row-major. smem: Wts [128][268] @0, Xs [64][268] @34304, bs @51456
#define K256_SMEM ((34304 + 17152 + 128) * 4)

__global__ void __launch_bounds__(256, 1)
gemm_k256(const float* __restrict__ X1, float* __restrict__ X2,
          const float* __restrict__ W, const float* __restrict__ bias, float* __restrict__ Y) {
    extern __shared__ float sm[];
    float* Wts = sm;             // [128 c][268 k], k 0..255
    float* Xs = sm + 34304;      // [64][268]
    float* bs = sm + 51456;
    int tid = threadIdx.x;

    // transpose-load W (256 k-rows x 128 cols)
    for (int idx = tid; idx < 8192; idx += 256) {
        int k = idx >> 5, c0 = (idx & 31) * 4;
        float4 v = reinterpret_cast<const float4*>(W)[idx];
        *(uint32_t*)&Wts[(c0 + 0) * 268 + k] = to_tf32(v.x);
        *(uint32_t*)&Wts[(c0 + 1) * 268 + k] = to_tf32(v.y);
        *(uint32_t*)&Wts[(c0 + 2) * 268 + k] = to_tf32(v.z);
        *(uint32_t*)&Wts[(c0 + 3) * 268 + k] = to_tf32(v.w);
    }
    if (tid < 128) bs[tid] = bias[tid];
    __syncthreads();

    uint32_t XsA = smem_u32(Xs), WtA = smem_u32(Wts);
    int L = tid & 31, w = tid >> 5;
    int mw = w & 1, nwg = w >> 1;
    int aRow = ((L >> 3) & 1) * 8 + (L & 7);
    uint32_t aBase0 = XsA + (uint32_t)(mw * 32 + aRow) * 1072 + (uint32_t)(L >> 4) * 16;
    uint32_t aBase1 = aBase0 + 16 * 1072;
    int Ln = L & 15;
    uint32_t bBase[4];
#pragma unroll
    for (int j = 0; j < 4; j++)
        bBase[j] = WtA + (uint32_t)((nwg * 4 + j) * 8 + (Ln & 7)) * 1072 + (uint32_t)(Ln >> 3) * 16;

    for (int tile = blockIdx.x; tile < NT_N; tile += gridDim.x) {
        int r0 = tile * 64;
        for (int idx = tid; idx < 2048; idx += 256) {
            int r = idx >> 5, k4 = (idx & 31) * 4;
            int gr = r0 + r;
            float4 v1 = make_float4(0.f, 0.f, 0.f, 0.f);
            float4 v2 = make_float4(0.f, 0.f, 0.f, 0.f);
            if (gr < N_NODES) {
                v1 = *reinterpret_cast<const float4*>(&X1[gr * HID + k4]);
                v2 = *reinterpret_cast<float4*>(&X2[gr * HID + k4]);
                *reinterpret_cast<float4*>(&X2[gr * HID + k4]) = make_float4(0.f, 0.f, 0.f, 0.f);
            }
            uint4 t;
            t.x = to_tf32(v1.x); t.y = to_tf32(v1.y); t.z = to_tf32(v1.z); t.w = to_tf32(v1.w);
            *reinterpret_cast<uint4*>(&Xs[r * 268 + k4]) = t;
            t.x = to_tf32(v2.x); t.y = to_tf32(v2.y); t.z = to_tf32(v2.z); t.w = to_tf32(v2.w);
            *reinterpret_cast<uint4*>(&Xs[r * 268 + 128 + k4]) = t;
        }
        __syncthreads();

        float acc[2][4][4];
#pragma unroll
        for (int i = 0; i < 2; i++)
#pragma unroll
            for (int j = 0; j < 4; j++)
#pragma unroll
                for (int e = 0; e < 4; e++) acc[i][j][e] = 0.0f;

#pragma unroll
        for (int kc = 0; kc < 32; kc++) {
            uint32_t a0[4], a1[4];
            ldsm_x4(a0, aBase0 + kc * 32);
            ldsm_x4(a1, aBase1 + kc * 32);
#pragma unroll
            for (int j = 0; j < 4; j++) {
                uint32_t b[2];
                ldsm_x2(b, bBase[j] + kc * 32);
                mma_tf32(acc[0][j], a0, b);
                mma_tf32(acc[1][j], a1, b);
            }
        }

#pragma unroll
        for (int i = 0; i < 2; i++) {
#pragma unroll
            for (int half = 0; half < 2; half++) {
                int gr = r0 + mw * 32 + i * 16 + half * 8 + (L >> 2);
                if (gr < N_NODES) {
#pragma unroll
                    for (int j = 0; j < 4; j++) {
                        int c = nwg * 32 + j * 8 + (L & 3) * 2;
                        float2 res;
                        res.x = silu_f(acc[i][j][half * 2 + 0] + bs[c]);
                        res.y = silu_f(acc[i][j][half * 2 + 1] + bs[c + 1]);
                        *reinterpret_cast<float2*>(&Y[gr * HID + c]) = res;
                    }
                }
            }
        }
        __syncthreads();
    }
}

// ---------------- mma edge kernel: 128-edge tiles, 512 threads ----------------
#define EDGE_SMEM (52352 * 4)

__global__ void __launch_bounds__(512, 1)
edge_mma(const int* __restrict__ row, const int* __restrict__ col,
         const float* __restrict__ ea,
         const float* __restrict__ W2, const float* __restrict__ b2,
         const float* __restrict__ Wc1, const float* __restrict__ bc1,
         const float* __restrict__ wc2,
         const float* __restrict__ wr, const float* __restrict__ we) {
    extern __shared__ float sm[];
    float* W2s = sm;
    float* Wc1s = sm + 16896;
    float* tS = sm + 33792;
    float* b2s = sm + 50688;
    float* bc1s = sm + 50816;
    float* wc2s = sm + 50944;
    float* wrs = sm + 51072;
    float* wes = sm + 51200;
    float* diffs = sm + 51328;
    float* cw_part = sm + 51712;
    int* rows_s = (int*)(sm + 52224);

    int tid = threadIdx.x;
    load_w_trans(W2, W2s, tid, 512, 132);
    load_w_trans(Wc1, Wc1s, tid, 512, 132);
    if (tid < 128) {
        b2s[tid] = b2[tid]; bc1s[tid] = bc1[tid]; wc2s[tid] = wc2[tid];
        wrs[tid] = wr[tid]; wes[tid] = we[tid];
    }
    __syncthreads();

    uint32_t tSA = smem_u32(tS);
    uint32_t W2A = smem_u32(W2s), Wc1A = smem_u32(Wc1s);
    int L = tid & 31, w = tid >> 5;
    int mw = w >> 2, nwg = w & 3;
    int aRow = ((L >> 3) & 1) * 8 + (L & 7);
    uint32_t aOff = (uint32_t)(mw * 32 + aRow) * 528 + (uint32_t)(L >> 4) * 16;
    int Ln = L & 15;
    uint32_t bOff[4];
#pragma unroll
    for (int j = 0; j < 4; j++)
        bOff[j] = (uint32_t)((nwg * 4 + j) * 8 + (Ln & 7)) * 528 + (uint32_t)(Ln >> 3) * 16;

    int e_loc = tid >> 2, q = tid & 3;

    for (int tile = blockIdx.x; tile < NT_E; tile += gridDim.x) {
        int e0 = tile * 128;
        {
            int e = e0 + e_loc;
            if (e < N_EDGES) {
                int r = row[e], c = col[e];
                float dx = d_coord[r * 3 + 0] - d_coord[c * 3 + 0];
                float dy = d_coord[r * 3 + 1] - d_coord[c * 3 + 1];
                float dz = d_coord[r * 3 + 2] - d_coord[c * 3 + 2];
                float radial = dx * dx + dy * dy + dz * dz;
                float eav = ea[e];
                if (q == 0) {
                    rows_s[e_loc] = r;
                    diffs[e_loc * 3 + 0] = dx; diffs[e_loc * 3 + 1] = dy; diffs[e_loc * 3 + 2] = dz;
                }
#pragma unroll
                for (int jj = 0; jj < 8; jj++) {
                    int ch = q * 32 + jj * 4;
                    float4 av = *reinterpret_cast<const float4*>(&d_A[r * HID + ch]);
                    float4 bv = *reinterpret_cast<const float4*>(&d_B[c * HID + ch]);
                    float4 w1 = *reinterpret_cast<const float4*>(&wrs[ch]);
                    float4 w2v = *reinterpret_cast<const float4*>(&wes[ch]);
                    uint4 t;
                    t.x = to_tf32(silu_f(av.x + bv.x + radial * w1.x + eav * w2v.x));
                    t.y = to_tf32(silu_f(av.y + bv.y + radial * w1.y + eav * w2v.y));
                    t.z = to_tf32(silu_f(av.z + bv.z + radial * w1.z + eav * w2v.z));
                    t.w = to_tf32(silu_f(av.w + bv.w + radial * w1.w + eav * w2v.w));
                    *reinterpret_cast<uint4*>(&tS[e_loc * 132 + ch]) = t;
                }
            } else {
                if (q == 0) {
                    rows_s[e_loc] = -1;
                    diffs[e_loc * 3 + 0] = 0.f; diffs[e_loc * 3 + 1] = 0.f; diffs[e_loc * 3 + 2] = 0.f;
                }
#pragma unroll
                for (int jj = 0; jj < 8; jj++) {
                    int ch = q * 32 + jj * 4;
                    *reinterpret_cast<uint4*>(&tS[e_loc * 132 + ch]) = make_uint4(0, 0, 0, 0);
                }
            }
        }
        __syncthreads();

        // MMA1: D1 = tS @ W2^T
        float acc[2][4][4];
#pragma unroll
        for (int i = 0; i < 2; i++)
#pragma unroll
            for (int j = 0; j < 4; j++)
#pragma unroll
                for (int e = 0; e < 4; e++) acc[i][j][e] = 0.0f;
#pragma unroll
        for (int kc = 0; kc < 16; kc++) {
            uint32_t a0[4], a1[4];
            ldsm_x4(a0, tSA + aOff + kc * 32);
            ldsm_x4(a1, tSA + aOff + 16 * 528 + kc * 32);
#pragma unroll
            for (int j = 0; j < 4; j++) {
                uint32_t b[2];
                ldsm_x2(b, W2A + bOff[j] + kc * 32);
                mma_tf32(acc[0][j], a0, b);
                mma_tf32(acc[1][j], a1, b);
            }
        }

        // epilogue1 (per-warp band, no sync needed)
#pragma unroll
        for (int i = 0; i < 2; i++) {
#pragma unroll
            for (int half = 0; half < 2; half++) {
                int rowl = mw * 32 + i * 16 + half * 8 + (L >> 2);
                int rn = rows_s[rowl];
#pragma unroll
                for (int j = 0; j < 4; j++) {
                    int c = nwg * 32 + j * 8 + (L & 3) * 2;
                    float m0 = silu_f(acc[i][j][half * 2 + 0] + b2s[c]);
                    float m1 = silu_f(acc[i][j][half * 2 + 1] + b2s[c + 1]);
                    if (rn >= 0) {
                        atomicAdd(&d_magg[rn * HID + c + 0], m0);
                        atomicAdd(&d_magg[rn * HID + c + 1], m1);
                    }
                    uint2 t;
                    t.x = to_tf32(m0); t.y = to_tf32(m1);
                    *reinterpret_cast<uint2*>(&tS[rowl * 132 + c]) = t;
                }
            }
        }

        // MMA2: D2 = mS @ Wc1^T
#pragma unroll
        for (int i = 0; i < 2; i++)
#pragma unroll
            for (int j = 0; j < 4; j++)
#pragma unroll
                for (int e = 0; e < 4; e++) acc[i][j][e] = 0.0f;
#pragma unroll
        for (int kc = 0; kc < 16; kc++) {
            uint32_t a0[4], a1[4];
            ldsm_x4(a0, tSA + aOff + kc * 32);
            ldsm_x4(a1, tSA + aOff + 16 * 528 + kc * 32);
#pragma unroll
            for (int j = 0; j < 4; j++) {
                uint32_t b[2];
                ldsm_x2(b, Wc1A + bOff[j] + kc * 32);
                mma_tf32(acc[0][j], a0, b);
                mma_tf32(acc[1][j], a1, b);
            }
        }

        // epilogue2
#pragma unroll
        for (int i = 0; i < 2; i++) {
#pragma unroll
            for (int half = 0; half < 2; half++) {
                float p = 0.0f;
#pragma unroll
                for (int j = 0; j < 4; j++) {
                    int c = nwg * 32 + j * 8 + (L & 3) * 2;
                    p += silu_f(acc[i][j][half * 2 + 0] + bc1s[c]) * wc2s[c];
                    p += silu_f(acc[i][j][half * 2 + 1] + bc1s[c + 1]) * wc2s[c + 1];
                }
                p += __shfl_xor_sync(0xffffffff, p, 1);
                p += __shfl_xor_sync(0xffffffff, p, 2);
                if ((L & 3) == 0) {
                    int rowl = mw * 32 + i * 16 + half * 8 + (L >> 2);
                    cw_part[nwg * 128 + rowl] = p;
                }
            }
        }
        __syncthreads();
        if (tid < 128) {
            int rn = rows_s[tid];
            if (rn >= 0) {
                float cw = cw_part[tid] + cw_part[128 + tid] + cw_part[256 + tid] + cw_part[384 + tid];
                atomicAdd(&d_cagg[rn * 3 + 0], diffs[tid * 3 + 0] * cw);
                atomicAdd(&d_cagg[rn * 3 + 1], diffs[tid * 3 + 1] * cw);
                atomicAdd(&d_cagg[rn * 3 + 2], diffs[tid * 3 + 2] * cw);
            }
        }
        __syncthreads();
    }
}

// ---------------- coord update ----------------
__global__ void coord_kernel() {
    int n = blockIdx.x * blockDim.x + threadIdx.x;
    if (n < N_NODES) {
        float inv = 1.0f / fmaxf(d_deg[n], 1.0f);
#pragma unroll
        for (int dd = 0; dd < 3; dd++) {
            d_coord[n * 3 + dd] += d_cagg[n * 3 + dd] * inv;
            d_cagg[n * 3 + dd] = 0.0f;
        }
    }
}

// ---------------- global mean pool ----------------
__global__ void pool_kernel(const int* __restrict__ batch) {
    int n0 = blockIdx.x * 512;
    int ch = threadIdx.x;
    if (n0 >= N_NODES) return;
    int nend = min(n0 + 512, N_NODES);
    int cur = batch[n0];
    float acc = 0.0f, cnt = 0.0f;
    for (int n = n0; n < nend; n++) {
        int g = batch[n];
        if (g != cur) {
            atomicAdd(&d_gsum[cur * HID + ch], acc);
            if (ch == 0) atomicAdd(&d_gcnt[cur], cnt);
            acc = 0.0f; cnt = 0.0f; cur = g;
        }
        acc += d_A[n * HID + ch];
        cnt += 1.0f;
    }
    atomicAdd(&d_gsum[cur * HID + ch], acc);
    if (ch == 0) atomicAdd(&d_gcnt[cur], cnt);
}

// ---------------- final fc ----------------
__global__ void fc_kernel(const float* __restrict__ fcw, const float* __restrict__ fcb,
                          float* __restrict__ out) {
    int g = blockIdx.x;
    int ch = threadIdx.x;
    float inv = 1.0f / fmaxf(d_gcnt[g], 1.0f);
    float acc = fcb[ch];
    for (int k = 0; k < HID; k++)
        acc += d_gsum[g * HID + k] * inv * fcw[k * OUT_DIM + ch];
    out[g * OUT_DIM + ch] = acc;
}

// ---------------- launch ----------------
#define GRID_G 296
#define GRID_F 148
#define GRID_E 148

extern "C" void kernel_launch(void* const* d_in, const int* in_sizes, int n_in,
                              void* d_out, int out_size) {
    const float* x = (const float*)d_in[0];
    const int* eidx = (const int*)d_in[1];
    const float* coord = (const float*)d_in[2];
    const float* ea = (const float*)d_in[3];
    const int* batch = (const int*)d_in[4];
    const float* emb_in_w = (const float*)d_in[5];
    const float* emb_in_b = (const float*)d_in[6];
    const float* edge_w1 = (const float*)d_in[7];
    const float* edge_b1 = (const float*)d_in[8];
    const float* edge_w2 = (const float*)d_in[9];
    const float* edge_b2 = (const float*)d_in[10];
    const float* node_w1 = (const float*)d_in[11];
    const float* node_b1 = (const float*)d_in[12];
    const float* node_w2 = (const float*)d_in[13];
    const float* node_b2 = (const float*)d_in[14];
    const float* coord_w1 = (const float*)d_in[15];
    const float* coord_b1 = (const float*)d_in[16];
    const float* coord_w2 = (const float*)d_in[17];
    const float* emb_out_w = (const float*)d_in[18];
    const float* emb_out_b = (const float*)d_in[19];
    const float* fc_w = (const float*)d_in[20];
    const float* fc_b = (const float*)d_in[21];
    float* out = (float*)d_out;

    const int* row = eidx;
    const int* col = eidx + N_EDGES;

    float *ph, *pA, *pB, *pT, *pmagg;
    cudaGetSymbolAddress((void**)&ph, d_h);
    cudaGetSymbolAddress((void**)&pA, d_A);
    cudaGetSymbolAddress((void**)&pB, d_B);
    cudaGetSymbolAddress((void**)&pT, d_T);
    cudaGetSymbolAddress((void**)&pmagg, d_magg);

    cudaFuncSetAttribute(edge_mma, cudaFuncAttributeMaxDynamicSharedMemorySize, EDGE_SMEM);
    cudaFuncSetAttribute(gemm_mma, cudaFuncAttributeMaxDynamicSharedMemorySize, GEMM_SMEM);
    cudaFuncSetAttribute(gemm_ab, cudaFuncAttributeMaxDynamicSharedMemorySize, AB_SMEM);
    cudaFuncSetAttribute(gemm_k256, cudaFuncAttributeMaxDynamicSharedMemorySize, K256_SMEM);

    // launch order: edge_mma is our 4th launch -> ncu capture slot
    init_kernel<<<(N_NODES * HID + 255) / 256, 256>>>(coord);
    emb_in_kernel<<<(N_NODES * HID + 255) / 256, 256>>>(x, emb_in_w, emb_in_b);

    for (int l = 0; l < N_LAYERS; l++) {
        const float* W1 = edge_w1 + l * 258 * HID;
        gemm_ab<<<GRID_F, 256, AB_SMEM>>>(ph, W1, W1 + 128 * HID, edge_b1 + l * HID, pA, pB);
        edge_mma<<<GRID_E, 512, EDGE_SMEM>>>(row, col, ea,
            edge_w2 + l * HID * HID, edge_b2 + l * HID,
            coord_w1 + l * HID * HID, coord_b1 + l * HID, coord_w2 + l * HID,
            W1 + 256 * HID, W1 + 257 * HID);
        if (l == 0) deg_kernel<<<(N_EDGES + 255) / 256, 256>>>(row);
        coord_kernel<<<(N_NODES + 255) / 256, 256>>>();
        gemm_k256<<<GRID_F, 256, K256_SMEM>>>(ph, pmagg, node_w1 + l * 256 * HID,
                                              node_b1 + l * HID, pT);
        gemm_mma<<<GRID_G, 256, GEMM_SMEM>>>(pT, node_w2 + l * HID * HID,
                                             node_b2 + l * HID, ph, GM_BIAS | GM_ACC);
    }

    gemm_mma<<<GRID_G, 256, GEMM_SMEM>>>(ph, emb_out_w, emb_out_b, pA, GM_BIAS);
    pool_kernel<<<(N_NODES + 511) / 512, 128>>>(batch);
    fc_kernel<<<N_GRAPHS, 256>>>(fc_w, fc_b, out);
}

// round 11
// speedup vs baseline: 1.6327x; 1.1284x over previous
#include <cuda_runtime.h>
#include <math.h>
#include <stdint.h>

#define N_NODES 50000
#define N_EDGES 600000
#define N_GRAPHS 64
#define HID 128
#define IN_DIM 16
#define OUT_DIM 256
#define N_LAYERS 3
#define NT_E 4688            // ceil(600000/128)
#define NT_N 782             // ceil(50000/64)
#define SCAN_B 98            // ceil(50000/512)

// ---------------- device scratch ----------------
__device__ float d_h[N_NODES * HID];
__device__ float d_A[N_NODES * HID];
__device__ float d_B[N_NODES * HID];
__device__ float d_T[N_NODES * HID];
__device__ float d_magg[N_NODES * HID];
__device__ float d_cagg[N_NODES * 3];
__device__ float d_coord[N_NODES * 3];
__device__ float d_gsum[N_GRAPHS * HID];
__device__ float d_gcnt[N_GRAPHS];
// edge sort
__device__ int d_cnt[N_NODES];
__device__ int d_cur[N_NODES];
__device__ int d_base[N_NODES];
__device__ int d_bsum[SCAN_B];
__device__ int d_erow[N_EDGES];
__device__ int d_ecol[N_EDGES];
__device__ float d_eea[N_EDGES];

// silu via tanh.approx: 1 MUFU
__device__ __forceinline__ float silu_f(float x) {
    float t;
    asm("tanh.approx.f32 %0, %1;" : "=f"(t) : "f"(x * 0.5f));
    return 0.5f * x * (1.0f + t);
}
__device__ __forceinline__ uint32_t smem_u32(const void* p) {
    uint32_t a;
    asm("{ .reg .u64 t; cvta.to.shared.u64 t, %1; cvt.u32.u64 %0, t; }" : "=r"(a) : "l"(p));
    return a;
}
__device__ __forceinline__ uint32_t to_tf32(float f) {
    uint32_t o;
    asm("cvt.rna.tf32.f32 %0, %1;" : "=r"(o) : "f"(f));
    return o;
}
__device__ __forceinline__ void ldsm_x4(uint32_t a[4], uint32_t addr) {
    asm volatile("ldmatrix.sync.aligned.m8n8.x4.shared.b16 {%0,%1,%2,%3}, [%4];"
        : "=r"(a[0]), "=r"(a[1]), "=r"(a[2]), "=r"(a[3]) : "r"(addr));
}
__device__ __forceinline__ void ldsm_x2(uint32_t b[2], uint32_t addr) {
    asm volatile("ldmatrix.sync.aligned.m8n8.x2.shared.b16 {%0,%1}, [%2];"
        : "=r"(b[0]), "=r"(b[1]) : "r"(addr));
}
__device__ __forceinline__ void mma_tf32(float d[4], const uint32_t a[4], const uint32_t b[2]) {
    asm volatile("mma.sync.aligned.m16n8k8.row.col.f32.tf32.tf32.f32 "
        "{%0,%1,%2,%3}, {%4,%5,%6,%7}, {%8,%9}, {%0,%1,%2,%3};"
        : "+f"(d[0]), "+f"(d[1]), "+f"(d[2]), "+f"(d[3])
        : "r"(a[0]), "r"(a[1]), "r"(a[2]), "r"(a[3]), "r"(b[0]), "r"(b[1]));
}

// ---------------- init ----------------
__global__ void init_kernel(const float* __restrict__ coord_in) {
    int idx = blockIdx.x * blockDim.x + threadIdx.x;
    if (idx < N_NODES * HID) d_magg[idx] = 0.0f;
    if (idx < N_NODES * 3) { d_cagg[idx] = 0.0f; d_coord[idx] = coord_in[idx]; }
    if (idx < N_NODES) { d_cnt[idx] = 0; d_cur[idx] = 0; }
    if (idx < N_GRAPHS * HID) d_gsum[idx] = 0.0f;
    if (idx < N_GRAPHS) d_gcnt[idx] = 0.0f;
}

// ---------------- edge sort pre-pass ----------------
__global__ void hist_kernel(const int* __restrict__ row) {
    int e = blockIdx.x * blockDim.x + threadIdx.x;
    if (e < N_EDGES) atomicAdd(&d_cnt[row[e]], 1);
}
__global__ void scan1_kernel() {
    __shared__ int s[512];
    int tid = threadIdx.x;
    int i = blockIdx.x * 512 + tid;
    int v = (i < N_NODES) ? d_cnt[i] : 0;
    s[tid] = v;
    __syncthreads();
    for (int off = 1; off < 512; off <<= 1) {
        int t = (tid >= off) ? s[tid - off] : 0;
        __syncthreads();
        s[tid] += t;
        __syncthreads();
    }
    if (i < N_NODES) d_base[i] = s[tid] - v;
    if (tid == 511) d_bsum[blockIdx.x] = s[511];
}
__global__ void scan2_kernel() {
    if (threadIdx.x == 0) {
        int acc = 0;
        for (int b = 0; b < SCAN_B; b++) { int t = d_bsum[b]; d_bsum[b] = acc; acc += t; }
    }
}
__global__ void scan3_kernel() {
    int i = blockIdx.x * blockDim.x + threadIdx.x;
    if (i < N_NODES) d_base[i] += d_bsum[i >> 9];
}
__global__ void scatter_kernel(const int* __restrict__ row, const int* __restrict__ col,
                               const float* __restrict__ ea) {
    int e = blockIdx.x * blockDim.x + threadIdx.x;
    if (e < N_EDGES) {
        int r = row[e];
        int p = d_base[r] + atomicAdd(&d_cur[r], 1);
        d_erow[p] = r;
        d_ecol[p] = col[e];
        d_eea[p] = ea[e];
    }
}

__global__ void emb_in_kernel(const float* __restrict__ x,
                              const float* __restrict__ w,
                              const float* __restrict__ b) {
    int idx = blockIdx.x * blockDim.x + threadIdx.x;
    if (idx >= N_NODES * HID) return;
    int n = idx >> 7, ch = idx & 127;
    float acc = b[ch];
#pragma unroll
    for (int k = 0; k < IN_DIM; k++) acc += x[n * IN_DIM + k] * w[k * HID + ch];
    d_h[idx] = acc;
}

// store W[k][c] (row-major, 128x128) transposed+tf32 into Ws[c][k] (stride floats)
__device__ __forceinline__ void load_w_trans(const float* __restrict__ W, float* __restrict__ Ws,
                                             int tid, int nthreads, int stride) {
    for (int idx = tid; idx < 4096; idx += nthreads) {
        int k = idx >> 5, c0 = (idx & 31) * 4;
        float4 v = reinterpret_cast<const float4*>(W)[idx];
        *(uint32_t*)&Ws[(c0 + 0) * stride + k] = to_tf32(v.x);
        *(uint32_t*)&Ws[(c0 + 1) * stride + k] = to_tf32(v.y);
        *(uint32_t*)&Ws[(c0 + 2) * stride + k] = to_tf32(v.z);
        *(uint32_t*)&Ws[(c0 + 3) * stride + k] = to_tf32(v.w);
    }
}

// ---------------- gemm_mma: Y = op(X@W (+bias) (+Y)) ----------------
#define GEMM_SMEM ((16896 + 8448 + 128) * 4)
#define GM_BIAS 1
#define GM_ACC 2
#define GM_SILU 4

__global__ void __launch_bounds__(256, 2)
gemm_mma(float* __restrict__ X, const float* __restrict__ W,
         const float* __restrict__ bias, float* __restrict__ Y, int mode) {
    extern __shared__ float sm[];
    float* Wts = sm;
    float* Xs = sm + 16896;
    float* bs = sm + 25344;
    int tid = threadIdx.x;

    load_w_trans(W, Wts, tid, 256, 132);
    if (tid < 128) bs[tid] = (mode & GM_BIAS) ? bias[tid] : 0.0f;
    __syncthreads();

    uint32_t XsA = smem_u32(Xs), WtA = smem_u32(Wts);
    int L = tid & 31, w = tid >> 5;
    int mw = w & 1, nwg = w >> 1;
    int aRow = ((L >> 3) & 1) * 8 + (L & 7);
    uint32_t aBase0 = XsA + (uint32_t)(mw * 32 + aRow) * 528 + (uint32_t)(L >> 4) * 16;
    uint32_t aBase1 = aBase0 + 16 * 528;
    int Ln = L & 15;
    uint32_t bBase[4];
#pragma unroll
    for (int j = 0; j < 4; j++)
        bBase[j] = WtA + (uint32_t)((nwg * 4 + j) * 8 + (Ln & 7)) * 528 + (uint32_t)(Ln >> 3) * 16;

    for (int tile = blockIdx.x; tile < NT_N; tile += gridDim.x) {
        int r0 = tile * 64;
        for (int idx = tid; idx < 2048; idx += 256) {
            int r = idx >> 5, k4 = (idx & 31) * 4;
            int gr = r0 + r;
            float4 v = make_float4(0.f, 0.f, 0.f, 0.f);
            if (gr < N_NODES) v = *reinterpret_cast<const float4*>(&X[gr * HID + k4]);
            uint4 t;
            t.x = to_tf32(v.x); t.y = to_tf32(v.y); t.z = to_tf32(v.z); t.w = to_tf32(v.w);
            *reinterpret_cast<uint4*>(&Xs[r * 132 + k4]) = t;
        }
        __syncthreads();

        float acc[2][4][4];
#pragma unroll
        for (int i = 0; i < 2; i++)
#pragma unroll
            for (int j = 0; j < 4; j++)
#pragma unroll
                for (int e = 0; e < 4; e++) acc[i][j][e] = 0.0f;

#pragma unroll
        for (int kc = 0; kc < 16; kc++) {
            uint32_t a0[4], a1[4];
            ldsm_x4(a0, aBase0 + kc * 32);
            ldsm_x4(a1, aBase1 + kc * 32);
#pragma unroll
            for (int j = 0; j < 4; j++) {
                uint32_t b[2];
                ldsm_x2(b, bBase[j] + kc * 32);
                mma_tf32(acc[0][j], a0, b);
                mma_tf32(acc[1][j], a1, b);
            }
        }

#pragma unroll
        for (int i = 0; i < 2; i++) {
#pragma unroll
            for (int half = 0; half < 2; half++) {
                int gr = r0 + mw * 32 + i * 16 + half * 8 + (L >> 2);
                if (gr < N_NODES) {
#pragma unroll
                    for (int j = 0; j < 4; j++) {
                        int c = nwg * 32 + j * 8 + (L & 3) * 2;
                        float2 res;
                        res.x = acc[i][j][half * 2 + 0] + bs[c];
                        res.y = acc[i][j][half * 2 + 1] + bs[c + 1];
                        float* yp = &Y[gr * HID + c];
                        if (mode & GM_ACC) {
                            float2 o = *reinterpret_cast<float2*>(yp);
                            res.x += o.x; res.y += o.y;
                        }
                        if (mode & GM_SILU) { res.x = silu_f(res.x); res.y = silu_f(res.y); }
                        *reinterpret_cast<float2*>(yp) = res;
                    }
                }
            }
        }
        __syncthreads();
    }
}

// ---------------- gemm_ab: Y1 = X@Wa + b, Y2 = X@Wb ----------------
#define AB_SMEM ((33792 + 8448 + 128) * 4)

__global__ void __launch_bounds__(256, 1)
gemm_ab(const float* __restrict__ X, const float* __restrict__ Wa, const float* __restrict__ Wb,
        const float* __restrict__ bias, float* __restrict__ Y1, float* __restrict__ Y2) {
    extern __shared__ float sm[];
    float* Wts = sm;
    float* Xs = sm + 33792;
    float* bs = sm + 42240;
    int tid = threadIdx.x;

    load_w_trans(Wa, Wts, tid, 256, 132);
    load_w_trans(Wb, Wts + 128 * 132, tid, 256, 132);
    if (tid < 128) bs[tid] = bias[tid];
    __syncthreads();

    uint32_t XsA = smem_u32(Xs), WtA = smem_u32(Wts);
    int L = tid & 31, w = tid >> 5;
    int mw = w & 1, nwg = w >> 1;
    int aRow = ((L >> 3) & 1) * 8 + (L & 7);
    uint32_t aBase0 = XsA + (uint32_t)(mw * 32 + aRow) * 528 + (uint32_t)(L >> 4) * 16;
    uint32_t aBase1 = aBase0 + 16 * 528;
    int Ln = L & 15;
    uint32_t bBase[8];
#pragma unroll
    for (int j = 0; j < 8; j++) {
        int blk = (j < 4) ? (nwg * 4 + j) : (16 + nwg * 4 + (j - 4));
        bBase[j] = WtA + (uint32_t)(blk * 8 + (Ln & 7)) * 528 + (uint32_t)(Ln >> 3) * 16;
    }

    for (int tile = blockIdx.x; tile < NT_N; tile += gridDim.x) {
        int r0 = tile * 64;
        for (int idx = tid; idx < 2048; idx += 256) {
            int r = idx >> 5, k4 = (idx & 31) * 4;
            int gr = r0 + r;
            float4 v = make_float4(0.f, 0.f, 0.f, 0.f);
            if (gr < N_NODES) v = *reinterpret_cast<const float4*>(&X[gr * HID + k4]);
            uint4 t;
            t.x = to_tf32(v.x); t.y = to_tf32(v.y); t.z = to_tf32(v.z); t.w = to_tf32(v.w);
            *reinterpret_cast<uint4*>(&Xs[r * 132 + k4]) = t;
        }
        __syncthreads();

        float acc[2][8][4];
#pragma unroll
        for (int i = 0; i < 2; i++)
#pragma unroll
            for (int j = 0; j < 8; j++)
#pragma unroll
                for (int e = 0; e < 4; e++) acc[i][j][e] = 0.0f;

#pragma unroll
        for (int kc = 0; kc < 16; kc++) {
            uint32_t a0[4], a1[4];
            ldsm_x4(a0, aBase0 + kc * 32);
            ldsm_x4(a1, aBase1 + kc * 32);
#pragma unroll
            for (int j = 0; j < 8; j++) {
                uint32_t b[2];
                ldsm_x2(b, bBase[j] + kc * 32);
                mma_tf32(acc[0][j], a0, b);
                mma_tf32(acc[1][j], a1, b);
            }
        }

#pragma unroll
        for (int i = 0; i < 2; i++) {
#pragma unroll
            for (int half = 0; half < 2; half++) {
                int gr = r0 + mw * 32 + i * 16 + half * 8 + (L >> 2);
                if (gr < N_NODES) {
#pragma unroll
                    for (int j = 0; j < 8; j++) {
                        int c = nwg * 32 + (j & 3) * 8 + (L & 3) * 2;
                        float2 res;
                        res.x = acc[i][j][half * 2 + 0];
                        res.y = acc[i][j][half * 2 + 1];
                        if (j < 4) {
                            res.x += bs[c]; res.y += bs[c + 1];
                            *reinterpret_cast<float2*>(&Y1[gr * HID + c]) = res;
                        } else {
                            *reinterpret_cast<float2*>(&Y2[gr * HID + c]) = res;
                        }
                    }
                }
            }
        }
        __syncthreads();
    }
}

// ---------------- gemm_k256: Y = silu([X1, X2]@W + b), clears X2 ----------------
#define K256_SMEM ((34304 + 17152 + 128) * 4)

__global__ void __launch_bounds__(256, 1)
gemm_k256(const float* __restrict__ X1, float* __restrict__ X2,
          const float* __restrict__ W, const float* __restrict__ bias, float* __restrict__ Y) {
    extern __shared__ float sm[];
    float* Wts = sm;
    float* Xs = sm + 34304;
    float* bs = sm + 51456;
    int tid = threadIdx.x;

    for (int idx = tid; idx < 8192; idx += 256) {
        int k = idx >> 5, c0 = (idx & 31) * 4;
        float4 v = reinterpret_cast<const float4*>(W)[idx];
        *(uint32_t*)&Wts[(c0 + 0) * 268 + k] = to_tf32(v.x);
        *(uint32_t*)&Wts[(c0 + 1) * 268 + k] = to_tf32(v.y);
        *(uint32_t*)&Wts[(c0 + 2) * 268 + k] = to_tf32(v.z);
        *(uint32_t*)&Wts[(c0 + 3) * 268 + k] = to_tf32(v.w);
    }
    if (tid < 128) bs[tid] = bias[tid];
    __syncthreads();

    uint32_t XsA = smem_u32(Xs), WtA = smem_u32(Wts);
    int L = tid & 31, w = tid >> 5;
    int mw = w & 1, nwg = w >> 1;
    int aRow = ((L >> 3) & 1) * 8 + (L & 7);
    uint32_t aBase0 = XsA + (uint32_t)(mw * 32 + aRow) * 1072 + (uint32_t)(L >> 4) * 16;
    uint32_t aBase1 = aBase0 + 16 * 1072;
    int Ln = L & 15;
    uint32_t bBase[4];
#pragma unroll
    for (int j = 0; j < 4; j++)
        bBase[j] = WtA + (uint32_t)((nwg * 4 + j) * 8 + (Ln & 7)) * 1072 + (uint32_t)(Ln >> 3) * 16;

    for (int tile = blockIdx.x; tile < NT_N; tile += gridDim.x) {
        int r0 = tile * 64;
        for (int idx = tid; idx < 2048; idx += 256) {
            int r = idx >> 5, k4 = (idx & 31) * 4;
            int gr = r0 + r;
            float4 v1 = make_float4(0.f, 0.f, 0.f, 0.f);
            float4 v2 = make_float4(0.f, 0.f, 0.f, 0.f);
            if (gr < N_NODES) {
                v1 = *reinterpret_cast<const float4*>(&X1[gr * HID + k4]);
                v2 = *reinterpret_cast<float4*>(&X2[gr * HID + k4]);
                *reinterpret_cast<float4*>(&X2[gr * HID + k4]) = make_float4(0.f, 0.f, 0.f, 0.f);
            }
            uint4 t;
            t.x = to_tf32(v1.x); t.y = to_tf32(v1.y); t.z = to_tf32(v1.z); t.w = to_tf32(v1.w);
            *reinterpret_cast<uint4*>(&Xs[r * 268 + k4]) = t;
            t.x = to_tf32(v2.x); t.y = to_tf32(v2.y); t.z = to_tf32(v2.z); t.w = to_tf32(v2.w);
            *reinterpret_cast<uint4*>(&Xs[r * 268 + 128 + k4]) = t;
        }
        __syncthreads();

        float acc[2][4][4];
#pragma unroll
        for (int i = 0; i < 2; i++)
#pragma unroll
            for (int j = 0; j < 4; j++)
#pragma unroll
                for (int e = 0; e < 4; e++) acc[i][j][e] = 0.0f;

#pragma unroll
        for (int kc = 0; kc < 32; kc++) {
            uint32_t a0[4], a1[4];
            ldsm_x4(a0, aBase0 + kc * 32);
            ldsm_x4(a1, aBase1 + kc * 32);
#pragma unroll
            for (int j = 0; j < 4; j++) {
                uint32_t b[2];
                ldsm_x2(b, bBase[j] + kc * 32);
                mma_tf32(acc[0][j], a0, b);
                mma_tf32(acc[1][j], a1, b);
            }
        }

#pragma unroll
        for (int i = 0; i < 2; i++) {
#pragma unroll
            for (int half = 0; half < 2; half++) {
                int gr = r0 + mw * 32 + i * 16 + half * 8 + (L >> 2);
                if (gr < N_NODES) {
#pragma unroll
                    for (int j = 0; j < 4; j++) {
                        int c = nwg * 32 + j * 8 + (L & 3) * 2;
                        float2 res;
                        res.x = silu_f(acc[i][j][half * 2 + 0] + bs[c]);
                        res.y = silu_f(acc[i][j][half * 2 + 1] + bs[c + 1]);
                        *reinterpret_cast<float2*>(&Y[gr * HID + c]) = res;
                    }
                }
            }
        }
        __syncthreads();
    }
}

// ---------------- mma edge kernel: sorted edges, segmented magg scatter ----------------
#define EDGE_SMEM (52352 * 4)

__global__ void __launch_bounds__(512, 1)
edge_mma(const float* __restrict__ W2, const float* __restrict__ b2,
         const float* __restrict__ Wc1, const float* __restrict__ bc1,
         const float* __restrict__ wc2,
         const float* __restrict__ wr, const float* __restrict__ we) {
    extern __shared__ float sm[];
    float* W2s = sm;
    float* Wc1s = sm + 16896;
    float* tS = sm + 33792;
    float* b2s = sm + 50688;
    float* bc1s = sm + 50816;
    float* wc2s = sm + 50944;
    float* wrs = sm + 51072;
    float* wes = sm + 51200;
    float* diffs = sm + 51328;
    float* cw_part = sm + 51712;
    int* rows_s = (int*)(sm + 52224);

    int tid = threadIdx.x;
    load_w_trans(W2, W2s, tid, 512, 132);
    load_w_trans(Wc1, Wc1s, tid, 512, 132);
    if (tid < 128) {
        b2s[tid] = b2[tid]; bc1s[tid] = bc1[tid]; wc2s[tid] = wc2[tid];
        wrs[tid] = wr[tid]; wes[tid] = we[tid];
    }
    __syncthreads();

    uint32_t tSA = smem_u32(tS);
    uint32_t W2A = smem_u32(W2s), Wc1A = smem_u32(Wc1s);
    int L = tid & 31, w = tid >> 5;
    int mw = w >> 2, nwg = w & 3;
    int aRow = ((L >> 3) & 1) * 8 + (L & 7);
    uint32_t aOff = (uint32_t)(mw * 32 + aRow) * 528 + (uint32_t)(L >> 4) * 16;
    int Ln = L & 15;
    uint32_t bOff[4];
#pragma unroll
    for (int j = 0; j < 4; j++)
        bOff[j] = (uint32_t)((nwg * 4 + j) * 8 + (Ln & 7)) * 528 + (uint32_t)(Ln >> 3) * 16;

    int e_loc = tid >> 2, q = tid & 3;

    for (int tile = blockIdx.x; tile < NT_E; tile += gridDim.x) {
        int e0 = tile * 128;
        // ---- gather (sorted edges) ----
        {
            int e = e0 + e_loc;
            if (e < N_EDGES) {
                int r = d_erow[e], c = d_ecol[e];
                float dx = d_coord[r * 3 + 0] - d_coord[c * 3 + 0];
                float dy = d_coord[r * 3 + 1] - d_coord[c * 3 + 1];
                float dz = d_coord[r * 3 + 2] - d_coord[c * 3 + 2];
                float radial = dx * dx + dy * dy + dz * dz;
                float eav = d_eea[e];
                if (q == 0) {
                    rows_s[e_loc] = r;
                    diffs[e_loc * 3 + 0] = dx; diffs[e_loc * 3 + 1] = dy; diffs[e_loc * 3 + 2] = dz;
                }
#pragma unroll
                for (int jj = 0; jj < 8; jj++) {
                    int ch = q * 32 + jj * 4;
                    float4 av = *reinterpret_cast<const float4*>(&d_A[r * HID + ch]);
                    float4 bv = *reinterpret_cast<const float4*>(&d_B[c * HID + ch]);
                    float4 w1 = *reinterpret_cast<const float4*>(&wrs[ch]);
                    float4 w2v = *reinterpret_cast<const float4*>(&wes[ch]);
                    uint4 t;
                    t.x = to_tf32(silu_f(av.x + bv.x + radial * w1.x + eav * w2v.x));
                    t.y = to_tf32(silu_f(av.y + bv.y + radial * w1.y + eav * w2v.y));
                    t.z = to_tf32(silu_f(av.z + bv.z + radial * w1.z + eav * w2v.z));
                    t.w = to_tf32(silu_f(av.w + bv.w + radial * w1.w + eav * w2v.w));
                    *reinterpret_cast<uint4*>(&tS[e_loc * 132 + ch]) = t;
                }
            } else {
                if (q == 0) {
                    rows_s[e_loc] = -1;
                    diffs[e_loc * 3 + 0] = 0.f; diffs[e_loc * 3 + 1] = 0.f; diffs[e_loc * 3 + 2] = 0.f;
                }
#pragma unroll
                for (int jj = 0; jj < 8; jj++) {
                    int ch = q * 32 + jj * 4;
                    *reinterpret_cast<uint4*>(&tS[e_loc * 132 + ch]) = make_uint4(0, 0, 0, 0);
                }
            }
        }
        __syncthreads();

        // ---- MMA1: D1 = tS @ W2^T ----
        float acc[2][4][4];
#pragma unroll
        for (int i = 0; i < 2; i++)
#pragma unroll
            for (int j = 0; j < 4; j++)
#pragma unroll
                for (int e = 0; e < 4; e++) acc[i][j][e] = 0.0f;
#pragma unroll
        for (int kc = 0; kc < 16; kc++) {
            uint32_t a0[4], a1[4];
            ldsm_x4(a0, tSA + aOff + kc * 32);
            ldsm_x4(a1, tSA + aOff + 16 * 528 + kc * 32);
#pragma unroll
            for (int j = 0; j < 4; j++) {
                uint32_t b[2];
                ldsm_x2(b, W2A + bOff[j] + kc * 32);
                mma_tf32(acc[0][j], a0, b);
                mma_tf32(acc[1][j], a1, b);
            }
        }

        // ---- epilogue1: m = silu(D1 + b2) -> tS (no atomics here) ----
#pragma unroll
        for (int i = 0; i < 2; i++) {
#pragma unroll
            for (int half = 0; half < 2; half++) {
                int rowl = mw * 32 + i * 16 + half * 8 + (L >> 2);
#pragma unroll
                for (int j = 0; j < 4; j++) {
                    int c = nwg * 32 + j * 8 + (L & 3) * 2;
                    float m0 = silu_f(acc[i][j][half * 2 + 0] + b2s[c]);
                    float m1 = silu_f(acc[i][j][half * 2 + 1] + b2s[c + 1]);
                    uint2 t;
                    t.x = to_tf32(m0); t.y = to_tf32(m1);
                    *reinterpret_cast<uint2*>(&tS[rowl * 132 + c]) = t;
                }
            }
        }
        __syncthreads();

        // ---- segmented magg scatter (sorted rows -> few atomics), issued before MMA2 ----
        {
            int ch = tid & 127, chunk = tid >> 7;   // 4 chunks x 32 edges
            int base = chunk * 32;
            float accm = 0.0f;
            int prev = rows_s[base];
#pragma unroll 4
            for (int el = base; el < base + 32; el++) {
                int rn = rows_s[el];
                float mv = tS[el * 132 + ch];
                if (rn != prev) {
                    if (prev >= 0) atomicAdd(&d_magg[prev * HID + ch], accm);
                    accm = 0.0f;
                    prev = rn;
                }
                accm += mv;
            }
            if (prev >= 0) atomicAdd(&d_magg[prev * HID + ch], accm);
        }

        // ---- MMA2: D2 = mS @ Wc1^T ----
#pragma unroll
        for (int i = 0; i < 2; i++)
#pragma unroll
            for (int j = 0; j < 4; j++)
#pragma unroll
                for (int e = 0; e < 4; e++) acc[i][j][e] = 0.0f;
#pragma unroll
        for (int kc = 0; kc < 16; kc++) {
            uint32_t a0[4], a1[4];
            ldsm_x4(a0, tSA + aOff + kc * 32);
            ldsm_x4(a1, tSA + aOff + 16 * 528 + kc * 32);
#pragma unroll
            for (int j = 0; j < 4; j++) {
                uint32_t b[2];
                ldsm_x2(b, Wc1A + bOff[j] + kc * 32);
                mma_tf32(acc[0][j], a0, b);
                mma_tf32(acc[1][j], a1, b);
            }
        }

        // ---- epilogue2: cw = sum_c silu(D2 + bc1)*wc2 ----
#pragma unroll
        for (int i = 0; i < 2; i++) {
#pragma unroll
            for (int half = 0; half < 2; half++) {
                float p = 0.0f;
#pragma unroll
                for (int j = 0; j < 4; j++) {
                    int c = nwg * 32 + j * 8 + (L & 3) * 2;
                    p += silu_f(acc[i][j][half * 2 + 0] + bc1s[c]) * wc2s[c];
                    p += silu_f(acc[i][j][half * 2 + 1] + bc1s[c + 1]) * wc2s[c + 1];
                }
                p += __shfl_xor_sync(0xffffffff, p, 1);
                p += __shfl_xor_sync(0xffffffff, p, 2);
                if ((L & 3) == 0) {
                    int rowl = mw * 32 + i * 16 + half * 8 + (L >> 2);
                    cw_part[nwg * 128 + rowl] = p;
                }
            }
        }
        __syncthreads();
        if (tid < 128) {
            int rn = rows_s[tid];
            if (rn >= 0) {
                float cw = cw_part[tid] + cw_part[128 + tid] + cw_part[256 + tid] + cw_part[384 + tid];
                atomicAdd(&d_cagg[rn * 3 + 0], diffs[tid * 3 + 0] * cw);
                atomicAdd(&d_cagg[rn * 3 + 1], diffs[tid * 3 + 1] * cw);
                atomicAdd(&d_cagg[rn * 3 + 2], diffs[tid * 3 + 2] * cw);
            }
        }
        __syncthreads();
    }
}

// ---------------- coord update (deg from histogram) ----------------
__global__ void coord_kernel() {
    int n = blockIdx.x * blockDim.x + threadIdx.x;
    if (n < N_NODES) {
        float inv = 1.0f / fmaxf((float)d_cnt[n], 1.0f);
#pragma unroll
        for (int dd = 0; dd < 3; dd++) {
            d_coord[n * 3 + dd] += d_cagg[n * 3 + dd] * inv;
            d_cagg[n * 3 + dd] = 0.0f;
        }
    }
}

// ---------------- global mean pool ----------------
__global__ void pool_kernel(const int* __restrict__ batch) {
    int n0 = blockIdx.x * 512;
    int ch = threadIdx.x;
    if (n0 >= N_NODES) return;
    int nend = min(n0 + 512, N_NODES);
    int cur = batch[n0];
    float acc = 0.0f, cnt = 0.0f;
    for (int n = n0; n < nend; n++) {
        int g = batch[n];
        if (g != cur) {
            atomicAdd(&d_gsum[cur * HID + ch], acc);
            if (ch == 0) atomicAdd(&d_gcnt[cur], cnt);
            acc = 0.0f; cnt = 0.0f; cur = g;
        }
        acc += d_A[n * HID + ch];
        cnt += 1.0f;
    }
    atomicAdd(&d_gsum[cur * HID + ch], acc);
    if (ch == 0) atomicAdd(&d_gcnt[cur], cnt);
}

// ---------------- final fc ----------------
__global__ void fc_kernel(const float* __restrict__ fcw, const float* __restrict__ fcb,
                          float* __restrict__ out) {
    int g = blockIdx.x;
    int ch = threadIdx.x;
    float inv = 1.0f / fmaxf(d_gcnt[g], 1.0f);
    float acc = fcb[ch];
    for (int k = 0; k < HID; k++)
        acc += d_gsum[g * HID + k] * inv * fcw[k * OUT_DIM + ch];
    out[g * OUT_DIM + ch] = acc;
}

// ---------------- launch ----------------
#define GRID_G 296
#define GRID_F 148
#define GRID_E 148

extern "C" void kernel_launch(void* const* d_in, const int* in_sizes, int n_in,
                              void* d_out, int out_size) {
    const float* x = (const float*)d_in[0];
    const int* eidx = (const int*)d_in[1];
    const float* coord = (const float*)d_in[2];
    const float* ea = (const float*)d_in[3];
    const int* batch = (const int*)d_in[4];
    const float* emb_in_w = (const float*)d_in[5];
    const float* emb_in_b = (const float*)d_in[6];
    const float* edge_w1 = (const float*)d_in[7];
    const float* edge_b1 = (const float*)d_in[8];
    const float* edge_w2 = (const float*)d_in[9];
    const float* edge_b2 = (const float*)d_in[10];
    const float* node_w1 = (const float*)d_in[11];
    const float* node_b1 = (const float*)d_in[12];
    const float* node_w2 = (const float*)d_in[13];
    const float* node_b2 = (const float*)d_in[14];
    const float* coord_w1 = (const float*)d_in[15];
    const float* coord_b1 = (const float*)d_in[16];
    const float* coord_w2 = (const float*)d_in[17];
    const float* emb_out_w = (const float*)d_in[18];
    const float* emb_out_b = (const float*)d_in[19];
    const float* fc_w = (const float*)d_in[20];
    const float* fc_b = (const float*)d_in[21];
    float* out = (float*)d_out;

    const int* row = eidx;
    const int* col = eidx + N_EDGES;

    float *ph, *pA, *pB, *pT, *pmagg;
    cudaGetSymbolAddress((void**)&ph, d_h);
    cudaGetSymbolAddress((void**)&pA, d_A);
    cudaGetSymbolAddress((void**)&pB, d_B);
    cudaGetSymbolAddress((void**)&pT, d_T);
    cudaGetSymbolAddress((void**)&pmagg, d_magg);

    cudaFuncSetAttribute(edge_mma, cudaFuncAttributeMaxDynamicSharedMemorySize, EDGE_SMEM);
    cudaFuncSetAttribute(gemm_mma, cudaFuncAttributeMaxDynamicSharedMemorySize, GEMM_SMEM);
    cudaFuncSetAttribute(gemm_ab, cudaFuncAttributeMaxDynamicSharedMemorySize, AB_SMEM);
    cudaFuncSetAttribute(gemm_k256, cudaFuncAttributeMaxDynamicSharedMemorySize, K256_SMEM);

    // ---- pre-pass: counting sort of edges by destination row ----
    init_kernel<<<(N_NODES * HID + 255) / 256, 256>>>(coord);
    hist_kernel<<<(N_EDGES + 255) / 256, 256>>>(row);
    scan1_kernel<<<SCAN_B, 512>>>();
    scan2_kernel<<<1, 32>>>();
    scan3_kernel<<<(N_NODES + 255) / 256, 256>>>();
    scatter_kernel<<<(N_EDGES + 255) / 256, 256>>>(row, col, ea);
    emb_in_kernel<<<(N_NODES * HID + 255) / 256, 256>>>(x, emb_in_w, emb_in_b);

    for (int l = 0; l < N_LAYERS; l++) {
        const float* W1 = edge_w1 + l * 258 * HID;
        gemm_ab<<<GRID_F, 256, AB_SMEM>>>(ph, W1, W1 + 128 * HID, edge_b1 + l * HID, pA, pB);
        edge_mma<<<GRID_E, 512, EDGE_SMEM>>>(
            edge_w2 + l * HID * HID, edge_b2 + l * HID,
            coord_w1 + l * HID * HID, coord_b1 + l * HID, coord_w2 + l * HID,
            W1 + 256 * HID, W1 + 257 * HID);
        coord_kernel<<<(N_NODES + 255) / 256, 256>>>();
        gemm_k256<<<GRID_F, 256, K256_SMEM>>>(ph, pmagg, node_w1 + l * 256 * HID,
                                              node_b1 + l * HID, pT);
        gemm_mma<<<GRID_G, 256, GEMM_SMEM>>>(pT, node_w2 + l * HID * HID,
                                             node_b2 + l * HID, ph, GM_BIAS | GM_ACC);
    }

    gemm_mma<<<GRID_G, 256, GEMM_SMEM>>>(ph, emb_out_w, emb_out_b, pA, GM_BIAS);
    pool_kernel<<<(N_NODES + 511) / 512, 128>>>(batch);
    fc_kernel<<<N_GRAPHS, 256>>>(fc_w, fc_b, out);
}

// round 12
// speedup vs baseline: 1.6515x; 1.0115x over previous
#include <cuda_runtime.h>
#include <math.h>
#include <stdint.h>

#define N_NODES 50000
#define N_EDGES 600000
#define N_GRAPHS 64
#define HID 128
#define IN_DIM 16
#define OUT_DIM 256
#define N_LAYERS 3
#define NT_E64 9375          // 600000 / 64 exactly
#define NT_N 782             // ceil(50000/64)
#define SCAN_B 98            // ceil(50000/512)

// ---------------- device scratch ----------------
__device__ float d_h[N_NODES * HID];
__device__ float d_A[N_NODES * HID];
__device__ float d_B[N_NODES * HID];
__device__ float d_T[N_NODES * HID];
__device__ float d_magg[N_NODES * HID];
__device__ float d_cagg[N_NODES * 3];
__device__ float d_coord[N_NODES * 3];
__device__ float d_gsum[N_GRAPHS * HID];
__device__ float d_gcnt[N_GRAPHS];
// edge sort
__device__ int d_cnt[N_NODES];
__device__ int d_cur[N_NODES];
__device__ int d_base[N_NODES];
__device__ int d_bsum[SCAN_B];
__device__ int d_erow[N_EDGES];
__device__ int d_ecol[N_EDGES];
__device__ float d_eea[N_EDGES];

// silu via tanh.approx: 1 MUFU
__device__ __forceinline__ float silu_f(float x) {
    float t;
    asm("tanh.approx.f32 %0, %1;" : "=f"(t) : "f"(x * 0.5f));
    return 0.5f * x * (1.0f + t);
}
__device__ __forceinline__ uint32_t smem_u32(const void* p) {
    uint32_t a;
    asm("{ .reg .u64 t; cvta.to.shared.u64 t, %1; cvt.u32.u64 %0, t; }" : "=r"(a) : "l"(p));
    return a;
}
__device__ __forceinline__ uint32_t to_tf32(float f) {
    uint32_t o;
    asm("cvt.rna.tf32.f32 %0, %1;" : "=r"(o) : "f"(f));
    return o;
}
__device__ __forceinline__ void ldsm_x4(uint32_t a[4], uint32_t addr) {
    asm volatile("ldmatrix.sync.aligned.m8n8.x4.shared.b16 {%0,%1,%2,%3}, [%4];"
        : "=r"(a[0]), "=r"(a[1]), "=r"(a[2]), "=r"(a[3]) : "r"(addr));
}
__device__ __forceinline__ void ldsm_x2(uint32_t b[2], uint32_t addr) {
    asm volatile("ldmatrix.sync.aligned.m8n8.x2.shared.b16 {%0,%1}, [%2];"
        : "=r"(b[0]), "=r"(b[1]) : "r"(addr));
}
__device__ __forceinline__ void mma_tf32(float d[4], const uint32_t a[4], const uint32_t b[2]) {
    asm volatile("mma.sync.aligned.m16n8k8.row.col.f32.tf32.tf32.f32 "
        "{%0,%1,%2,%3}, {%4,%5,%6,%7}, {%8,%9}, {%0,%1,%2,%3};"
        : "+f"(d[0]), "+f"(d[1]), "+f"(d[2]), "+f"(d[3])
        : "r"(a[0]), "r"(a[1]), "r"(a[2]), "r"(a[3]), "r"(b[0]), "r"(b[1]));
}
#define GBAR(id) asm volatile("bar.sync %0, 256;" :: "r"(id) : "memory")

// ---------------- init ----------------
__global__ void init_kernel(const float* __restrict__ coord_in) {
    int idx = blockIdx.x * blockDim.x + threadIdx.x;
    if (idx < N_NODES * HID) d_magg[idx] = 0.0f;
    if (idx < N_NODES * 3) { d_cagg[idx] = 0.0f; d_coord[idx] = coord_in[idx]; }
    if (idx < N_NODES) { d_cnt[idx] = 0; d_cur[idx] = 0; }
    if (idx < N_GRAPHS * HID) d_gsum[idx] = 0.0f;
    if (idx < N_GRAPHS) d_gcnt[idx] = 0.0f;
}

// ---------------- edge sort pre-pass ----------------
__global__ void hist_kernel(const int* __restrict__ row) {
    int e = blockIdx.x * blockDim.x + threadIdx.x;
    if (e < N_EDGES) atomicAdd(&d_cnt[row[e]], 1);
}
__global__ void scan1_kernel() {
    __shared__ int s[512];
    int tid = threadIdx.x;
    int i = blockIdx.x * 512 + tid;
    int v = (i < N_NODES) ? d_cnt[i] : 0;
    s[tid] = v;
    __syncthreads();
    for (int off = 1; off < 512; off <<= 1) {
        int t = (tid >= off) ? s[tid - off] : 0;
        __syncthreads();
        s[tid] += t;
        __syncthreads();
    }
    if (i < N_NODES) d_base[i] = s[tid] - v;
    if (tid == 511) d_bsum[blockIdx.x] = s[511];
}
__global__ void scan2_kernel() {
    if (threadIdx.x == 0) {
        int acc = 0;
        for (int b = 0; b < SCAN_B; b++) { int t = d_bsum[b]; d_bsum[b] = acc; acc += t; }
    }
}
__global__ void scan3_kernel() {
    int i = blockIdx.x * blockDim.x + threadIdx.x;
    if (i < N_NODES) d_base[i] += d_bsum[i >> 9];
}
__global__ void scatter_kernel(const int* __restrict__ row, const int* __restrict__ col,
                               const float* __restrict__ ea) {
    int e = blockIdx.x * blockDim.x + threadIdx.x;
    if (e < N_EDGES) {
        int r = row[e];
        int p = d_base[r] + atomicAdd(&d_cur[r], 1);
        d_erow[p] = r;
        d_ecol[p] = col[e];
        d_eea[p] = ea[e];
    }
}

__global__ void emb_in_kernel(const float* __restrict__ x,
                              const float* __restrict__ w,
                              const float* __restrict__ b) {
    int idx = blockIdx.x * blockDim.x + threadIdx.x;
    if (idx >= N_NODES * HID) return;
    int n = idx >> 7, ch = idx & 127;
    float acc = b[ch];
#pragma unroll
    for (int k = 0; k < IN_DIM; k++) acc += x[n * IN_DIM + k] * w[k * HID + ch];
    d_h[idx] = acc;
}

// store W[k][c] transposed+tf32 into Ws[c][k] (stride floats)
__device__ __forceinline__ void load_w_trans(const float* __restrict__ W, float* __restrict__ Ws,
                                             int tid, int nthreads, int stride) {
    for (int idx = tid; idx < 4096; idx += nthreads) {
        int k = idx >> 5, c0 = (idx & 31) * 4;
        float4 v = reinterpret_cast<const float4*>(W)[idx];
        *(uint32_t*)&Ws[(c0 + 0) * stride + k] = to_tf32(v.x);
        *(uint32_t*)&Ws[(c0 + 1) * stride + k] = to_tf32(v.y);
        *(uint32_t*)&Ws[(c0 + 2) * stride + k] = to_tf32(v.z);
        *(uint32_t*)&Ws[(c0 + 3) * stride + k] = to_tf32(v.w);
    }
}

// ---------------- gemm_mma: Y = op(X@W (+bias) (+Y)) ----------------
#define GEMM_SMEM ((16896 + 8448 + 128) * 4)
#define GM_BIAS 1
#define GM_ACC 2
#define GM_SILU 4

__global__ void __launch_bounds__(256, 2)
gemm_mma(float* __restrict__ X, const float* __restrict__ W,
         const float* __restrict__ bias, float* __restrict__ Y, int mode) {
    extern __shared__ float sm[];
    float* Wts = sm;
    float* Xs = sm + 16896;
    float* bs = sm + 25344;
    int tid = threadIdx.x;

    load_w_trans(W, Wts, tid, 256, 132);
    if (tid < 128) bs[tid] = (mode & GM_BIAS) ? bias[tid] : 0.0f;
    __syncthreads();

    uint32_t XsA = smem_u32(Xs), WtA = smem_u32(Wts);
    int L = tid & 31, w = tid >> 5;
    int mw = w & 1, nwg = w >> 1;
    int aRow = ((L >> 3) & 1) * 8 + (L & 7);
    uint32_t aBase0 = XsA + (uint32_t)(mw * 32 + aRow) * 528 + (uint32_t)(L >> 4) * 16;
    uint32_t aBase1 = aBase0 + 16 * 528;
    int Ln = L & 15;
    uint32_t bBase[4];
#pragma unroll
    for (int j = 0; j < 4; j++)
        bBase[j] = WtA + (uint32_t)((nwg * 4 + j) * 8 + (Ln & 7)) * 528 + (uint32_t)(Ln >> 3) * 16;

    for (int tile = blockIdx.x; tile < NT_N; tile += gridDim.x) {
        int r0 = tile * 64;
        for (int idx = tid; idx < 2048; idx += 256) {
            int r = idx >> 5, k4 = (idx & 31) * 4;
            int gr = r0 + r;
            float4 v = make_float4(0.f, 0.f, 0.f, 0.f);
            if (gr < N_NODES) v = *reinterpret_cast<const float4*>(&X[gr * HID + k4]);
            uint4 t;
            t.x = to_tf32(v.x); t.y = to_tf32(v.y); t.z = to_tf32(v.z); t.w = to_tf32(v.w);
            *reinterpret_cast<uint4*>(&Xs[r * 132 + k4]) = t;
        }
        __syncthreads();

        float acc[2][4][4];
#pragma unroll
        for (int i = 0; i < 2; i++)
#pragma unroll
            for (int j = 0; j < 4; j++)
#pragma unroll
                for (int e = 0; e < 4; e++) acc[i][j][e] = 0.0f;

#pragma unroll
        for (int kc = 0; kc < 16; kc++) {
            uint32_t a0[4], a1[4];
            ldsm_x4(a0, aBase0 + kc * 32);
            ldsm_x4(a1, aBase1 + kc * 32);
#pragma unroll
            for (int j = 0; j < 4; j++) {
                uint32_t b[2];
                ldsm_x2(b, bBase[j] + kc * 32);
                mma_tf32(acc[0][j], a0, b);
                mma_tf32(acc[1][j], a1, b);
            }
        }

#pragma unroll
        for (int i = 0; i < 2; i++) {
#pragma unroll
            for (int half = 0; half < 2; half++) {
                int gr = r0 + mw * 32 + i * 16 + half * 8 + (L >> 2);
                if (gr < N_NODES) {
#pragma unroll
                    for (int j = 0; j < 4; j++) {
                        int c = nwg * 32 + j * 8 + (L & 3) * 2;
                        float2 res;
                        res.x = acc[i][j][half * 2 + 0] + bs[c];
                        res.y = acc[i][j][half * 2 + 1] + bs[c + 1];
                        float* yp = &Y[gr * HID + c];
                        if (mode & GM_ACC) {
                            float2 o = *reinterpret_cast<float2*>(yp);
                            res.x += o.x; res.y += o.y;
                        }
                        if (mode & GM_SILU) { res.x = silu_f(res.x); res.y = silu_f(res.y); }
                        *reinterpret_cast<float2*>(yp) = res;
                    }
                }
            }
        }
        __syncthreads();
    }
}

// ---------------- gemm_ab: Y1 = X@Wa + b, Y2 = X@Wb ----------------
#define AB_SMEM ((33792 + 8448 + 128) * 4)

__global__ void __launch_bounds__(256, 1)
gemm_ab(const float* __restrict__ X, const float* __restrict__ Wa, const float* __restrict__ Wb,
        const float* __restrict__ bias, float* __restrict__ Y1, float* __restrict__ Y2) {
    extern __shared__ float sm[];
    float* Wts = sm;
    float* Xs = sm + 33792;
    float* bs = sm + 42240;
    int tid = threadIdx.x;

    load_w_trans(Wa, Wts, tid, 256, 132);
    load_w_trans(Wb, Wts + 128 * 132, tid, 256, 132);
    if (tid < 128) bs[tid] = bias[tid];
    __syncthreads();

    uint32_t XsA = smem_u32(Xs), WtA = smem_u32(Wts);
    int L = tid & 31, w = tid >> 5;
    int mw = w & 1, nwg = w >> 1;
    int aRow = ((L >> 3) & 1) * 8 + (L & 7);
    uint32_t aBase0 = XsA + (uint32_t)(mw * 32 + aRow) * 528 + (uint32_t)(L >> 4) * 16;
    uint32_t aBase1 = aBase0 + 16 * 528;
    int Ln = L & 15;
    uint32_t bBase[8];
#pragma unroll
    for (int j = 0; j < 8; j++) {
        int blk = (j < 4) ? (nwg * 4 + j) : (16 + nwg * 4 + (j - 4));
        bBase[j] = WtA + (uint32_t)(blk * 8 + (Ln & 7)) * 528 + (uint32_t)(Ln >> 3) * 16;
    }

    for (int tile = blockIdx.x; tile < NT_N; tile += gridDim.x) {
        int r0 = tile * 64;
        for (int idx = tid; idx < 2048; idx += 256) {
            int r = idx >> 5, k4 = (idx & 31) * 4;
            int gr = r0 + r;
            float4 v = make_float4(0.f, 0.f, 0.f, 0.f);
            if (gr < N_NODES) v = *reinterpret_cast<const float4*>(&X[gr * HID + k4]);
            uint4 t;
            t.x = to_tf32(v.x); t.y = to_tf32(v.y); t.z = to_tf32(v.z); t.w = to_tf32(v.w);
            *reinterpret_cast<uint4*>(&Xs[r * 132 + k4]) = t;
        }
        __syncthreads();

        float acc[2][8][4];
#pragma unroll
        for (int i = 0; i < 2; i++)
#pragma unroll
            for (int j = 0; j < 8; j++)
#pragma unroll
                for (int e = 0; e < 4; e++) acc[i][j][e] = 0.0f;

#pragma unroll
        for (int kc = 0; kc < 16; kc++) {
            uint32_t a0[4], a1[4];
            ldsm_x4(a0, aBase0 + kc * 32);
            ldsm_x4(a1, aBase1 + kc * 32);
#pragma unroll
            for (int j = 0; j < 8; j++) {
                uint32_t b[2];
                ldsm_x2(b, bBase[j] + kc * 32);
                mma_tf32(acc[0][j], a0, b);
                mma_tf32(acc[1][j], a1, b);
            }
        }

#pragma unroll
        for (int i = 0; i < 2; i++) {
#pragma unroll
            for (int half = 0; half < 2; half++) {
                int gr = r0 + mw * 32 + i * 16 + half * 8 + (L >> 2);
                if (gr < N_NODES) {
#pragma unroll
                    for (int j = 0; j < 8; j++) {
                        int c = nwg * 32 + (j & 3) * 8 + (L & 3) * 2;
                        float2 res;
                        res.x = acc[i][j][half * 2 + 0];
                        res.y = acc[i][j][half * 2 + 1];
                        if (j < 4) {
                            res.x += bs[c]; res.y += bs[c + 1];
                            *reinterpret_cast<float2*>(&Y1[gr * HID + c]) = res;
                        } else {
                            *reinterpret_cast<float2*>(&Y2[gr * HID + c]) = res;
                        }
                    }
                }
            }
        }
        __syncthreads();
    }
}

// ---------------- gemm_k256: Y = silu([X1, X2]@W + b), clears X2 ----------------
#define K256_SMEM ((34304 + 17152 + 128) * 4)

__global__ void __launch_bounds__(256, 1)
gemm_k256(const float* __restrict__ X1, float* __restrict__ X2,
          const float* __restrict__ W, const float* __restrict__ bias, float* __restrict__ Y) {
    extern __shared__ float sm[];
    float* Wts = sm;
    float* Xs = sm + 34304;
    float* bs = sm + 51456;
    int tid = threadIdx.x;

    for (int idx = tid; idx < 8192; idx += 256) {
        int k = idx >> 5, c0 = (idx & 31) * 4;
        float4 v = reinterpret_cast<const float4*>(W)[idx];
        *(uint32_t*)&Wts[(c0 + 0) * 268 + k] = to_tf32(v.x);
        *(uint32_t*)&Wts[(c0 + 1) * 268 + k] = to_tf32(v.y);
        *(uint32_t*)&Wts[(c0 + 2) * 268 + k] = to_tf32(v.z);
        *(uint32_t*)&Wts[(c0 + 3) * 268 + k] = to_tf32(v.w);
    }
    if (tid < 128) bs[tid] = bias[tid];
    __syncthreads();

    uint32_t XsA = smem_u32(Xs), WtA = smem_u32(Wts);
    int L = tid & 31, w = tid >> 5;
    int mw = w & 1, nwg = w >> 1;
    int aRow = ((L >> 3) & 1) * 8 + (L & 7);
    uint32_t aBase0 = XsA + (uint32_t)(mw * 32 + aRow) * 1072 + (uint32_t)(L >> 4) * 16;
    uint32_t aBase1 = aBase0 + 16 * 1072;
    int Ln = L & 15;
    uint32_t bBase[4];
#pragma unroll
    for (int j = 0; j < 4; j++)
        bBase[j] = WtA + (uint32_t)((nwg * 4 + j) * 8 + (Ln & 7)) * 1072 + (uint32_t)(Ln >> 3) * 16;

    for (int tile = blockIdx.x; tile < NT_N; tile += gridDim.x) {
        int r0 = tile * 64;
        for (int idx = tid; idx < 2048; idx += 256) {
            int r = idx >> 5, k4 = (idx & 31) * 4;
            int gr = r0 + r;
            float4 v1 = make_float4(0.f, 0.f, 0.f, 0.f);
            float4 v2 = make_float4(0.f, 0.f, 0.f, 0.f);
            if (gr < N_NODES) {
                v1 = *reinterpret_cast<const float4*>(&X1[gr * HID + k4]);
                v2 = *reinterpret_cast<float4*>(&X2[gr * HID + k4]);
                *reinterpret_cast<float4*>(&X2[gr * HID + k4]) = make_float4(0.f, 0.f, 0.f, 0.f);
            }
            uint4 t;
            t.x = to_tf32(v1.x); t.y = to_tf32(v1.y); t.z = to_tf32(v1.z); t.w = to_tf32(v1.w);
            *reinterpret_cast<uint4*>(&Xs[r * 268 + k4]) = t;
            t.x = to_tf32(v2.x); t.y = to_tf32(v2.y); t.z = to_tf32(v2.z); t.w = to_tf32(v2.w);
            *reinterpret_cast<uint4*>(&Xs[r * 268 + 128 + k4]) = t;
        }
        __syncthreads();

        float acc[2][4][4];
#pragma unroll
        for (int i = 0; i < 2; i++)
#pragma unroll
            for (int j = 0; j < 4; j++)
#pragma unroll
                for (int e = 0; e < 4; e++) acc[i][j][e] = 0.0f;

#pragma unroll
        for (int kc = 0; kc < 32; kc++) {
            uint32_t a0[4], a1[4];
            ldsm_x4(a0, aBase0 + kc * 32);
            ldsm_x4(a1, aBase1 + kc * 32);
#pragma unroll
            for (int j = 0; j < 4; j++) {
                uint32_t b[2];
                ldsm_x2(b, bBase[j] + kc * 32);
                mma_tf32(acc[0][j], a0, b);
                mma_tf32(acc[1][j], a1, b);
            }
        }

#pragma unroll
        for (int i = 0; i < 2; i++) {
#pragma unroll
            for (int half = 0; half < 2; half++) {
                int gr = r0 + mw * 32 + i * 16 + half * 8 + (L >> 2);
                if (gr < N_NODES) {
#pragma unroll
                    for (int j = 0; j < 4; j++) {
                        int c = nwg * 32 + j * 8 + (L & 3) * 2;
                        float2 res;
                        res.x = silu_f(acc[i][j][half * 2 + 0] + bs[c]);
                        res.y = silu_f(acc[i][j][half * 2 + 1] + bs[c + 1]);
                        *reinterpret_cast<float2*>(&Y[gr * HID + c]) = res;
                    }
                }
            }
        }
        __syncthreads();
    }
}

// ---------------- edge kernel: two independent 256-thread groups per CTA ----------------
// smem floats: W2s@0, Wc1s@16896, tS@33792 (2 x 64 x 132), b2s@50688, bc1s@50816,
// wc2s@50944, wrs@51072, wes@51200, diffs@51328 (2x192), cw_part@51712 (2x256),
// rows_s@52224 (2x64 int) -> 52352 floats = 209 KB
#define EDGE_SMEM (52352 * 4)

__global__ void __launch_bounds__(512, 1)
edge_mma(const float* __restrict__ W2, const float* __restrict__ b2,
         const float* __restrict__ Wc1, const float* __restrict__ bc1,
         const float* __restrict__ wc2,
         const float* __restrict__ wr, const float* __restrict__ we) {
    extern __shared__ float sm[];
    float* W2s = sm;
    float* Wc1s = sm + 16896;
    float* b2s = sm + 50688;
    float* bc1s = sm + 50816;
    float* wc2s = sm + 50944;
    float* wrs = sm + 51072;
    float* wes = sm + 51200;

    int tid = threadIdx.x;
    load_w_trans(W2, W2s, tid, 512, 132);
    load_w_trans(Wc1, Wc1s, tid, 512, 132);
    if (tid < 128) {
        b2s[tid] = b2[tid]; bc1s[tid] = bc1[tid]; wc2s[tid] = wc2[tid];
        wrs[tid] = wr[tid]; wes[tid] = we[tid];
    }
    __syncthreads();

    int g = tid >> 8;           // group 0 / 1
    int gtid = tid & 255;
    int barid = 1 + g;

    float* tS = sm + 33792 + g * 8448;       // [64][132]
    float* diffs = sm + 51328 + g * 192;
    float* cw_part = sm + 51712 + g * 256;
    int* rows_s = (int*)(sm + 52224) + g * 64;

    uint32_t tSA = smem_u32(tS);
    uint32_t W2A = smem_u32(W2s), Wc1A = smem_u32(Wc1s);
    int L = gtid & 31, w = gtid >> 5;        // 8 warps per group
    int mw = w & 1, nwg = w >> 1;
    int aRow = ((L >> 3) & 1) * 8 + (L & 7);
    uint32_t aOff = (uint32_t)(mw * 32 + aRow) * 528 + (uint32_t)(L >> 4) * 16;
    int Ln = L & 15;
    uint32_t bOff[4];
#pragma unroll
    for (int j = 0; j < 4; j++)
        bOff[j] = (uint32_t)((nwg * 4 + j) * 8 + (Ln & 7)) * 528 + (uint32_t)(Ln >> 3) * 16;

    int e_loc = gtid >> 2, q = gtid & 3;     // 64 edges, 4 channel quarters

    for (int tile = blockIdx.x * 2 + g; tile < NT_E64; tile += gridDim.x * 2) {
        int e0 = tile * 64;
        // ---- gather (sorted edges; 600000 = 9375*64, no bounds needed) ----
        {
            int e = e0 + e_loc;
            int r = d_erow[e], c = d_ecol[e];
            float dx = d_coord[r * 3 + 0] - d_coord[c * 3 + 0];
            float dy = d_coord[r * 3 + 1] - d_coord[c * 3 + 1];
            float dz = d_coord[r * 3 + 2] - d_coord[c * 3 + 2];
            float radial = dx * dx + dy * dy + dz * dz;
            float eav = d_eea[e];
            if (q == 0) {
                rows_s[e_loc] = r;
                diffs[e_loc * 3 + 0] = dx; diffs[e_loc * 3 + 1] = dy; diffs[e_loc * 3 + 2] = dz;
            }
#pragma unroll
            for (int jj = 0; jj < 8; jj++) {
                int ch = q * 32 + jj * 4;
                float4 av = *reinterpret_cast<const float4*>(&d_A[r * HID + ch]);
                float4 bv = *reinterpret_cast<const float4*>(&d_B[c * HID + ch]);
                float4 w1 = *reinterpret_cast<const float4*>(&wrs[ch]);
                float4 w2v = *reinterpret_cast<const float4*>(&wes[ch]);
                uint4 t;
                t.x = to_tf32(silu_f(av.x + bv.x + radial * w1.x + eav * w2v.x));
                t.y = to_tf32(silu_f(av.y + bv.y + radial * w1.y + eav * w2v.y));
                t.z = to_tf32(silu_f(av.z + bv.z + radial * w1.z + eav * w2v.z));
                t.w = to_tf32(silu_f(av.w + bv.w + radial * w1.w + eav * w2v.w));
                *reinterpret_cast<uint4*>(&tS[e_loc * 132 + ch]) = t;
            }
        }
        GBAR(barid);

        // ---- MMA1: D1 = tS @ W2^T ----
        float acc[2][4][4];
#pragma unroll
        for (int i = 0; i < 2; i++)
#pragma unroll
            for (int j = 0; j < 4; j++)
#pragma unroll
                for (int e = 0; e < 4; e++) acc[i][j][e] = 0.0f;
#pragma unroll
        for (int kc = 0; kc < 16; kc++) {
            uint32_t a0[4], a1[4];
            ldsm_x4(a0, tSA + aOff + kc * 32);
            ldsm_x4(a1, tSA + aOff + 16 * 528 + kc * 32);
#pragma unroll
            for (int j = 0; j < 4; j++) {
                uint32_t b[2];
                ldsm_x2(b, W2A + bOff[j] + kc * 32);
                mma_tf32(acc[0][j], a0, b);
                mma_tf32(acc[1][j], a1, b);
            }
        }

        // ---- epilogue1: m = silu(D1 + b2) -> tS (own band) ----
#pragma unroll
        for (int i = 0; i < 2; i++) {
#pragma unroll
            for (int half = 0; half < 2; half++) {
                int rowl = mw * 32 + i * 16 + half * 8 + (L >> 2);
#pragma unroll
                for (int j = 0; j < 4; j++) {
                    int c = nwg * 32 + j * 8 + (L & 3) * 2;
                    float m0 = silu_f(acc[i][j][half * 2 + 0] + b2s[c]);
                    float m1 = silu_f(acc[i][j][half * 2 + 1] + b2s[c + 1]);
                    uint2 t;
                    t.x = to_tf32(m0); t.y = to_tf32(m1);
                    *reinterpret_cast<uint2*>(&tS[rowl * 132 + c]) = t;
                }
            }
        }
        GBAR(barid);

        // ---- segmented magg scatter (sorted rows), drains under MMA2 ----
        {
            int ch = gtid & 127, chunk = gtid >> 7;   // 2 chunks x 32 edges
            int base = chunk * 32;
            float accm = 0.0f;
            int prev = rows_s[base];
#pragma unroll 4
            for (int el = base; el < base + 32; el++) {
                int rn = rows_s[el];
                float mv = tS[el * 132 + ch];
                if (rn != prev) {
                    atomicAdd(&d_magg[prev * HID + ch], accm);
                    accm = 0.0f;
                    prev = rn;
                }
                accm += mv;
            }
            atomicAdd(&d_magg[prev * HID + ch], accm);
        }

        // ---- MMA2: D2 = mS @ Wc1^T ----
#pragma unroll
        for (int i = 0; i < 2; i++)
#pragma unroll
            for (int j = 0; j < 4; j++)
#pragma unroll
                for (int e = 0; e < 4; e++) acc[i][j][e] = 0.0f;
#pragma unroll
        for (int kc = 0; kc < 16; kc++) {
            uint32_t a0[4], a1[4];
            ldsm_x4(a0, tSA + aOff + kc * 32);
            ldsm_x4(a1, tSA + aOff + 16 * 528 + kc * 32);
#pragma unroll
            for (int j = 0; j < 4; j++) {
                uint32_t b[2];
                ldsm_x2(b, Wc1A + bOff[j] + kc * 32);
                mma_tf32(acc[0][j], a0, b);
                mma_tf32(acc[1][j], a1, b);
            }
        }

        // ---- epilogue2: cw = sum_c silu(D2 + bc1)*wc2 ----
#pragma unroll
        for (int i = 0; i < 2; i++) {
#pragma unroll
            for (int half = 0; half < 2; half++) {
                float p = 0.0f;
#pragma unroll
                for (int j = 0; j < 4; j++) {
                    int c = nwg * 32 + j * 8 + (L & 3) * 2;
                    p += silu_f(acc[i][j][half * 2 + 0] + bc1s[c]) * wc2s[c];
                    p += silu_f(acc[i][j][half * 2 + 1] + bc1s[c + 1]) * wc2s[c + 1];
                }
                p += __shfl_xor_sync(0xffffffff, p, 1);
                p += __shfl_xor_sync(0xffffffff, p, 2);
                if ((L & 3) == 0) {
                    int rowl = mw * 32 + i * 16 + half * 8 + (L >> 2);
                    cw_part[nwg * 64 + rowl] = p;
                }
            }
        }
        GBAR(barid);
        if (gtid < 64) {
            int rn = rows_s[gtid];
            float cw = cw_part[gtid] + cw_part[64 + gtid] + cw_part[128 + gtid] + cw_part[192 + gtid];
            atomicAdd(&d_cagg[rn * 3 + 0], diffs[gtid * 3 + 0] * cw);
            atomicAdd(&d_cagg[rn * 3 + 1], diffs[gtid * 3 + 1] * cw);
            atomicAdd(&d_cagg[rn * 3 + 2], diffs[gtid * 3 + 2] * cw);
        }
        GBAR(barid);
    }
}

// ---------------- coord update (deg from histogram) ----------------
__global__ void coord_kernel() {
    int n = blockIdx.x * blockDim.x + threadIdx.x;
    if (n < N_NODES) {
        float inv = 1.0f / fmaxf((float)d_cnt[n], 1.0f);
#pragma unroll
        for (int dd = 0; dd < 3; dd++) {
            d_coord[n * 3 + dd] += d_cagg[n * 3 + dd] * inv;
            d_cagg[n * 3 + dd] = 0.0f;
        }
    }
}

// ---------------- global mean pool ----------------
__global__ void pool_kernel(const int* __restrict__ batch) {
    int n0 = blockIdx.x * 512;
    int ch = threadIdx.x;
    if (n0 >= N_NODES) return;
    int nend = min(n0 + 512, N_NODES);
    int cur = batch[n0];
    float acc = 0.0f, cnt = 0.0f;
    for (int n = n0; n < nend; n++) {
        int g = batch[n];
        if (g != cur) {
            atomicAdd(&d_gsum[cur * HID + ch], acc);
            if (ch == 0) atomicAdd(&d_gcnt[cur], cnt);
            acc = 0.0f; cnt = 0.0f; cur = g;
        }
        acc += d_A[n * HID + ch];
        cnt += 1.0f;
    }
    atomicAdd(&d_gsum[cur * HID + ch], acc);
    if (ch == 0) atomicAdd(&d_gcnt[cur], cnt);
}

// ---------------- final fc ----------------
__global__ void fc_kernel(const float* __restrict__ fcw, const float* __restrict__ fcb,
                          float* __restrict__ out) {
    int g = blockIdx.x;
    int ch = threadIdx.x;
    float inv = 1.0f / fmaxf(d_gcnt[g], 1.0f);
    float acc = fcb[ch];
    for (int k = 0; k < HID; k++)
        acc += d_gsum[g * HID + k] * inv * fcw[k * OUT_DIM + ch];
    out[g * OUT_DIM + ch] = acc;
}

// ---------------- launch ----------------
#define GRID_G 296
#define GRID_F 148
#define GRID_E 148

extern "C" void kernel_launch(void* const* d_in, const int* in_sizes, int n_in,
                              void* d_out, int out_size) {
    const float* x = (const float*)d_in[0];
    const int* eidx = (const int*)d_in[1];
    const float* coord = (const float*)d_in[2];
    const float* ea = (const float*)d_in[3];
    const int* batch = (const int*)d_in[4];
    const float* emb_in_w = (const float*)d_in[5];
    const float* emb_in_b = (const float*)d_in[6];
    const float* edge_w1 = (const float*)d_in[7];
    const float* edge_b1 = (const float*)d_in[8];
    const float* edge_w2 = (const float*)d_in[9];
    const float* edge_b2 = (const float*)d_in[10];
    const float* node_w1 = (const float*)d_in[11];
    const float* node_b1 = (const float*)d_in[12];
    const float* node_w2 = (const float*)d_in[13];
    const float* node_b2 = (const float*)d_in[14];
    const float* coord_w1 = (const float*)d_in[15];
    const float* coord_b1 = (const float*)d_in[16];
    const float* coord_w2 = (const float*)d_in[17];
    const float* emb_out_w = (const float*)d_in[18];
    const float* emb_out_b = (const float*)d_in[19];
    const float* fc_w = (const float*)d_in[20];
    const float* fc_b = (const float*)d_in[21];
    float* out = (float*)d_out;

    const int* row = eidx;
    const int* col = eidx + N_EDGES;

    float *ph, *pA, *pB, *pT, *pmagg;
    cudaGetSymbolAddress((void**)&ph, d_h);
    cudaGetSymbolAddress((void**)&pA, d_A);
    cudaGetSymbolAddress((void**)&pB, d_B);
    cudaGetSymbolAddress((void**)&pT, d_T);
    cudaGetSymbolAddress((void**)&pmagg, d_magg);

    cudaFuncSetAttribute(edge_mma, cudaFuncAttributeMaxDynamicSharedMemorySize, EDGE_SMEM);
    cudaFuncSetAttribute(gemm_mma, cudaFuncAttributeMaxDynamicSharedMemorySize, GEMM_SMEM);
    cudaFuncSetAttribute(gemm_ab, cudaFuncAttributeMaxDynamicSharedMemorySize, AB_SMEM);
    cudaFuncSetAttribute(gemm_k256, cudaFuncAttributeMaxDynamicSharedMemorySize, K256_SMEM);

    // ---- pre-pass: counting sort of edges by destination row ----
    init_kernel<<<(N_NODES * HID + 255) / 256, 256>>>(coord);
    hist_kernel<<<(N_EDGES + 255) / 256, 256>>>(row);
    scan1_kernel<<<SCAN_B, 512>>>();
    scan2_kernel<<<1, 32>>>();
    scan3_kernel<<<(N_NODES + 255) / 256, 256>>>();
    scatter_kernel<<<(N_EDGES + 255) / 256, 256>>>(row, col, ea);
    emb_in_kernel<<<(N_NODES * HID + 255) / 256, 256>>>(x, emb_in_w, emb_in_b);

    for (int l = 0; l < N_LAYERS; l++) {
        const float* W1 = edge_w1 + l * 258 * HID;
        gemm_ab<<<GRID_F, 256, AB_SMEM>>>(ph, W1, W1 + 128 * HID, edge_b1 + l * HID, pA, pB);
        edge_mma<<<GRID_E, 512, EDGE_SMEM>>>(
            edge_w2 + l * HID * HID, edge_b2 + l * HID,
            coord_w1 + l * HID * HID, coord_b1 + l * HID, coord_w2 + l * HID,
            W1 + 256 * HID, W1 + 257 * HID);
        coord_kernel<<<(N_NODES + 255) / 256, 256>>>();
        gemm_k256<<<GRID_F, 256, K256_SMEM>>>(ph, pmagg, node_w1 + l * 256 * HID,
                                              node_b1 + l * HID, pT);
        gemm_mma<<<GRID_G, 256, GEMM_SMEM>>>(pT, node_w2 + l * HID * HID,
                                             node_b2 + l * HID, ph, GM_BIAS | GM_ACC);
    }

    gemm_mma<<<GRID_G, 256, GEMM_SMEM>>>(ph, emb_out_w, emb_out_b, pA, GM_BIAS);
    pool_kernel<<<(N_NODES + 511) / 512, 128>>>(batch);
    fc_kernel<<<N_GRAPHS, 256>>>(fc_w, fc_b, out);
}

// round 13
// speedup vs baseline: 2.0756x; 1.2567x over previous
#include <cuda_runtime.h>
#include <math.h>
#include <stdint.h>

#define N_NODES 50000
#define N_EDGES 600000
#define N_GRAPHS 64
#define HID 128
#define IN_DIM 16
#define OUT_DIM 256
#define N_LAYERS 3
#define NT_E64 9375          // 600000 / 64 exactly
#define NT_N 782             // ceil(50000/64)
#define SCAN_B 98            // ceil(50000/512)

// ---------------- device scratch ----------------
__device__ float d_h[N_NODES * HID];
__device__ float d_A[N_NODES * HID];
__device__ float d_B[N_NODES * HID];
__device__ float d_T[N_NODES * HID];
__device__ float d_magg[N_NODES * HID];
__device__ float d_cagg[N_NODES * 3];
__device__ float d_coord[N_NODES * 3];
__device__ float d_gsum[N_GRAPHS * HID];
__device__ float d_gcnt[N_GRAPHS];
// edge sort
__device__ int d_cnt[N_NODES];
__device__ int d_cur[N_NODES];
__device__ int d_base[N_NODES];
__device__ int d_bsum[SCAN_B];
__device__ int d_erow[N_EDGES];
__device__ int d_ecol[N_EDGES];
__device__ float d_eea[N_EDGES];

// silu via tanh.approx: 1 MUFU
__device__ __forceinline__ float silu_f(float x) {
    float t;
    asm("tanh.approx.f32 %0, %1;" : "=f"(t) : "f"(x * 0.5f));
    return 0.5f * x * (1.0f + t);
}
__device__ __forceinline__ uint32_t smem_u32(const void* p) {
    uint32_t a;
    asm("{ .reg .u64 t; cvta.to.shared.u64 t, %1; cvt.u32.u64 %0, t; }" : "=r"(a) : "l"(p));
    return a;
}
__device__ __forceinline__ uint32_t to_tf32(float f) {
    uint32_t o;
    asm("cvt.rna.tf32.f32 %0, %1;" : "=r"(o) : "f"(f));
    return o;
}
__device__ __forceinline__ void ldsm_x4(uint32_t a[4], uint32_t addr) {
    asm volatile("ldmatrix.sync.aligned.m8n8.x4.shared.b16 {%0,%1,%2,%3}, [%4];"
        : "=r"(a[0]), "=r"(a[1]), "=r"(a[2]), "=r"(a[3]) : "r"(addr));
}
__device__ __forceinline__ void ldsm_x2(uint32_t b[2], uint32_t addr) {
    asm volatile("ldmatrix.sync.aligned.m8n8.x2.shared.b16 {%0,%1}, [%2];"
        : "=r"(b[0]), "=r"(b[1]) : "r"(addr));
}
__device__ __forceinline__ void mma_tf32(float d[4], const uint32_t a[4], const uint32_t b[2]) {
    asm volatile("mma.sync.aligned.m16n8k8.row.col.f32.tf32.tf32.f32 "
        "{%0,%1,%2,%3}, {%4,%5,%6,%7}, {%8,%9}, {%0,%1,%2,%3};"
        : "+f"(d[0]), "+f"(d[1]), "+f"(d[2]), "+f"(d[3])
        : "r"(a[0]), "r"(a[1]), "r"(a[2]), "r"(a[3]), "r"(b[0]), "r"(b[1]));
}
#define GBAR(id) asm volatile("bar.sync %0, 256;" :: "r"(id) : "memory")

// ---------------- init ----------------
__global__ void init_kernel(const float* __restrict__ coord_in) {
    int idx = blockIdx.x * blockDim.x + threadIdx.x;
    if (idx < N_NODES * HID) d_magg[idx] = 0.0f;
    if (idx < N_NODES * 3) { d_cagg[idx] = 0.0f; d_coord[idx] = coord_in[idx]; }
    if (idx < N_NODES) { d_cnt[idx] = 0; d_cur[idx] = 0; }
    if (idx < N_GRAPHS * HID) d_gsum[idx] = 0.0f;
    if (idx < N_GRAPHS) d_gcnt[idx] = 0.0f;
}

// ---------------- edge sort pre-pass ----------------
__global__ void hist_kernel(const int* __restrict__ row) {
    int e = blockIdx.x * blockDim.x + threadIdx.x;
    if (e < N_EDGES) atomicAdd(&d_cnt[row[e]], 1);
}
__global__ void scan1_kernel() {
    __shared__ int s[512];
    int tid = threadIdx.x;
    int i = blockIdx.x * 512 + tid;
    int v = (i < N_NODES) ? d_cnt[i] : 0;
    s[tid] = v;
    __syncthreads();
    for (int off = 1; off < 512; off <<= 1) {
        int t = (tid >= off) ? s[tid - off] : 0;
        __syncthreads();
        s[tid] += t;
        __syncthreads();
    }
    if (i < N_NODES) d_base[i] = s[tid] - v;
    if (tid == 511) d_bsum[blockIdx.x] = s[511];
}
__global__ void scan2_kernel() {
    if (threadIdx.x == 0) {
        int acc = 0;
        for (int b = 0; b < SCAN_B; b++) { int t = d_bsum[b]; d_bsum[b] = acc; acc += t; }
    }
}
__global__ void scan3_kernel() {
    int i = blockIdx.x * blockDim.x + threadIdx.x;
    if (i < N_NODES) d_base[i] += d_bsum[i >> 9];
}
__global__ void scatter_kernel(const int* __restrict__ row, const int* __restrict__ col,
                               const float* __restrict__ ea) {
    int e = blockIdx.x * blockDim.x + threadIdx.x;
    if (e < N_EDGES) {
        int r = row[e];
        int p = d_base[r] + atomicAdd(&d_cur[r], 1);
        d_erow[p] = r;
        d_ecol[p] = col[e];
        d_eea[p] = ea[e];
    }
}

__global__ void emb_in_kernel(const float* __restrict__ x,
                              const float* __restrict__ w,
                              const float* __restrict__ b) {
    int idx = blockIdx.x * blockDim.x + threadIdx.x;
    if (idx >= N_NODES * HID) return;
    int n = idx >> 7, ch = idx & 127;
    float acc = b[ch];
#pragma unroll
    for (int k = 0; k < IN_DIM; k++) acc += x[n * IN_DIM + k] * w[k * HID + ch];
    d_h[idx] = acc;
}

// store W[k][c] transposed+tf32 into Ws[c][k] (stride floats)
__device__ __forceinline__ void load_w_trans(const float* __restrict__ W, float* __restrict__ Ws,
                                             int tid, int nthreads, int stride) {
    for (int idx = tid; idx < 4096; idx += nthreads) {
        int k = idx >> 5, c0 = (idx & 31) * 4;
        float4 v = reinterpret_cast<const float4*>(W)[idx];
        *(uint32_t*)&Ws[(c0 + 0) * stride + k] = to_tf32(v.x);
        *(uint32_t*)&Ws[(c0 + 1) * stride + k] = to_tf32(v.y);
        *(uint32_t*)&Ws[(c0 + 2) * stride + k] = to_tf32(v.z);
        *(uint32_t*)&Ws[(c0 + 3) * stride + k] = to_tf32(v.w);
    }
}

// ---------------- gemm_mma: Y = op(X@W (+bias) (+Y)) ----------------
#define GEMM_SMEM ((16896 + 8448 + 128) * 4)
#define GM_BIAS 1
#define GM_ACC 2
#define GM_SILU 4

__global__ void __launch_bounds__(256, 2)
gemm_mma(float* __restrict__ X, const float* __restrict__ W,
         const float* __restrict__ bias, float* __restrict__ Y, int mode) {
    extern __shared__ float sm[];
    float* Wts = sm;
    float* Xs = sm + 16896;
    float* bs = sm + 25344;
    int tid = threadIdx.x;

    load_w_trans(W, Wts, tid, 256, 132);
    if (tid < 128) bs[tid] = (mode & GM_BIAS) ? bias[tid] : 0.0f;
    __syncthreads();

    uint32_t XsA = smem_u32(Xs), WtA = smem_u32(Wts);
    int L = tid & 31, w = tid >> 5;
    int mw = w & 1, nwg = w >> 1;
    int aRow = ((L >> 3) & 1) * 8 + (L & 7);
    uint32_t aBase0 = XsA + (uint32_t)(mw * 32 + aRow) * 528 + (uint32_t)(L >> 4) * 16;
    uint32_t aBase1 = aBase0 + 16 * 528;
    int Ln = L & 15;
    uint32_t bBase[4];
#pragma unroll
    for (int j = 0; j < 4; j++)
        bBase[j] = WtA + (uint32_t)((nwg * 4 + j) * 8 + (Ln & 7)) * 528 + (uint32_t)(Ln >> 3) * 16;

    for (int tile = blockIdx.x; tile < NT_N; tile += gridDim.x) {
        int r0 = tile * 64;
        for (int idx = tid; idx < 2048; idx += 256) {
            int r = idx >> 5, k4 = (idx & 31) * 4;
            int gr = r0 + r;
            float4 v = make_float4(0.f, 0.f, 0.f, 0.f);
            if (gr < N_NODES) v = *reinterpret_cast<const float4*>(&X[gr * HID + k4]);
            uint4 t;
            t.x = to_tf32(v.x); t.y = to_tf32(v.y); t.z = to_tf32(v.z); t.w = to_tf32(v.w);
            *reinterpret_cast<uint4*>(&Xs[r * 132 + k4]) = t;
        }
        __syncthreads();

        float acc[2][4][4];
#pragma unroll
        for (int i = 0; i < 2; i++)
#pragma unroll
            for (int j = 0; j < 4; j++)
#pragma unroll
                for (int e = 0; e < 4; e++) acc[i][j][e] = 0.0f;

#pragma unroll
        for (int kc = 0; kc < 16; kc++) {
            uint32_t a0[4], a1[4];
            ldsm_x4(a0, aBase0 + kc * 32);
            ldsm_x4(a1, aBase1 + kc * 32);
#pragma unroll
            for (int j = 0; j < 4; j++) {
                uint32_t b[2];
                ldsm_x2(b, bBase[j] + kc * 32);
                mma_tf32(acc[0][j], a0, b);
                mma_tf32(acc[1][j], a1, b);
            }
        }

#pragma unroll
        for (int i = 0; i < 2; i++) {
#pragma unroll
            for (int half = 0; half < 2; half++) {
                int gr = r0 + mw * 32 + i * 16 + half * 8 + (L >> 2);
                if (gr < N_NODES) {
#pragma unroll
                    for (int j = 0; j < 4; j++) {
                        int c = nwg * 32 + j * 8 + (L & 3) * 2;
                        float2 res;
                        res.x = acc[i][j][half * 2 + 0] + bs[c];
                        res.y = acc[i][j][half * 2 + 1] + bs[c + 1];
                        float* yp = &Y[gr * HID + c];
                        if (mode & GM_ACC) {
                            float2 o = *reinterpret_cast<float2*>(yp);
                            res.x += o.x; res.y += o.y;
                        }
                        if (mode & GM_SILU) { res.x = silu_f(res.x); res.y = silu_f(res.y); }
                        *reinterpret_cast<float2*>(yp) = res;
                    }
                }
            }
        }
        __syncthreads();
    }
}

// ---------------- gemm_ab: Y1 = X@Wa + b, Y2 = X@Wb ----------------
#define AB_SMEM ((33792 + 8448 + 128) * 4)

__global__ void __launch_bounds__(256, 1)
gemm_ab(const float* __restrict__ X, const float* __restrict__ Wa, const float* __restrict__ Wb,
        const float* __restrict__ bias, float* __restrict__ Y1, float* __restrict__ Y2) {
    extern __shared__ float sm[];
    float* Wts = sm;
    float* Xs = sm + 33792;
    float* bs = sm + 42240;
    int tid = threadIdx.x;

    load_w_trans(Wa, Wts, tid, 256, 132);
    load_w_trans(Wb, Wts + 128 * 132, tid, 256, 132);
    if (tid < 128) bs[tid] = bias[tid];
    __syncthreads();

    uint32_t XsA = smem_u32(Xs), WtA = smem_u32(Wts);
    int L = tid & 31, w = tid >> 5;
    int mw = w & 1, nwg = w >> 1;
    int aRow = ((L >> 3) & 1) * 8 + (L & 7);
    uint32_t aBase0 = XsA + (uint32_t)(mw * 32 + aRow) * 528 + (uint32_t)(L >> 4) * 16;
    uint32_t aBase1 = aBase0 + 16 * 528;
    int Ln = L & 15;
    uint32_t bBase[8];
#pragma unroll
    for (int j = 0; j < 8; j++) {
        int blk = (j < 4) ? (nwg * 4 + j) : (16 + nwg * 4 + (j - 4));
        bBase[j] = WtA + (uint32_t)(blk * 8 + (Ln & 7)) * 528 + (uint32_t)(Ln >> 3) * 16;
    }

    for (int tile = blockIdx.x; tile < NT_N; tile += gridDim.x) {
        int r0 = tile * 64;
        for (int idx = tid; idx < 2048; idx += 256) {
            int r = idx >> 5, k4 = (idx & 31) * 4;
            int gr = r0 + r;
            float4 v = make_float4(0.f, 0.f, 0.f, 0.f);
            if (gr < N_NODES) v = *reinterpret_cast<const float4*>(&X[gr * HID + k4]);
            uint4 t;
            t.x = to_tf32(v.x); t.y = to_tf32(v.y); t.z = to_tf32(v.z); t.w = to_tf32(v.w);
            *reinterpret_cast<uint4*>(&Xs[r * 132 + k4]) = t;
        }
        __syncthreads();

        float acc[2][8][4];
#pragma unroll
        for (int i = 0; i < 2; i++)
#pragma unroll
            for (int j = 0; j < 8; j++)
#pragma unroll
                for (int e = 0; e < 4; e++) acc[i][j][e] = 0.0f;

#pragma unroll
        for (int kc = 0; kc < 16; kc++) {
            uint32_t a0[4], a1[4];
            ldsm_x4(a0, aBase0 + kc * 32);
            ldsm_x4(a1, aBase1 + kc * 32);
#pragma unroll
            for (int j = 0; j < 8; j++) {
                uint32_t b[2];
                ldsm_x2(b, bBase[j] + kc * 32);
                mma_tf32(acc[0][j], a0, b);
                mma_tf32(acc[1][j], a1, b);
            }
        }

#pragma unroll
        for (int i = 0; i < 2; i++) {
#pragma unroll
            for (int half = 0; half < 2; half++) {
                int gr = r0 + mw * 32 + i * 16 + half * 8 + (L >> 2);
                if (gr < N_NODES) {
#pragma unroll
                    for (int j = 0; j < 8; j++) {
                        int c = nwg * 32 + (j & 3) * 8 + (L & 3) * 2;
                        float2 res;
                        res.x = acc[i][j][half * 2 + 0];
                        res.y = acc[i][j][half * 2 + 1];
                        if (j < 4) {
                            res.x += bs[c]; res.y += bs[c + 1];
                            *reinterpret_cast<float2*>(&Y1[gr * HID + c]) = res;
                        } else {
                            *reinterpret_cast<float2*>(&Y2[gr * HID + c]) = res;
                        }
                    }
                }
            }
        }
        __syncthreads();
    }
}

// ---------------- gemm_k256: Y = silu([X1, X2]@W + b), clears X2 ----------------
#define K256_SMEM ((34304 + 17152 + 128) * 4)

__global__ void __launch_bounds__(256, 1)
gemm_k256(const float* __restrict__ X1, float* __restrict__ X2,
          const float* __restrict__ W, const float* __restrict__ bias, float* __restrict__ Y) {
    extern __shared__ float sm[];
    float* Wts = sm;
    float* Xs = sm + 34304;
    float* bs = sm + 51456;
    int tid = threadIdx.x;

    for (int idx = tid; idx < 8192; idx += 256) {
        int k = idx >> 5, c0 = (idx & 31) * 4;
        float4 v = reinterpret_cast<const float4*>(W)[idx];
        *(uint32_t*)&Wts[(c0 + 0) * 268 + k] = to_tf32(v.x);
        *(uint32_t*)&Wts[(c0 + 1) * 268 + k] = to_tf32(v.y);
        *(uint32_t*)&Wts[(c0 + 2) * 268 + k] = to_tf32(v.z);
        *(uint32_t*)&Wts[(c0 + 3) * 268 + k] = to_tf32(v.w);
    }
    if (tid < 128) bs[tid] = bias[tid];
    __syncthreads();

    uint32_t XsA = smem_u32(Xs), WtA = smem_u32(Wts);
    int L = tid & 31, w = tid >> 5;
    int mw = w & 1, nwg = w >> 1;
    int aRow = ((L >> 3) & 1) * 8 + (L & 7);
    uint32_t aBase0 = XsA + (uint32_t)(mw * 32 + aRow) * 1072 + (uint32_t)(L >> 4) * 16;
    uint32_t aBase1 = aBase0 + 16 * 1072;
    int Ln = L & 15;
    uint32_t bBase[4];
#pragma unroll
    for (int j = 0; j < 4; j++)
        bBase[j] = WtA + (uint32_t)((nwg * 4 + j) * 8 + (Ln & 7)) * 1072 + (uint32_t)(Ln >> 3) * 16;

    for (int tile = blockIdx.x; tile < NT_N; tile += gridDim.x) {
        int r0 = tile * 64;
        for (int idx = tid; idx < 2048; idx += 256) {
            int r = idx >> 5, k4 = (idx & 31) * 4;
            int gr = r0 + r;
            float4 v1 = make_float4(0.f, 0.f, 0.f, 0.f);
            float4 v2 = make_float4(0.f, 0.f, 0.f, 0.f);
            if (gr < N_NODES) {
                v1 = *reinterpret_cast<const float4*>(&X1[gr * HID + k4]);
                v2 = *reinterpret_cast<float4*>(&X2[gr * HID + k4]);
                *reinterpret_cast<float4*>(&X2[gr * HID + k4]) = make_float4(0.f, 0.f, 0.f, 0.f);
            }
            uint4 t;
            t.x = to_tf32(v1.x); t.y = to_tf32(v1.y); t.z = to_tf32(v1.z); t.w = to_tf32(v1.w);
            *reinterpret_cast<uint4*>(&Xs[r * 268 + k4]) = t;
            t.x = to_tf32(v2.x); t.y = to_tf32(v2.y); t.z = to_tf32(v2.z); t.w = to_tf32(v2.w);
            *reinterpret_cast<uint4*>(&Xs[r * 268 + 128 + k4]) = t;
        }
        __syncthreads();

        float acc[2][4][4];
#pragma unroll
        for (int i = 0; i < 2; i++)
#pragma unroll
            for (int j = 0; j < 4; j++)
#pragma unroll
                for (int e = 0; e < 4; e++) acc[i][j][e] = 0.0f;

#pragma unroll
        for (int kc = 0; kc < 32; kc++) {
            uint32_t a0[4], a1[4];
            ldsm_x4(a0, aBase0 + kc * 32);
            ldsm_x4(a1, aBase1 + kc * 32);
#pragma unroll
            for (int j = 0; j < 4; j++) {
                uint32_t b[2];
                ldsm_x2(b, bBase[j] + kc * 32);
                mma_tf32(acc[0][j], a0, b);
                mma_tf32(acc[1][j], a1, b);
            }
        }

#pragma unroll
        for (int i = 0; i < 2; i++) {
#pragma unroll
            for (int half = 0; half < 2; half++) {
                int gr = r0 + mw * 32 + i * 16 + half * 8 + (L >> 2);
                if (gr < N_NODES) {
#pragma unroll
                    for (int j = 0; j < 4; j++) {
                        int c = nwg * 32 + j * 8 + (L & 3) * 2;
                        float2 res;
                        res.x = silu_f(acc[i][j][half * 2 + 0] + bs[c]);
                        res.y = silu_f(acc[i][j][half * 2 + 1] + bs[c + 1]);
                        *reinterpret_cast<float2*>(&Y[gr * HID + c]) = res;
                    }
                }
            }
        }
        __syncthreads();
    }
}

// ---------------- edge kernel: two independent 256-thread groups per CTA ----------------
#define EDGE_SMEM (52352 * 4)

__global__ void __launch_bounds__(512, 1)
edge_mma(const float* __restrict__ W2, const float* __restrict__ b2,
         const float* __restrict__ Wc1, const float* __restrict__ bc1,
         const float* __restrict__ wc2,
         const float* __restrict__ wr, const float* __restrict__ we) {
    extern __shared__ float sm[];
    float* W2s = sm;
    float* Wc1s = sm + 16896;
    float* b2s = sm + 50688;
    float* bc1s = sm + 50816;
    float* wc2s = sm + 50944;
    float* wrs = sm + 51072;
    float* wes = sm + 51200;

    int tid = threadIdx.x;
    load_w_trans(W2, W2s, tid, 512, 132);
    load_w_trans(Wc1, Wc1s, tid, 512, 132);
    if (tid < 128) {
        b2s[tid] = b2[tid]; bc1s[tid] = bc1[tid]; wc2s[tid] = wc2[tid];
        wrs[tid] = wr[tid]; wes[tid] = we[tid];
    }
    __syncthreads();

    int g = tid >> 8;           // group 0 / 1
    int gtid = tid & 255;
    int barid = 1 + g;

    float* tS = sm + 33792 + g * 8448;       // [64][132]
    float* diffs = sm + 51328 + g * 192;
    float* cw_part = sm + 51712 + g * 256;
    int* rows_s = (int*)(sm + 52224) + g * 64;

    uint32_t tSA = smem_u32(tS);
    uint32_t W2A = smem_u32(W2s), Wc1A = smem_u32(Wc1s);
    int L = gtid & 31, w = gtid >> 5;        // 8 warps per group
    int mw = w & 1, nwg = w >> 1;
    int aRow = ((L >> 3) & 1) * 8 + (L & 7);
    uint32_t aOff = (uint32_t)(mw * 32 + aRow) * 528 + (uint32_t)(L >> 4) * 16;
    // B-operand x4: lanes 0-15 tile jp*2, lanes 16-31 tile jp*2+1 (k-halves by L>>3 & 1)
    uint32_t bOff4[2];
#pragma unroll
    for (int jp = 0; jp < 2; jp++)
        bOff4[jp] = (uint32_t)((nwg * 4 + jp * 2 + (L >> 4)) * 8 + (L & 7)) * 528
                  + (uint32_t)((L >> 3) & 1) * 16;

    int e_loc = gtid >> 2, q = gtid & 3;     // 64 edges, 4 channel quarters

    for (int tile = blockIdx.x * 2 + g; tile < NT_E64; tile += gridDim.x * 2) {
        int e0 = tile * 64;
        // ---- gather (sorted edges; coalesced ch mapping: ch = jj*16 + q*4) ----
        {
            int e = e0 + e_loc;
            int r = d_erow[e], c = d_ecol[e];
            float dx = d_coord[r * 3 + 0] - d_coord[c * 3 + 0];
            float dy = d_coord[r * 3 + 1] - d_coord[c * 3 + 1];
            float dz = d_coord[r * 3 + 2] - d_coord[c * 3 + 2];
            float radial = dx * dx + dy * dy + dz * dz;
            float eav = d_eea[e];
            if (q == 0) {
                rows_s[e_loc] = r;
                diffs[e_loc * 3 + 0] = dx; diffs[e_loc * 3 + 1] = dy; diffs[e_loc * 3 + 2] = dz;
            }
#pragma unroll
            for (int jj = 0; jj < 8; jj++) {
                int ch = jj * 16 + q * 4;   // quarter-threads cover contiguous 64B per edge
                float4 av = *reinterpret_cast<const float4*>(&d_A[r * HID + ch]);
                float4 bv = *reinterpret_cast<const float4*>(&d_B[c * HID + ch]);
                float4 w1 = *reinterpret_cast<const float4*>(&wrs[ch]);
                float4 w2v = *reinterpret_cast<const float4*>(&wes[ch]);
                uint4 t;
                t.x = to_tf32(silu_f(av.x + bv.x + radial * w1.x + eav * w2v.x));
                t.y = to_tf32(silu_f(av.y + bv.y + radial * w1.y + eav * w2v.y));
                t.z = to_tf32(silu_f(av.z + bv.z + radial * w1.z + eav * w2v.z));
                t.w = to_tf32(silu_f(av.w + bv.w + radial * w1.w + eav * w2v.w));
                *reinterpret_cast<uint4*>(&tS[e_loc * 132 + ch]) = t;
            }
        }
        GBAR(barid);

        // ---- MMA1: D1 = tS @ W2^T ----
        float acc[2][4][4];
#pragma unroll
        for (int i = 0; i < 2; i++)
#pragma unroll
            for (int j = 0; j < 4; j++)
#pragma unroll
                for (int e = 0; e < 4; e++) acc[i][j][e] = 0.0f;
#pragma unroll
        for (int kc = 0; kc < 16; kc++) {
            uint32_t a0[4], a1[4];
            ldsm_x4(a0, tSA + aOff + kc * 32);
            ldsm_x4(a1, tSA + aOff + 16 * 528 + kc * 32);
#pragma unroll
            for (int jp = 0; jp < 2; jp++) {
                uint32_t b4[4];
                ldsm_x4(b4, W2A + bOff4[jp] + kc * 32);
                mma_tf32(acc[0][jp * 2 + 0], a0, b4 + 0);
                mma_tf32(acc[1][jp * 2 + 0], a1, b4 + 0);
                mma_tf32(acc[0][jp * 2 + 1], a0, b4 + 2);
                mma_tf32(acc[1][jp * 2 + 1], a1, b4 + 2);
            }
        }

        // ---- epilogue1: m = silu(D1 + b2) -> tS (own band) ----
#pragma unroll
        for (int i = 0; i < 2; i++) {
#pragma unroll
            for (int half = 0; half < 2; half++) {
                int rowl = mw * 32 + i * 16 + half * 8 + (L >> 2);
#pragma unroll
                for (int j = 0; j < 4; j++) {
                    int c = nwg * 32 + j * 8 + (L & 3) * 2;
                    float m0 = silu_f(acc[i][j][half * 2 + 0] + b2s[c]);
                    float m1 = silu_f(acc[i][j][half * 2 + 1] + b2s[c + 1]);
                    uint2 t;
                    t.x = to_tf32(m0); t.y = to_tf32(m1);
                    *reinterpret_cast<uint2*>(&tS[rowl * 132 + c]) = t;
                }
            }
        }
        GBAR(barid);

        // ---- segmented magg scatter (sorted rows), drains under MMA2 ----
        {
            int ch = gtid & 127, chunk = gtid >> 7;   // 2 chunks x 32 edges
            int base = chunk * 32;
            float accm = 0.0f;
            int prev = rows_s[base];
#pragma unroll 4
            for (int el = base; el < base + 32; el++) {
                int rn = rows_s[el];
                float mv = tS[el * 132 + ch];
                if (rn != prev) {
                    atomicAdd(&d_magg[prev * HID + ch], accm);
                    accm = 0.0f;
                    prev = rn;
                }
                accm += mv;
            }
            atomicAdd(&d_magg[prev * HID + ch], accm);
        }

        // ---- MMA2: D2 = mS @ Wc1^T ----
#pragma unroll
        for (int i = 0; i < 2; i++)
#pragma unroll
            for (int j = 0; j < 4; j++)
#pragma unroll
                for (int e = 0; e < 4; e++) acc[i][j][e] = 0.0f;
#pragma unroll
        for (int kc = 0; kc < 16; kc++) {
            uint32_t a0[4], a1[4];
            ldsm_x4(a0, tSA + aOff + kc * 32);
            ldsm_x4(a1, tSA + aOff + 16 * 528 + kc * 32);
#pragma unroll
            for (int jp = 0; jp < 2; jp++) {
                uint32_t b4[4];
                ldsm_x4(b4, Wc1A + bOff4[jp] + kc * 32);
                mma_tf32(acc[0][jp * 2 + 0], a0, b4 + 0);
                mma_tf32(acc[1][jp * 2 + 0], a1, b4 + 0);
                mma_tf32(acc[0][jp * 2 + 1], a0, b4 + 2);
                mma_tf32(acc[1][jp * 2 + 1], a1, b4 + 2);
            }
        }

        // ---- epilogue2: cw = sum_c silu(D2 + bc1)*wc2 ----
#pragma unroll
        for (int i = 0; i < 2; i++) {
#pragma unroll
            for (int half = 0; half < 2; half++) {
                float p = 0.0f;
#pragma unroll
                for (int j = 0; j < 4; j++) {
                    int c = nwg * 32 + j * 8 + (L & 3) * 2;
                    p += silu_f(acc[i][j][half * 2 + 0] + bc1s[c]) * wc2s[c];
                    p += silu_f(acc[i][j][half * 2 + 1] + bc1s[c + 1]) * wc2s[c + 1];
                }
                p += __shfl_xor_sync(0xffffffff, p, 1);
                p += __shfl_xor_sync(0xffffffff, p, 2);
                if ((L & 3) == 0) {
                    int rowl = mw * 32 + i * 16 + half * 8 + (L >> 2);
                    cw_part[nwg * 64 + rowl] = p;
                }
            }
        }
        GBAR(barid);
        if (gtid < 64) {
            int rn = rows_s[gtid];
            float cw = cw_part[gtid] + cw_part[64 + gtid] + cw_part[128 + gtid] + cw_part[192 + gtid];
            atomicAdd(&d_cagg[rn * 3 + 0], diffs[gtid * 3 + 0] * cw);
            atomicAdd(&d_cagg[rn * 3 + 1], diffs[gtid * 3 + 1] * cw);
            atomicAdd(&d_cagg[rn * 3 + 2], diffs[gtid * 3 + 2] * cw);
        }
        GBAR(barid);
    }
}

// ---------------- coord update (deg from histogram) ----------------
__global__ void coord_kernel() {
    int n = blockIdx.x * blockDim.x + threadIdx.x;
    if (n < N_NODES) {
        float inv = 1.0f / fmaxf((float)d_cnt[n], 1.0f);
#pragma unroll
        for (int dd = 0; dd < 3; dd++) {
            d_coord[n * 3 + dd] += d_cagg[n * 3 + dd] * inv;
            d_cagg[n * 3 + dd] = 0.0f;
        }
    }
}

// ---------------- global mean pool ----------------
__global__ void pool_kernel(const int* __restrict__ batch) {
    int n0 = blockIdx.x * 512;
    int ch = threadIdx.x;
    if (n0 >= N_NODES) return;
    int nend = min(n0 + 512, N_NODES);
    int cur = batch[n0];
    float acc = 0.0f, cnt = 0.0f;
    for (int n = n0; n < nend; n++) {
        int g = batch[n];
        if (g != cur) {
            atomicAdd(&d_gsum[cur * HID + ch], acc);
            if (ch == 0) atomicAdd(&d_gcnt[cur], cnt);
            acc = 0.0f; cnt = 0.0f; cur = g;
        }
        acc += d_A[n * HID + ch];
        cnt += 1.0f;
    }
    atomicAdd(&d_gsum[cur * HID + ch], acc);
    if (ch == 0) atomicAdd(&d_gcnt[cur], cnt);
}

// ---------------- final fc ----------------
__global__ void fc_kernel(const float* __restrict__ fcw, const float* __restrict__ fcb,
                          float* __restrict__ out) {
    int g = blockIdx.x;
    int ch = threadIdx.x;
    float inv = 1.0f / fmaxf(d_gcnt[g], 1.0f);
    float acc = fcb[ch];
    for (int k = 0; k < HID; k++)
        acc += d_gsum[g * HID + k] * inv * fcw[k * OUT_DIM + ch];
    out[g * OUT_DIM + ch] = acc;
}

// ---------------- launch ----------------
#define GRID_G 296
#define GRID_F 148
#define GRID_E 148

extern "C" void kernel_launch(void* const* d_in, const int* in_sizes, int n_in,
                              void* d_out, int out_size) {
    const float* x = (const float*)d_in[0];
    const int* eidx = (const int*)d_in[1];
    const float* coord = (const float*)d_in[2];
    const float* ea = (const float*)d_in[3];
    const int* batch = (const int*)d_in[4];
    const float* emb_in_w = (const float*)d_in[5];
    const float* emb_in_b = (const float*)d_in[6];
    const float* edge_w1 = (const float*)d_in[7];
    const float* edge_b1 = (const float*)d_in[8];
    const float* edge_w2 = (const float*)d_in[9];
    const float* edge_b2 = (const float*)d_in[10];
    const float* node_w1 = (const float*)d_in[11];
    const float* node_b1 = (const float*)d_in[12];
    const float* node_w2 = (const float*)d_in[13];
    const float* node_b2 = (const float*)d_in[14];
    const float* coord_w1 = (const float*)d_in[15];
    const float* coord_b1 = (const float*)d_in[16];
    const float* coord_w2 = (const float*)d_in[17];
    const float* emb_out_w = (const float*)d_in[18];
    const float* emb_out_b = (const float*)d_in[19];
    const float* fc_w = (const float*)d_in[20];
    const float* fc_b = (const float*)d_in[21];
    float* out = (float*)d_out;

    const int* row = eidx;
    const int* col = eidx + N_EDGES;

    float *ph, *pA, *pB, *pT, *pmagg;
    cudaGetSymbolAddress((void**)&ph, d_h);
    cudaGetSymbolAddress((void**)&pA, d_A);
    cudaGetSymbolAddress((void**)&pB, d_B);
    cudaGetSymbolAddress((void**)&pT, d_T);
    cudaGetSymbolAddress((void**)&pmagg, d_magg);

    cudaFuncSetAttribute(edge_mma, cudaFuncAttributeMaxDynamicSharedMemorySize, EDGE_SMEM);
    cudaFuncSetAttribute(gemm_mma, cudaFuncAttributeMaxDynamicSharedMemorySize, GEMM_SMEM);
    cudaFuncSetAttribute(gemm_ab, cudaFuncAttributeMaxDynamicSharedMemorySize, AB_SMEM);
    cudaFuncSetAttribute(gemm_k256, cudaFuncAttributeMaxDynamicSharedMemorySize, K256_SMEM);

    // ---- pre-pass: counting sort of edges by destination row ----
    init_kernel<<<(N_NODES * HID + 255) / 256, 256>>>(coord);
    hist_kernel<<<(N_EDGES + 255) / 256, 256>>>(row);
    scan1_kernel<<<SCAN_B, 512>>>();
    scan2_kernel<<<1, 32>>>();
    scan3_kernel<<<(N_NODES + 255) / 256, 256>>>();
    scatter_kernel<<<(N_EDGES + 255) / 256, 256>>>(row, col, ea);
    emb_in_kernel<<<(N_NODES * HID + 255) / 256, 256>>>(x, emb_in_w, emb_in_b);

    for (int l = 0; l < N_LAYERS; l++) {
        const float* W1 = edge_w1 + l * 258 * HID;
        gemm_ab<<<GRID_F, 256, AB_SMEM>>>(ph, W1, W1 + 128 * HID, edge_b1 + l * HID, pA, pB);
        edge_mma<<<GRID_E, 512, EDGE_SMEM>>>(
            edge_w2 + l * HID * HID, edge_b2 + l * HID,
            coord_w1 + l * HID * HID, coord_b1 + l * HID, coord_w2 + l * HID,
            W1 + 256 * HID, W1 + 257 * HID);
        coord_kernel<<<(N_NODES + 255) / 256, 256>>>();
        gemm_k256<<<GRID_F, 256, K256_SMEM>>>(ph, pmagg, node_w1 + l * 256 * HID,
                                              node_b1 + l * HID, pT);
        gemm_mma<<<GRID_G, 256, GEMM_SMEM>>>(pT, node_w2 + l * HID * HID,
                                             node_b2 + l * HID, ph, GM_BIAS | GM_ACC);
    }

    gemm_mma<<<GRID_G, 256, GEMM_SMEM>>>(ph, emb_out_w, emb_out_b, pA, GM_BIAS);
    pool_kernel<<<(N_NODES + 511) / 512, 128>>>(batch);
    fc_kernel<<<N_GRAPHS, 256>>>(fc_w, fc_b, out);
}

// round 14
// speedup vs baseline: 2.1426x; 1.0323x over previous
#include <cuda_runtime.h>
#include <math.h>
#include <stdint.h>

#define N_NODES 50000
#define N_EDGES 600000
#define N_GRAPHS 64
#define HID 128
#define IN_DIM 16
#define OUT_DIM 256
#define N_LAYERS 3
#define NT_E32 18750         // 600000 / 32 exactly
#define NT_N 782             // ceil(50000/64)
#define SCAN_B 98            // ceil(50000/512)

// ---------------- device scratch ----------------
__device__ float d_h[N_NODES * HID];
__device__ float d_A[N_NODES * HID];
__device__ float d_B[N_NODES * HID];
__device__ float d_T[N_NODES * HID];
__device__ float d_magg[N_NODES * HID];
__device__ float d_cagg[N_NODES * 3];
__device__ float d_coord[N_NODES * 3];
__device__ float d_gsum[N_GRAPHS * HID];
__device__ float d_gcnt[N_GRAPHS];
// edge sort
__device__ int d_cnt[N_NODES];
__device__ int d_cur[N_NODES];
__device__ int d_base[N_NODES];
__device__ int d_bsum[SCAN_B];
__device__ int d_erow[N_EDGES];
__device__ int d_ecol[N_EDGES];
__device__ float d_eea[N_EDGES];

// silu via tanh.approx: 1 MUFU
__device__ __forceinline__ float silu_f(float x) {
    float t;
    asm("tanh.approx.f32 %0, %1;" : "=f"(t) : "f"(x * 0.5f));
    return 0.5f * x * (1.0f + t);
}
__device__ __forceinline__ uint32_t smem_u32(const void* p) {
    uint32_t a;
    asm("{ .reg .u64 t; cvta.to.shared.u64 t, %1; cvt.u32.u64 %0, t; }" : "=r"(a) : "l"(p));
    return a;
}
__device__ __forceinline__ uint32_t to_tf32(float f) {
    uint32_t o;
    asm("cvt.rna.tf32.f32 %0, %1;" : "=r"(o) : "f"(f));
    return o;
}
__device__ __forceinline__ void ldsm_x4(uint32_t a[4], uint32_t addr) {
    asm volatile("ldmatrix.sync.aligned.m8n8.x4.shared.b16 {%0,%1,%2,%3}, [%4];"
        : "=r"(a[0]), "=r"(a[1]), "=r"(a[2]), "=r"(a[3]) : "r"(addr));
}
__device__ __forceinline__ void ldsm_x2(uint32_t b[2], uint32_t addr) {
    asm volatile("ldmatrix.sync.aligned.m8n8.x2.shared.b16 {%0,%1}, [%2];"
        : "=r"(b[0]), "=r"(b[1]) : "r"(addr));
}
__device__ __forceinline__ void mma_tf32(float d[4], const uint32_t a[4], const uint32_t b[2]) {
    asm volatile("mma.sync.aligned.m16n8k8.row.col.f32.tf32.tf32.f32 "
        "{%0,%1,%2,%3}, {%4,%5,%6,%7}, {%8,%9}, {%0,%1,%2,%3};"
        : "+f"(d[0]), "+f"(d[1]), "+f"(d[2]), "+f"(d[3])
        : "r"(a[0]), "r"(a[1]), "r"(a[2]), "r"(a[3]), "r"(b[0]), "r"(b[1]));
}
#define GBAR(id, cnt) asm volatile("bar.sync %0, %1;" :: "r"(id), "r"(cnt) : "memory")

// ---------------- init ----------------
__global__ void init_kernel(const float* __restrict__ coord_in) {
    int idx = blockIdx.x * blockDim.x + threadIdx.x;
    if (idx < N_NODES * HID) d_magg[idx] = 0.0f;
    if (idx < N_NODES * 3) { d_cagg[idx] = 0.0f; d_coord[idx] = coord_in[idx]; }
    if (idx < N_NODES) { d_cnt[idx] = 0; d_cur[idx] = 0; }
    if (idx < N_GRAPHS * HID) d_gsum[idx] = 0.0f;
    if (idx < N_GRAPHS) d_gcnt[idx] = 0.0f;
}

// ---------------- edge sort pre-pass ----------------
__global__ void hist_kernel(const int* __restrict__ row) {
    int e = blockIdx.x * blockDim.x + threadIdx.x;
    if (e < N_EDGES) atomicAdd(&d_cnt[row[e]], 1);
}
__global__ void scan1_kernel() {
    __shared__ int s[512];
    int tid = threadIdx.x;
    int i = blockIdx.x * 512 + tid;
    int v = (i < N_NODES) ? d_cnt[i] : 0;
    s[tid] = v;
    __syncthreads();
    for (int off = 1; off < 512; off <<= 1) {
        int t = (tid >= off) ? s[tid - off] : 0;
        __syncthreads();
        s[tid] += t;
        __syncthreads();
    }
    if (i < N_NODES) d_base[i] = s[tid] - v;
    if (tid == 511) d_bsum[blockIdx.x] = s[511];
}
__global__ void scan2_kernel() {
    if (threadIdx.x == 0) {
        int acc = 0;
        for (int b = 0; b < SCAN_B; b++) { int t = d_bsum[b]; d_bsum[b] = acc; acc += t; }
    }
}
__global__ void scan3_kernel() {
    int i = blockIdx.x * blockDim.x + threadIdx.x;
    if (i < N_NODES) d_base[i] += d_bsum[i >> 9];
}
__global__ void scatter_kernel(const int* __restrict__ row, const int* __restrict__ col,
                               const float* __restrict__ ea) {
    int e = blockIdx.x * blockDim.x + threadIdx.x;
    if (e < N_EDGES) {
        int r = row[e];
        int p = d_base[r] + atomicAdd(&d_cur[r], 1);
        d_erow[p] = r;
        d_ecol[p] = col[e];
        d_eea[p] = ea[e];
    }
}

__global__ void emb_in_kernel(const float* __restrict__ x,
                              const float* __restrict__ w,
                              const float* __restrict__ b) {
    int idx = blockIdx.x * blockDim.x + threadIdx.x;
    if (idx >= N_NODES * HID) return;
    int n = idx >> 7, ch = idx & 127;
    float acc = b[ch];
#pragma unroll
    for (int k = 0; k < IN_DIM; k++) acc += x[n * IN_DIM + k] * w[k * HID + ch];
    d_h[idx] = acc;
}

// store W[k][c] transposed+tf32 into Ws[c][k] (stride floats)
__device__ __forceinline__ void load_w_trans(const float* __restrict__ W, float* __restrict__ Ws,
                                             int tid, int nthreads, int stride) {
    for (int idx = tid; idx < 4096; idx += nthreads) {
        int k = idx >> 5, c0 = (idx & 31) * 4;
        float4 v = reinterpret_cast<const float4*>(W)[idx];
        *(uint32_t*)&Ws[(c0 + 0) * stride + k] = to_tf32(v.x);
        *(uint32_t*)&Ws[(c0 + 1) * stride + k] = to_tf32(v.y);
        *(uint32_t*)&Ws[(c0 + 2) * stride + k] = to_tf32(v.z);
        *(uint32_t*)&Ws[(c0 + 3) * stride + k] = to_tf32(v.w);
    }
}

// ---------------- gemm_mma: Y = op(X@W (+bias) (+Y)) ----------------
#define GEMM_SMEM ((16896 + 8448 + 128) * 4)
#define GM_BIAS 1
#define GM_ACC 2
#define GM_SILU 4

__global__ void __launch_bounds__(256, 2)
gemm_mma(float* __restrict__ X, const float* __restrict__ W,
         const float* __restrict__ bias, float* __restrict__ Y, int mode) {
    extern __shared__ float sm[];
    float* Wts = sm;
    float* Xs = sm + 16896;
    float* bs = sm + 25344;
    int tid = threadIdx.x;

    load_w_trans(W, Wts, tid, 256, 132);
    if (tid < 128) bs[tid] = (mode & GM_BIAS) ? bias[tid] : 0.0f;
    __syncthreads();

    uint32_t XsA = smem_u32(Xs), WtA = smem_u32(Wts);
    int L = tid & 31, w = tid >> 5;
    int mw = w & 1, nwg = w >> 1;
    int aRow = ((L >> 3) & 1) * 8 + (L & 7);
    uint32_t aBase0 = XsA + (uint32_t)(mw * 32 + aRow) * 528 + (uint32_t)(L >> 4) * 16;
    uint32_t aBase1 = aBase0 + 16 * 528;
    int Ln = L & 15;
    uint32_t bBase[4];
#pragma unroll
    for (int j = 0; j < 4; j++)
        bBase[j] = WtA + (uint32_t)((nwg * 4 + j) * 8 + (Ln & 7)) * 528 + (uint32_t)(Ln >> 3) * 16;

    for (int tile = blockIdx.x; tile < NT_N; tile += gridDim.x) {
        int r0 = tile * 64;
        for (int idx = tid; idx < 2048; idx += 256) {
            int r = idx >> 5, k4 = (idx & 31) * 4;
            int gr = r0 + r;
            float4 v = make_float4(0.f, 0.f, 0.f, 0.f);
            if (gr < N_NODES) v = *reinterpret_cast<const float4*>(&X[gr * HID + k4]);
            uint4 t;
            t.x = to_tf32(v.x); t.y = to_tf32(v.y); t.z = to_tf32(v.z); t.w = to_tf32(v.w);
            *reinterpret_cast<uint4*>(&Xs[r * 132 + k4]) = t;
        }
        __syncthreads();

        float acc[2][4][4];
#pragma unroll
        for (int i = 0; i < 2; i++)
#pragma unroll
            for (int j = 0; j < 4; j++)
#pragma unroll
                for (int e = 0; e < 4; e++) acc[i][j][e] = 0.0f;

#pragma unroll
        for (int kc = 0; kc < 16; kc++) {
            uint32_t a0[4], a1[4];
            ldsm_x4(a0, aBase0 + kc * 32);
            ldsm_x4(a1, aBase1 + kc * 32);
#pragma unroll
            for (int j = 0; j < 4; j++) {
                uint32_t b[2];
                ldsm_x2(b, bBase[j] + kc * 32);
                mma_tf32(acc[0][j], a0, b);
                mma_tf32(acc[1][j], a1, b);
            }
        }

#pragma unroll
        for (int i = 0; i < 2; i++) {
#pragma unroll
            for (int half = 0; half < 2; half++) {
                int gr = r0 + mw * 32 + i * 16 + half * 8 + (L >> 2);
                if (gr < N_NODES) {
#pragma unroll
                    for (int j = 0; j < 4; j++) {
                        int c = nwg * 32 + j * 8 + (L & 3) * 2;
                        float2 res;
                        res.x = acc[i][j][half * 2 + 0] + bs[c];
                        res.y = acc[i][j][half * 2 + 1] + bs[c + 1];
                        float* yp = &Y[gr * HID + c];
                        if (mode & GM_ACC) {
                            float2 o = *reinterpret_cast<float2*>(yp);
                            res.x += o.x; res.y += o.y;
                        }
                        if (mode & GM_SILU) { res.x = silu_f(res.x); res.y = silu_f(res.y); }
                        *reinterpret_cast<float2*>(yp) = res;
                    }
                }
            }
        }
        __syncthreads();
    }
}

// ---------------- gemm_ab: Y1 = X@Wa + b, Y2 = X@Wb ----------------
#define AB_SMEM ((33792 + 8448 + 128) * 4)

__global__ void __launch_bounds__(256, 1)
gemm_ab(const float* __restrict__ X, const float* __restrict__ Wa, const float* __restrict__ Wb,
        const float* __restrict__ bias, float* __restrict__ Y1, float* __restrict__ Y2) {
    extern __shared__ float sm[];
    float* Wts = sm;
    float* Xs = sm + 33792;
    float* bs = sm + 42240;
    int tid = threadIdx.x;

    load_w_trans(Wa, Wts, tid, 256, 132);
    load_w_trans(Wb, Wts + 128 * 132, tid, 256, 132);
    if (tid < 128) bs[tid] = bias[tid];
    __syncthreads();

    uint32_t XsA = smem_u32(Xs), WtA = smem_u32(Wts);
    int L = tid & 31, w = tid >> 5;
    int mw = w & 1, nwg = w >> 1;
    int aRow = ((L >> 3) & 1) * 8 + (L & 7);
    uint32_t aBase0 = XsA + (uint32_t)(mw * 32 + aRow) * 528 + (uint32_t)(L >> 4) * 16;
    uint32_t aBase1 = aBase0 + 16 * 528;
    int Ln = L & 15;
    uint32_t bBase[8];
#pragma unroll
    for (int j = 0; j < 8; j++) {
        int blk = (j < 4) ? (nwg * 4 + j) : (16 + nwg * 4 + (j - 4));
        bBase[j] = WtA + (uint32_t)(blk * 8 + (Ln & 7)) * 528 + (uint32_t)(Ln >> 3) * 16;
    }

    for (int tile = blockIdx.x; tile < NT_N; tile += gridDim.x) {
        int r0 = tile * 64;
        for (int idx = tid; idx < 2048; idx += 256) {
            int r = idx >> 5, k4 = (idx & 31) * 4;
            int gr = r0 + r;
            float4 v = make_float4(0.f, 0.f, 0.f, 0.f);
            if (gr < N_NODES) v = *reinterpret_cast<const float4*>(&X[gr * HID + k4]);
            uint4 t;
            t.x = to_tf32(v.x); t.y = to_tf32(v.y); t.z = to_tf32(v.z); t.w = to_tf32(v.w);
            *reinterpret_cast<uint4*>(&Xs[r * 132 + k4]) = t;
        }
        __syncthreads();

        float acc[2][8][4];
#pragma unroll
        for (int i = 0; i < 2; i++)
#pragma unroll
            for (int j = 0; j < 8; j++)
#pragma unroll
                for (int e = 0; e < 4; e++) acc[i][j][e] = 0.0f;

#pragma unroll
        for (int kc = 0; kc < 16; kc++) {
            uint32_t a0[4], a1[4];
            ldsm_x4(a0, aBase0 + kc * 32);
            ldsm_x4(a1, aBase1 + kc * 32);
#pragma unroll
            for (int j = 0; j < 8; j++) {
                uint32_t b[2];
                ldsm_x2(b, bBase[j] + kc * 32);
                mma_tf32(acc[0][j], a0, b);
                mma_tf32(acc[1][j], a1, b);
            }
        }

#pragma unroll
        for (int i = 0; i < 2; i++) {
#pragma unroll
            for (int half = 0; half < 2; half++) {
                int gr = r0 + mw * 32 + i * 16 + half * 8 + (L >> 2);
                if (gr < N_NODES) {
#pragma unroll
                    for (int j = 0; j < 8; j++) {
                        int c = nwg * 32 + (j & 3) * 8 + (L & 3) * 2;
                        float2 res;
                        res.x = acc[i][j][half * 2 + 0];
                        res.y = acc[i][j][half * 2 + 1];
                        if (j < 4) {
                            res.x += bs[c]; res.y += bs[c + 1];
                            *reinterpret_cast<float2*>(&Y1[gr * HID + c]) = res;
                        } else {
                            *reinterpret_cast<float2*>(&Y2[gr * HID + c]) = res;
                        }
                    }
                }
            }
        }
        __syncthreads();
    }
}

// ---------------- gemm_k256: Y = silu([X1, X2]@W + b), clears X2 ----------------
#define K256_SMEM ((34304 + 17152 + 128) * 4)

__global__ void __launch_bounds__(256, 1)
gemm_k256(const float* __restrict__ X1, float* __restrict__ X2,
          const float* __restrict__ W, const float* __restrict__ bias, float* __restrict__ Y) {
    extern __shared__ float sm[];
    float* Wts = sm;
    float* Xs = sm + 34304;
    float* bs = sm + 51456;
    int tid = threadIdx.x;

    for (int idx = tid; idx < 8192; idx += 256) {
        int k = idx >> 5, c0 = (idx & 31) * 4;
        float4 v = reinterpret_cast<const float4*>(W)[idx];
        *(uint32_t*)&Wts[(c0 + 0) * 268 + k] = to_tf32(v.x);
        *(uint32_t*)&Wts[(c0 + 1) * 268 + k] = to_tf32(v.y);
        *(uint32_t*)&Wts[(c0 + 2) * 268 + k] = to_tf32(v.z);
        *(uint32_t*)&Wts[(c0 + 3) * 268 + k] = to_tf32(v.w);
    }
    if (tid < 128) bs[tid] = bias[tid];
    __syncthreads();

    uint32_t XsA = smem_u32(Xs), WtA = smem_u32(Wts);
    int L = tid & 31, w = tid >> 5;
    int mw = w & 1, nwg = w >> 1;
    int aRow = ((L >> 3) & 1) * 8 + (L & 7);
    uint32_t aBase0 = XsA + (uint32_t)(mw * 32 + aRow) * 1072 + (uint32_t)(L >> 4) * 16;
    uint32_t aBase1 = aBase0 + 16 * 1072;
    int Ln = L & 15;
    uint32_t bBase[4];
#pragma unroll
    for (int j = 0; j < 4; j++)
        bBase[j] = WtA + (uint32_t)((nwg * 4 + j) * 8 + (Ln & 7)) * 1072 + (uint32_t)(Ln >> 3) * 16;

    for (int tile = blockIdx.x; tile < NT_N; tile += gridDim.x) {
        int r0 = tile * 64;
        for (int idx = tid; idx < 2048; idx += 256) {
            int r = idx >> 5, k4 = (idx & 31) * 4;
            int gr = r0 + r;
            float4 v1 = make_float4(0.f, 0.f, 0.f, 0.f);
            float4 v2 = make_float4(0.f, 0.f, 0.f, 0.f);
            if (gr < N_NODES) {
                v1 = *reinterpret_cast<const float4*>(&X1[gr * HID + k4]);
                v2 = *reinterpret_cast<float4*>(&X2[gr * HID + k4]);
                *reinterpret_cast<float4*>(&X2[gr * HID + k4]) = make_float4(0.f, 0.f, 0.f, 0.f);
            }
            uint4 t;
            t.x = to_tf32(v1.x); t.y = to_tf32(v1.y); t.z = to_tf32(v1.z); t.w = to_tf32(v1.w);
            *reinterpret_cast<uint4*>(&Xs[r * 268 + k4]) = t;
            t.x = to_tf32(v2.x); t.y = to_tf32(v2.y); t.z = to_tf32(v2.z); t.w = to_tf32(v2.w);
            *reinterpret_cast<uint4*>(&Xs[r * 268 + 128 + k4]) = t;
        }
        __syncthreads();

        float acc[2][4][4];
#pragma unroll
        for (int i = 0; i < 2; i++)
#pragma unroll
            for (int j = 0; j < 4; j++)
#pragma unroll
                for (int e = 0; e < 4; e++) acc[i][j][e] = 0.0f;

#pragma unroll
        for (int kc = 0; kc < 32; kc++) {
            uint32_t a0[4], a1[4];
            ldsm_x4(a0, aBase0 + kc * 32);
            ldsm_x4(a1, aBase1 + kc * 32);
#pragma unroll
            for (int j = 0; j < 4; j++) {
                uint32_t b[2];
                ldsm_x2(b, bBase[j] + kc * 32);
                mma_tf32(acc[0][j], a0, b);
                mma_tf32(acc[1][j], a1, b);
            }
        }

#pragma unroll
        for (int i = 0; i < 2; i++) {
#pragma unroll
            for (int half = 0; half < 2; half++) {
                int gr = r0 + mw * 32 + i * 16 + half * 8 + (L >> 2);
                if (gr < N_NODES) {
#pragma unroll
                    for (int j = 0; j < 4; j++) {
                        int c = nwg * 32 + j * 8 + (L & 3) * 2;
                        float2 res;
                        res.x = silu_f(acc[i][j][half * 2 + 0] + bs[c]);
                        res.y = silu_f(acc[i][j][half * 2 + 1] + bs[c + 1]);
                        *reinterpret_cast<float2*>(&Y[gr * HID + c]) = res;
                    }
                }
            }
        }
        __syncthreads();
    }
}

// ---------------- edge kernel: FOUR independent 128-thread groups per CTA ----------------
// smem floats: W2s@0, Wc1s@16896, tS@33792 (4 x 32 x 132), b2s@50688, bc1s@50816,
// wc2s@50944, wrs@51072, wes@51200, diffs@51328 (4x96), cw_part@51712 (4x128),
// rows_s@52224 (4x32 int) -> 52352 floats = 209 KB
#define EDGE_SMEM (52352 * 4)

__global__ void __launch_bounds__(512, 1)
edge_mma(const float* __restrict__ W2, const float* __restrict__ b2,
         const float* __restrict__ Wc1, const float* __restrict__ bc1,
         const float* __restrict__ wc2,
         const float* __restrict__ wr, const float* __restrict__ we) {
    extern __shared__ float sm[];
    float* W2s = sm;
    float* Wc1s = sm + 16896;
    float* b2s = sm + 50688;
    float* bc1s = sm + 50816;
    float* wc2s = sm + 50944;
    float* wrs = sm + 51072;
    float* wes = sm + 51200;

    int tid = threadIdx.x;
    load_w_trans(W2, W2s, tid, 512, 132);
    load_w_trans(Wc1, Wc1s, tid, 512, 132);
    if (tid < 128) {
        b2s[tid] = b2[tid]; bc1s[tid] = bc1[tid]; wc2s[tid] = wc2[tid];
        wrs[tid] = wr[tid]; wes[tid] = we[tid];
    }
    __syncthreads();

    int g = tid >> 7;           // group 0..3
    int gtid = tid & 127;
    int barid = 1 + g;

    float* tS = sm + 33792 + g * 4224;       // [32][132]
    float* diffs = sm + 51328 + g * 96;
    float* cw_part = sm + 51712 + g * 128;
    int* rows_s = (int*)(sm + 52224) + g * 32;

    uint32_t tSA = smem_u32(tS);
    uint32_t W2A = smem_u32(W2s), Wc1A = smem_u32(Wc1s);
    int L = gtid & 31, w = gtid >> 5;        // 4 warps per group
    int nwg = w;                             // each warp: all 32 rows x its 32 cols
    int aRow = ((L >> 3) & 1) * 8 + (L & 7);
    uint32_t aOff = (uint32_t)aRow * 528 + (uint32_t)(L >> 4) * 16;
    uint32_t bOff4[2];
#pragma unroll
    for (int jp = 0; jp < 2; jp++)
        bOff4[jp] = (uint32_t)((nwg * 4 + jp * 2 + (L >> 4)) * 8 + (L & 7)) * 528
                  + (uint32_t)((L >> 3) & 1) * 16;

    int e_loc = gtid >> 2, q = gtid & 3;     // 32 edges, 4 channel quarters

    for (int tile = blockIdx.x * 4 + g; tile < NT_E32; tile += gridDim.x * 4) {
        int e0 = tile * 32;
        // ---- gather (sorted edges; coalesced ch = jj*16 + q*4) ----
        {
            int e = e0 + e_loc;
            int r = d_erow[e], c = d_ecol[e];
            float dx = d_coord[r * 3 + 0] - d_coord[c * 3 + 0];
            float dy = d_coord[r * 3 + 1] - d_coord[c * 3 + 1];
            float dz = d_coord[r * 3 + 2] - d_coord[c * 3 + 2];
            float radial = dx * dx + dy * dy + dz * dz;
            float eav = d_eea[e];
            if (q == 0) {
                rows_s[e_loc] = r;
                diffs[e_loc * 3 + 0] = dx; diffs[e_loc * 3 + 1] = dy; diffs[e_loc * 3 + 2] = dz;
            }
#pragma unroll
            for (int jj = 0; jj < 8; jj++) {
                int ch = jj * 16 + q * 4;
                float4 av = *reinterpret_cast<const float4*>(&d_A[r * HID + ch]);
                float4 bv = *reinterpret_cast<const float4*>(&d_B[c * HID + ch]);
                float4 w1 = *reinterpret_cast<const float4*>(&wrs[ch]);
                float4 w2v = *reinterpret_cast<const float4*>(&wes[ch]);
                uint4 t;
                t.x = to_tf32(silu_f(av.x + bv.x + radial * w1.x + eav * w2v.x));
                t.y = to_tf32(silu_f(av.y + bv.y + radial * w1.y + eav * w2v.y));
                t.z = to_tf32(silu_f(av.z + bv.z + radial * w1.z + eav * w2v.z));
                t.w = to_tf32(silu_f(av.w + bv.w + radial * w1.w + eav * w2v.w));
                *reinterpret_cast<uint4*>(&tS[e_loc * 132 + ch]) = t;
            }
        }
        GBAR(barid, 128);

        // ---- MMA1: D1 = tS @ W2^T (rows 0-31, warp covers cols nwg*32..+31) ----
        float acc[2][4][4];
#pragma unroll
        for (int i = 0; i < 2; i++)
#pragma unroll
            for (int j = 0; j < 4; j++)
#pragma unroll
                for (int e = 0; e < 4; e++) acc[i][j][e] = 0.0f;
#pragma unroll
        for (int kc = 0; kc < 16; kc++) {
            uint32_t a0[4], a1[4];
            ldsm_x4(a0, tSA + aOff + kc * 32);
            ldsm_x4(a1, tSA + aOff + 16 * 528 + kc * 32);
#pragma unroll
            for (int jp = 0; jp < 2; jp++) {
                uint32_t b4[4];
                ldsm_x4(b4, W2A + bOff4[jp] + kc * 32);
                mma_tf32(acc[0][jp * 2 + 0], a0, b4 + 0);
                mma_tf32(acc[1][jp * 2 + 0], a1, b4 + 0);
                mma_tf32(acc[0][jp * 2 + 1], a0, b4 + 2);
                mma_tf32(acc[1][jp * 2 + 1], a1, b4 + 2);
            }
        }

        // ---- epilogue1: m = silu(D1 + b2) -> tS ----
#pragma unroll
        for (int i = 0; i < 2; i++) {
#pragma unroll
            for (int half = 0; half < 2; half++) {
                int rowl = i * 16 + half * 8 + (L >> 2);
#pragma unroll
                for (int j = 0; j < 4; j++) {
                    int c = nwg * 32 + j * 8 + (L & 3) * 2;
                    float m0 = silu_f(acc[i][j][half * 2 + 0] + b2s[c]);
                    float m1 = silu_f(acc[i][j][half * 2 + 1] + b2s[c + 1]);
                    uint2 t;
                    t.x = to_tf32(m0); t.y = to_tf32(m1);
                    *reinterpret_cast<uint2*>(&tS[rowl * 132 + c]) = t;
                }
            }
        }
        GBAR(barid, 128);

        // ---- segmented magg scatter: one thread per channel over 32 sorted edges ----
        {
            int ch = gtid;
            float accm = 0.0f;
            int prev = rows_s[0];
#pragma unroll 4
            for (int el = 0; el < 32; el++) {
                int rn = rows_s[el];
                float mv = tS[el * 132 + ch];
                if (rn != prev) {
                    atomicAdd(&d_magg[prev * HID + ch], accm);
                    accm = 0.0f;
                    prev = rn;
                }
                accm += mv;
            }
            atomicAdd(&d_magg[prev * HID + ch], accm);
        }

        // ---- MMA2: D2 = mS @ Wc1^T ----
#pragma unroll
        for (int i = 0; i < 2; i++)
#pragma unroll
            for (int j = 0; j < 4; j++)
#pragma unroll
                for (int e = 0; e < 4; e++) acc[i][j][e] = 0.0f;
#pragma unroll
        for (int kc = 0; kc < 16; kc++) {
            uint32_t a0[4], a1[4];
            ldsm_x4(a0, tSA + aOff + kc * 32);
            ldsm_x4(a1, tSA + aOff + 16 * 528 + kc * 32);
#pragma unroll
            for (int jp = 0; jp < 2; jp++) {
                uint32_t b4[4];
                ldsm_x4(b4, Wc1A + bOff4[jp] + kc * 32);
                mma_tf32(acc[0][jp * 2 + 0], a0, b4 + 0);
                mma_tf32(acc[1][jp * 2 + 0], a1, b4 + 0);
                mma_tf32(acc[0][jp * 2 + 1], a0, b4 + 2);
                mma_tf32(acc[1][jp * 2 + 1], a1, b4 + 2);
            }
        }

        // ---- epilogue2: cw = sum_c silu(D2 + bc1)*wc2 ----
#pragma unroll
        for (int i = 0; i < 2; i++) {
#pragma unroll
            for (int half = 0; half < 2; half++) {
                float p = 0.0f;
#pragma unroll
                for (int j = 0; j < 4; j++) {
                    int c = nwg * 32 + j * 8 + (L & 3) * 2;
                    p += silu_f(acc[i][j][half * 2 + 0] + bc1s[c]) * wc2s[c];
                    p += silu_f(acc[i][j][half * 2 + 1] + bc1s[c + 1]) * wc2s[c + 1];
                }
                p += __shfl_xor_sync(0xffffffff, p, 1);
                p += __shfl_xor_sync(0xffffffff, p, 2);
                if ((L & 3) == 0) {
                    int rowl = i * 16 + half * 8 + (L >> 2);
                    cw_part[nwg * 32 + rowl] = p;
                }
            }
        }
        GBAR(barid, 128);
        if (gtid < 32) {
            int rn = rows_s[gtid];
            float cw = cw_part[gtid] + cw_part[32 + gtid] + cw_part[64 + gtid] + cw_part[96 + gtid];
            atomicAdd(&d_cagg[rn * 3 + 0], diffs[gtid * 3 + 0] * cw);
            atomicAdd(&d_cagg[rn * 3 + 1], diffs[gtid * 3 + 1] * cw);
            atomicAdd(&d_cagg[rn * 3 + 2], diffs[gtid * 3 + 2] * cw);
        }
        GBAR(barid, 128);
    }
}

// ---------------- coord update (deg from histogram) ----------------
__global__ void coord_kernel() {
    int n = blockIdx.x * blockDim.x + threadIdx.x;
    if (n < N_NODES) {
        float inv = 1.0f / fmaxf((float)d_cnt[n], 1.0f);
#pragma unroll
        for (int dd = 0; dd < 3; dd++) {
            d_coord[n * 3 + dd] += d_cagg[n * 3 + dd] * inv;
            d_cagg[n * 3 + dd] = 0.0f;
        }
    }
}

// ---------------- global mean pool ----------------
__global__ void pool_kernel(const int* __restrict__ batch) {
    int n0 = blockIdx.x * 512;
    int ch = threadIdx.x;
    if (n0 >= N_NODES) return;
    int nend = min(n0 + 512, N_NODES);
    int cur = batch[n0];
    float acc = 0.0f, cnt = 0.0f;
    for (int n = n0; n < nend; n++) {
        int g = batch[n];
        if (g != cur) {
            atomicAdd(&d_gsum[cur * HID + ch], acc);
            if (ch == 0) atomicAdd(&d_gcnt[cur], cnt);
            acc = 0.0f; cnt = 0.0f; cur = g;
        }
        acc += d_A[n * HID + ch];
        cnt += 1.0f;
    }
    atomicAdd(&d_gsum[cur * HID + ch], acc);
    if (ch == 0) atomicAdd(&d_gcnt[cur], cnt);
}

// ---------------- final fc ----------------
__global__ void fc_kernel(const float* __restrict__ fcw, const float* __restrict__ fcb,
                          float* __restrict__ out) {
    int g = blockIdx.x;
    int ch = threadIdx.x;
    float inv = 1.0f / fmaxf(d_gcnt[g], 1.0f);
    float acc = fcb[ch];
    for (int k = 0; k < HID; k++)
        acc += d_gsum[g * HID + k] * inv * fcw[k * OUT_DIM + ch];
    out[g * OUT_DIM + ch] = acc;
}

// ---------------- launch ----------------
#define GRID_G 296
#define GRID_F 148
#define GRID_E 148

extern "C" void kernel_launch(void* const* d_in, const int* in_sizes, int n_in,
                              void* d_out, int out_size) {
    const float* x = (const float*)d_in[0];
    const int* eidx = (const int*)d_in[1];
    const float* coord = (const float*)d_in[2];
    const float* ea = (const float*)d_in[3];
    const int* batch = (const int*)d_in[4];
    const float* emb_in_w = (const float*)d_in[5];
    const float* emb_in_b = (const float*)d_in[6];
    const float* edge_w1 = (const float*)d_in[7];
    const float* edge_b1 = (const float*)d_in[8];
    const float* edge_w2 = (const float*)d_in[9];
    const float* edge_b2 = (const float*)d_in[10];
    const float* node_w1 = (const float*)d_in[11];
    const float* node_b1 = (const float*)d_in[12];
    const float* node_w2 = (const float*)d_in[13];
    const float* node_b2 = (const float*)d_in[14];
    const float* coord_w1 = (const float*)d_in[15];
    const float* coord_b1 = (const float*)d_in[16];
    const float* coord_w2 = (const float*)d_in[17];
    const float* emb_out_w = (const float*)d_in[18];
    const float* emb_out_b = (const float*)d_in[19];
    const float* fc_w = (const float*)d_in[20];
    const float* fc_b = (const float*)d_in[21];
    float* out = (float*)d_out;

    const int* row = eidx;
    const int* col = eidx + N_EDGES;

    float *ph, *pA, *pB, *pT, *pmagg;
    cudaGetSymbolAddress((void**)&ph, d_h);
    cudaGetSymbolAddress((void**)&pA, d_A);
    cudaGetSymbolAddress((void**)&pB, d_B);
    cudaGetSymbolAddress((void**)&pT, d_T);
    cudaGetSymbolAddress((void**)&pmagg, d_magg);

    cudaFuncSetAttribute(edge_mma, cudaFuncAttributeMaxDynamicSharedMemorySize, EDGE_SMEM);
    cudaFuncSetAttribute(gemm_mma, cudaFuncAttributeMaxDynamicSharedMemorySize, GEMM_SMEM);
    cudaFuncSetAttribute(gemm_ab, cudaFuncAttributeMaxDynamicSharedMemorySize, AB_SMEM);
    cudaFuncSetAttribute(gemm_k256, cudaFuncAttributeMaxDynamicSharedMemorySize, K256_SMEM);

    // ---- pre-pass: counting sort of edges by destination row ----
    init_kernel<<<(N_NODES * HID + 255) / 256, 256>>>(coord);
    hist_kernel<<<(N_EDGES + 255) / 256, 256>>>(row);
    scan1_kernel<<<SCAN_B, 512>>>();
    scan2_kernel<<<1, 32>>>();
    scan3_kernel<<<(N_NODES + 255) / 256, 256>>>();
    scatter_kernel<<<(N_EDGES + 255) / 256, 256>>>(row, col, ea);
    emb_in_kernel<<<(N_NODES * HID + 255) / 256, 256>>>(x, emb_in_w, emb_in_b);

    for (int l = 0; l < N_LAYERS; l++) {
        const float* W1 = edge_w1 + l * 258 * HID;
        gemm_ab<<<GRID_F, 256, AB_SMEM>>>(ph, W1, W1 + 128 * HID, edge_b1 + l * HID, pA, pB);
        edge_mma<<<GRID_E, 512, EDGE_SMEM>>>(
            edge_w2 + l * HID * HID, edge_b2 + l * HID,
            coord_w1 + l * HID * HID, coord_b1 + l * HID, coord_w2 + l * HID,
            W1 + 256 * HID, W1 + 257 * HID);
        coord_kernel<<<(N_NODES + 255) / 256, 256>>>();
        gemm_k256<<<GRID_F, 256, K256_SMEM>>>(ph, pmagg, node_w1 + l * 256 * HID,
                                              node_b1 + l * HID, pT);
        gemm_mma<<<GRID_G, 256, GEMM_SMEM>>>(pT, node_w2 + l * HID * HID,
                                             node_b2 + l * HID, ph, GM_BIAS | GM_ACC);
    }

    gemm_mma<<<GRID_G, 256, GEMM_SMEM>>>(ph, emb_out_w, emb_out_b, pA, GM_BIAS);
    pool_kernel<<<(N_NODES + 511) / 512, 128>>>(batch);
    fc_kernel<<<N_GRAPHS, 256>>>(fc_w, fc_b, out);
}

// round 15
// speedup vs baseline: 2.5541x; 1.1921x over previous
#include <cuda_runtime.h>
#include <cuda_fp16.h>
#include <math.h>
#include <stdint.h>

#define N_NODES 50000
#define N_EDGES 600000
#define N_GRAPHS 64
#define HID 128
#define IN_DIM 16
#define OUT_DIM 256
#define N_LAYERS 3
#define NT_E32 18750         // 600000 / 32 exactly
#define NT_N 782             // ceil(50000/64)
#define SCAN_B 98            // ceil(50000/512)
#define HSTR 136             // half-element stride for fp16 tiles (272B, conflict-free)

// ---------------- device scratch ----------------
__device__ float d_h[N_NODES * HID];
__device__ float d_A[N_NODES * HID];
__device__ float d_B[N_NODES * HID];
__device__ float d_T[N_NODES * HID];
__device__ float d_magg[N_NODES * HID];
__device__ float d_cagg[N_NODES * 3];
__device__ float d_coord[N_NODES * 3];
__device__ float d_gsum[N_GRAPHS * HID];
__device__ float d_gcnt[N_GRAPHS];
// edge sort
__device__ int d_cnt[N_NODES];
__device__ int d_cur[N_NODES];
__device__ int d_base[N_NODES];
__device__ int d_bsum[SCAN_B];
__device__ int d_erow[N_EDGES];
__device__ int d_ecol[N_EDGES];
__device__ float d_eea[N_EDGES];

// silu via tanh.approx: 1 MUFU
__device__ __forceinline__ float silu_f(float x) {
    float t;
    asm("tanh.approx.f32 %0, %1;" : "=f"(t) : "f"(x * 0.5f));
    return 0.5f * x * (1.0f + t);
}
__device__ __forceinline__ uint32_t smem_u32(const void* p) {
    uint32_t a;
    asm("{ .reg .u64 t; cvta.to.shared.u64 t, %1; cvt.u32.u64 %0, t; }" : "=r"(a) : "l"(p));
    return a;
}
__device__ __forceinline__ uint32_t to_tf32(float f) {
    uint32_t o;
    asm("cvt.rna.tf32.f32 %0, %1;" : "=r"(o) : "f"(f));
    return o;
}
__device__ __forceinline__ void ldsm_x4(uint32_t a[4], uint32_t addr) {
    asm volatile("ldmatrix.sync.aligned.m8n8.x4.shared.b16 {%0,%1,%2,%3}, [%4];"
        : "=r"(a[0]), "=r"(a[1]), "=r"(a[2]), "=r"(a[3]) : "r"(addr));
}
__device__ __forceinline__ void ldsm_x2(uint32_t b[2], uint32_t addr) {
    asm volatile("ldmatrix.sync.aligned.m8n8.x2.shared.b16 {%0,%1}, [%2];"
        : "=r"(b[0]), "=r"(b[1]) : "r"(addr));
}
__device__ __forceinline__ void mma_tf32(float d[4], const uint32_t a[4], const uint32_t b[2]) {
    asm volatile("mma.sync.aligned.m16n8k8.row.col.f32.tf32.tf32.f32 "
        "{%0,%1,%2,%3}, {%4,%5,%6,%7}, {%8,%9}, {%0,%1,%2,%3};"
        : "+f"(d[0]), "+f"(d[1]), "+f"(d[2]), "+f"(d[3])
        : "r"(a[0]), "r"(a[1]), "r"(a[2]), "r"(a[3]), "r"(b[0]), "r"(b[1]));
}
__device__ __forceinline__ void mma_f16(float d[4], const uint32_t a[4], const uint32_t b[2]) {
    asm volatile("mma.sync.aligned.m16n8k16.row.col.f32.f16.f16.f32 "
        "{%0,%1,%2,%3}, {%4,%5,%6,%7}, {%8,%9}, {%0,%1,%2,%3};"
        : "+f"(d[0]), "+f"(d[1]), "+f"(d[2]), "+f"(d[3])
        : "r"(a[0]), "r"(a[1]), "r"(a[2]), "r"(a[3]), "r"(b[0]), "r"(b[1]));
}
#define GBAR(id, cnt) asm volatile("bar.sync %0, %1;" :: "r"(id), "r"(cnt) : "memory")

// ---------------- init ----------------
__global__ void init_kernel(const float* __restrict__ coord_in) {
    int idx = blockIdx.x * blockDim.x + threadIdx.x;
    if (idx < N_NODES * HID) d_magg[idx] = 0.0f;
    if (idx < N_NODES * 3) { d_cagg[idx] = 0.0f; d_coord[idx] = coord_in[idx]; }
    if (idx < N_NODES) { d_cnt[idx] = 0; d_cur[idx] = 0; }
    if (idx < N_GRAPHS * HID) d_gsum[idx] = 0.0f;
    if (idx < N_GRAPHS) d_gcnt[idx] = 0.0f;
}

// ---------------- edge sort pre-pass ----------------
__global__ void hist_kernel(const int* __restrict__ row) {
    int e = blockIdx.x * blockDim.x + threadIdx.x;
    if (e < N_EDGES) atomicAdd(&d_cnt[row[e]], 1);
}
__global__ void scan1_kernel() {
    __shared__ int s[512];
    int tid = threadIdx.x;
    int i = blockIdx.x * 512 + tid;
    int v = (i < N_NODES) ? d_cnt[i] : 0;
    s[tid] = v;
    __syncthreads();
    for (int off = 1; off < 512; off <<= 1) {
        int t = (tid >= off) ? s[tid - off] : 0;
        __syncthreads();
        s[tid] += t;
        __syncthreads();
    }
    if (i < N_NODES) d_base[i] = s[tid] - v;
    if (tid == 511) d_bsum[blockIdx.x] = s[511];
}
__global__ void scan2_kernel() {
    if (threadIdx.x == 0) {
        int acc = 0;
        for (int b = 0; b < SCAN_B; b++) { int t = d_bsum[b]; d_bsum[b] = acc; acc += t; }
    }
}
__global__ void scan3_kernel() {
    int i = blockIdx.x * blockDim.x + threadIdx.x;
    if (i < N_NODES) d_base[i] += d_bsum[i >> 9];
}
__global__ void scatter_kernel(const int* __restrict__ row, const int* __restrict__ col,
                               const float* __restrict__ ea) {
    int e = blockIdx.x * blockDim.x + threadIdx.x;
    if (e < N_EDGES) {
        int r = row[e];
        int p = d_base[r] + atomicAdd(&d_cur[r], 1);
        d_erow[p] = r;
        d_ecol[p] = col[e];
        d_eea[p] = ea[e];
    }
}

__global__ void emb_in_kernel(const float* __restrict__ x,
                              const float* __restrict__ w,
                              const float* __restrict__ b) {
    int idx = blockIdx.x * blockDim.x + threadIdx.x;
    if (idx >= N_NODES * HID) return;
    int n = idx >> 7, ch = idx & 127;
    float acc = b[ch];
#pragma unroll
    for (int k = 0; k < IN_DIM; k++) acc += x[n * IN_DIM + k] * w[k * HID + ch];
    d_h[idx] = acc;
}

// store W[k][c] transposed+tf32 into Ws[c][k] (stride floats)
__device__ __forceinline__ void load_w_trans(const float* __restrict__ W, float* __restrict__ Ws,
                                             int tid, int nthreads, int stride) {
    for (int idx = tid; idx < 4096; idx += nthreads) {
        int k = idx >> 5, c0 = (idx & 31) * 4;
        float4 v = reinterpret_cast<const float4*>(W)[idx];
        *(uint32_t*)&Ws[(c0 + 0) * stride + k] = to_tf32(v.x);
        *(uint32_t*)&Ws[(c0 + 1) * stride + k] = to_tf32(v.y);
        *(uint32_t*)&Ws[(c0 + 2) * stride + k] = to_tf32(v.z);
        *(uint32_t*)&Ws[(c0 + 3) * stride + k] = to_tf32(v.w);
    }
}
// store W[k][c] transposed+fp16 into Wh[c][k] (HSTR halves stride)
__device__ __forceinline__ void load_w_trans_h(const float* __restrict__ W, __half* __restrict__ Wh,
                                               int tid, int nthreads) {
    for (int idx = tid; idx < 4096; idx += nthreads) {
        int k = idx >> 5, c0 = (idx & 31) * 4;
        float4 v = reinterpret_cast<const float4*>(W)[idx];
        Wh[(c0 + 0) * HSTR + k] = __float2half_rn(v.x);
        Wh[(c0 + 1) * HSTR + k] = __float2half_rn(v.y);
        Wh[(c0 + 2) * HSTR + k] = __float2half_rn(v.z);
        Wh[(c0 + 3) * HSTR + k] = __float2half_rn(v.w);
    }
}

// ---------------- gemm_mma: Y = op(X@W (+bias) (+Y)) ----------------
#define GEMM_SMEM ((16896 + 8448 + 128) * 4)
#define GM_BIAS 1
#define GM_ACC 2
#define GM_SILU 4

__global__ void __launch_bounds__(256, 2)
gemm_mma(float* __restrict__ X, const float* __restrict__ W,
         const float* __restrict__ bias, float* __restrict__ Y, int mode) {
    extern __shared__ float sm[];
    float* Wts = sm;
    float* Xs = sm + 16896;
    float* bs = sm + 25344;
    int tid = threadIdx.x;

    load_w_trans(W, Wts, tid, 256, 132);
    if (tid < 128) bs[tid] = (mode & GM_BIAS) ? bias[tid] : 0.0f;
    __syncthreads();

    uint32_t XsA = smem_u32(Xs), WtA = smem_u32(Wts);
    int L = tid & 31, w = tid >> 5;
    int mw = w & 1, nwg = w >> 1;
    int aRow = ((L >> 3) & 1) * 8 + (L & 7);
    uint32_t aBase0 = XsA + (uint32_t)(mw * 32 + aRow) * 528 + (uint32_t)(L >> 4) * 16;
    uint32_t aBase1 = aBase0 + 16 * 528;
    int Ln = L & 15;
    uint32_t bBase[4];
#pragma unroll
    for (int j = 0; j < 4; j++)
        bBase[j] = WtA + (uint32_t)((nwg * 4 + j) * 8 + (Ln & 7)) * 528 + (uint32_t)(Ln >> 3) * 16;

    for (int tile = blockIdx.x; tile < NT_N; tile += gridDim.x) {
        int r0 = tile * 64;
        for (int idx = tid; idx < 2048; idx += 256) {
            int r = idx >> 5, k4 = (idx & 31) * 4;
            int gr = r0 + r;
            float4 v = make_float4(0.f, 0.f, 0.f, 0.f);
            if (gr < N_NODES) v = *reinterpret_cast<const float4*>(&X[gr * HID + k4]);
            uint4 t;
            t.x = to_tf32(v.x); t.y = to_tf32(v.y); t.z = to_tf32(v.z); t.w = to_tf32(v.w);
            *reinterpret_cast<uint4*>(&Xs[r * 132 + k4]) = t;
        }
        __syncthreads();

        float acc[2][4][4];
#pragma unroll
        for (int i = 0; i < 2; i++)
#pragma unroll
            for (int j = 0; j < 4; j++)
#pragma unroll
                for (int e = 0; e < 4; e++) acc[i][j][e] = 0.0f;

#pragma unroll
        for (int kc = 0; kc < 16; kc++) {
            uint32_t a0[4], a1[4];
            ldsm_x4(a0, aBase0 + kc * 32);
            ldsm_x4(a1, aBase1 + kc * 32);
#pragma unroll
            for (int j = 0; j < 4; j++) {
                uint32_t b[2];
                ldsm_x2(b, bBase[j] + kc * 32);
                mma_tf32(acc[0][j], a0, b);
                mma_tf32(acc[1][j], a1, b);
            }
        }

#pragma unroll
        for (int i = 0; i < 2; i++) {
#pragma unroll
            for (int half = 0; half < 2; half++) {
                int gr = r0 + mw * 32 + i * 16 + half * 8 + (L >> 2);
                if (gr < N_NODES) {
#pragma unroll
                    for (int j = 0; j < 4; j++) {
                        int c = nwg * 32 + j * 8 + (L & 3) * 2;
                        float2 res;
                        res.x = acc[i][j][half * 2 + 0] + bs[c];
                        res.y = acc[i][j][half * 2 + 1] + bs[c + 1];
                        float* yp = &Y[gr * HID + c];
                        if (mode & GM_ACC) {
                            float2 o = *reinterpret_cast<float2*>(yp);
                            res.x += o.x; res.y += o.y;
                        }
                        if (mode & GM_SILU) { res.x = silu_f(res.x); res.y = silu_f(res.y); }
                        *reinterpret_cast<float2*>(yp) = res;
                    }
                }
            }
        }
        __syncthreads();
    }
}

// ---------------- gemm_ab: Y1 = X@Wa + b, Y2 = X@Wb ----------------
#define AB_SMEM ((33792 + 8448 + 128) * 4)

__global__ void __launch_bounds__(256, 1)
gemm_ab(const float* __restrict__ X, const float* __restrict__ Wa, const float* __restrict__ Wb,
        const float* __restrict__ bias, float* __restrict__ Y1, float* __restrict__ Y2) {
    extern __shared__ float sm[];
    float* Wts = sm;
    float* Xs = sm + 33792;
    float* bs = sm + 42240;
    int tid = threadIdx.x;

    load_w_trans(Wa, Wts, tid, 256, 132);
    load_w_trans(Wb, Wts + 128 * 132, tid, 256, 132);
    if (tid < 128) bs[tid] = bias[tid];
    __syncthreads();

    uint32_t XsA = smem_u32(Xs), WtA = smem_u32(Wts);
    int L = tid & 31, w = tid >> 5;
    int mw = w & 1, nwg = w >> 1;
    int aRow = ((L >> 3) & 1) * 8 + (L & 7);
    uint32_t aBase0 = XsA + (uint32_t)(mw * 32 + aRow) * 528 + (uint32_t)(L >> 4) * 16;
    uint32_t aBase1 = aBase0 + 16 * 528;
    int Ln = L & 15;
    uint32_t bBase[8];
#pragma unroll
    for (int j = 0; j < 8; j++) {
        int blk = (j < 4) ? (nwg * 4 + j) : (16 + nwg * 4 + (j - 4));
        bBase[j] = WtA + (uint32_t)(blk * 8 + (Ln & 7)) * 528 + (uint32_t)(Ln >> 3) * 16;
    }

    for (int tile = blockIdx.x; tile < NT_N; tile += gridDim.x) {
        int r0 = tile * 64;
        for (int idx = tid; idx < 2048; idx += 256) {
            int r = idx >> 5, k4 = (idx & 31) * 4;
            int gr = r0 + r;
            float4 v = make_float4(0.f, 0.f, 0.f, 0.f);
            if (gr < N_NODES) v = *reinterpret_cast<const float4*>(&X[gr * HID + k4]);
            uint4 t;
            t.x = to_tf32(v.x); t.y = to_tf32(v.y); t.z = to_tf32(v.z); t.w = to_tf32(v.w);
            *reinterpret_cast<uint4*>(&Xs[r * 132 + k4]) = t;
        }
        __syncthreads();

        float acc[2][8][4];
#pragma unroll
        for (int i = 0; i < 2; i++)
#pragma unroll
            for (int j = 0; j < 8; j++)
#pragma unroll
                for (int e = 0; e < 4; e++) acc[i][j][e] = 0.0f;

#pragma unroll
        for (int kc = 0; kc < 16; kc++) {
            uint32_t a0[4], a1[4];
            ldsm_x4(a0, aBase0 + kc * 32);
            ldsm_x4(a1, aBase1 + kc * 32);
#pragma unroll
            for (int j = 0; j < 8; j++) {
                uint32_t b[2];
                ldsm_x2(b, bBase[j] + kc * 32);
                mma_tf32(acc[0][j], a0, b);
                mma_tf32(acc[1][j], a1, b);
            }
        }

#pragma unroll
        for (int i = 0; i < 2; i++) {
#pragma unroll
            for (int half = 0; half < 2; half++) {
                int gr = r0 + mw * 32 + i * 16 + half * 8 + (L >> 2);
                if (gr < N_NODES) {
#pragma unroll
                    for (int j = 0; j < 8; j++) {
                        int c = nwg * 32 + (j & 3) * 8 + (L & 3) * 2;
                        float2 res;
                        res.x = acc[i][j][half * 2 + 0];
                        res.y = acc[i][j][half * 2 + 1];
                        if (j < 4) {
                            res.x += bs[c]; res.y += bs[c + 1];
                            *reinterpret_cast<float2*>(&Y1[gr * HID + c]) = res;
                        } else {
                            *reinterpret_cast<float2*>(&Y2[gr * HID + c]) = res;
                        }
                    }
                }
            }
        }
        __syncthreads();
    }
}

// ---------------- gemm_k256: Y = silu([X1, X2]@W + b), clears X2 ----------------
#define K256_SMEM ((34304 + 17152 + 128) * 4)

__global__ void __launch_bounds__(256, 1)
gemm_k256(const float* __restrict__ X1, float* __restrict__ X2,
          const float* __restrict__ W, const float* __restrict__ bias, float* __restrict__ Y) {
    extern __shared__ float sm[];
    float* Wts = sm;
    float* Xs = sm + 34304;
    float* bs = sm + 51456;
    int tid = threadIdx.x;

    for (int idx = tid; idx < 8192; idx += 256) {
        int k = idx >> 5, c0 = (idx & 31) * 4;
        float4 v = reinterpret_cast<const float4*>(W)[idx];
        *(uint32_t*)&Wts[(c0 + 0) * 268 + k] = to_tf32(v.x);
        *(uint32_t*)&Wts[(c0 + 1) * 268 + k] = to_tf32(v.y);
        *(uint32_t*)&Wts[(c0 + 2) * 268 + k] = to_tf32(v.z);
        *(uint32_t*)&Wts[(c0 + 3) * 268 + k] = to_tf32(v.w);
    }
    if (tid < 128) bs[tid] = bias[tid];
    __syncthreads();

    uint32_t XsA = smem_u32(Xs), WtA = smem_u32(Wts);
    int L = tid & 31, w = tid >> 5;
    int mw = w & 1, nwg = w >> 1;
    int aRow = ((L >> 3) & 1) * 8 + (L & 7);
    uint32_t aBase0 = XsA + (uint32_t)(mw * 32 + aRow) * 1072 + (uint32_t)(L >> 4) * 16;
    uint32_t aBase1 = aBase0 + 16 * 1072;
    int Ln = L & 15;
    uint32_t bBase[4];
#pragma unroll
    for (int j = 0; j < 4; j++)
        bBase[j] = WtA + (uint32_t)((nwg * 4 + j) * 8 + (Ln & 7)) * 1072 + (uint32_t)(Ln >> 3) * 16;

    for (int tile = blockIdx.x; tile < NT_N; tile += gridDim.x) {
        int r0 = tile * 64;
        for (int idx = tid; idx < 2048; idx += 256) {
            int r = idx >> 5, k4 = (idx & 31) * 4;
            int gr = r0 + r;
            float4 v1 = make_float4(0.f, 0.f, 0.f, 0.f);
            float4 v2 = make_float4(0.f, 0.f, 0.f, 0.f);
            if (gr < N_NODES) {
                v1 = *reinterpret_cast<const float4*>(&X1[gr * HID + k4]);
                v2 = *reinterpret_cast<float4*>(&X2[gr * HID + k4]);
                *reinterpret_cast<float4*>(&X2[gr * HID + k4]) = make_float4(0.f, 0.f, 0.f, 0.f);
            }
            uint4 t;
            t.x = to_tf32(v1.x); t.y = to_tf32(v1.y); t.z = to_tf32(v1.z); t.w = to_tf32(v1.w);
            *reinterpret_cast<uint4*>(&Xs[r * 268 + k4]) = t;
            t.x = to_tf32(v2.x); t.y = to_tf32(v2.y); t.z = to_tf32(v2.z); t.w = to_tf32(v2.w);
            *reinterpret_cast<uint4*>(&Xs[r * 268 + 128 + k4]) = t;
        }
        __syncthreads();

        float acc[2][4][4];
#pragma unroll
        for (int i = 0; i < 2; i++)
#pragma unroll
            for (int j = 0; j < 4; j++)
#pragma unroll
                for (int e = 0; e < 4; e++) acc[i][j][e] = 0.0f;

#pragma unroll
        for (int kc = 0; kc < 32; kc++) {
            uint32_t a0[4], a1[4];
            ldsm_x4(a0, aBase0 + kc * 32);
            ldsm_x4(a1, aBase1 + kc * 32);
#pragma unroll
            for (int j = 0; j < 4; j++) {
                uint32_t b[2];
                ldsm_x2(b, bBase[j] + kc * 32);
                mma_tf32(acc[0][j], a0, b);
                mma_tf32(acc[1][j], a1, b);
            }
        }

#pragma unroll
        for (int i = 0; i < 2; i++) {
#pragma unroll
            for (int half = 0; half < 2; half++) {
                int gr = r0 + mw * 32 + i * 16 + half * 8 + (L >> 2);
                if (gr < N_NODES) {
#pragma unroll
                    for (int j = 0; j < 4; j++) {
                        int c = nwg * 32 + j * 8 + (L & 3) * 2;
                        float2 res;
                        res.x = silu_f(acc[i][j][half * 2 + 0] + bs[c]);
                        res.y = silu_f(acc[i][j][half * 2 + 1] + bs[c + 1]);
                        *reinterpret_cast<float2*>(&Y[gr * HID + c]) = res;
                    }
                }
            }
        }
        __syncthreads();
    }
}

// ---------------- edge kernel: fp16 MMA (m16n8k16), 4 x 128-thread groups ----------------
// float offsets: W2h@0 (8704 f), Wc1h@8704, tS@17408 (4 x 2176 f), b2s@26112,
// bc1s@26240, wc2s@26368, wrs@26496, wes@26624, diffs@26752 (384),
// cw_part@27136 (512), rows_s@27648 (128) -> 27776 floats = 111104 B
#define EDGE_SMEM (27776 * 4)

__global__ void __launch_bounds__(512, 1)
edge_mma(const float* __restrict__ W2, const float* __restrict__ b2,
         const float* __restrict__ Wc1, const float* __restrict__ bc1,
         const float* __restrict__ wc2,
         const float* __restrict__ wr, const float* __restrict__ we) {
    extern __shared__ float sm[];
    __half* W2h = reinterpret_cast<__half*>(sm);
    __half* Wc1h = reinterpret_cast<__half*>(sm + 8704);
    float* b2s = sm + 26112;
    float* bc1s = sm + 26240;
    float* wc2s = sm + 26368;
    float* wrs = sm + 26496;
    float* wes = sm + 26624;

    int tid = threadIdx.x;
    load_w_trans_h(W2, W2h, tid, 512);
    load_w_trans_h(Wc1, Wc1h, tid, 512);
    if (tid < 128) {
        b2s[tid] = b2[tid]; bc1s[tid] = bc1[tid]; wc2s[tid] = wc2[tid];
        wrs[tid] = wr[tid]; wes[tid] = we[tid];
    }
    __syncthreads();

    int g = tid >> 7;           // group 0..3
    int gtid = tid & 127;
    int barid = 1 + g;

    __half* tSh = reinterpret_cast<__half*>(sm + 17408) + g * (32 * HSTR);
    float* diffs = sm + 26752 + g * 96;
    float* cw_part = sm + 27136 + g * 128;
    int* rows_s = (int*)(sm + 27648) + g * 32;

    uint32_t tSA = smem_u32(tSh);
    uint32_t W2A = smem_u32(W2h), Wc1A = smem_u32(Wc1h);
    int L = gtid & 31, w = gtid >> 5;        // 4 warps per group
    int nwg = w;                             // warp covers cols nwg*32..+31
    // A fragment (m16k16): lanes 0-15 -> rows 0-15 (k bytes 0-15), lanes 16-31 -> +16B
    uint32_t aOffH = (uint32_t)(L & 15) * (HSTR * 2) + (uint32_t)(L >> 4) * 16;
    // B fragment x4 over Wt[n][k] halves: 2 n-tiles x 2 k-halves
    uint32_t bOffH[2];
#pragma unroll
    for (int jp = 0; jp < 2; jp++)
        bOffH[jp] = (uint32_t)((nwg * 32 + jp * 16 + (L >> 4) * 8 + (L & 7))) * (HSTR * 2)
                  + (uint32_t)((L >> 3) & 1) * 16;

    int e_loc = gtid >> 2, q = gtid & 3;     // 32 edges, 4 channel quarters

    for (int tile = blockIdx.x * 4 + g; tile < NT_E32; tile += gridDim.x * 4) {
        int e0 = tile * 32;
        // ---- gather (sorted edges; coalesced ch = jj*16 + q*4), fp16 store ----
        {
            int e = e0 + e_loc;
            int r = d_erow[e], c = d_ecol[e];
            float dx = d_coord[r * 3 + 0] - d_coord[c * 3 + 0];
            float dy = d_coord[r * 3 + 1] - d_coord[c * 3 + 1];
            float dz = d_coord[r * 3 + 2] - d_coord[c * 3 + 2];
            float radial = dx * dx + dy * dy + dz * dz;
            float eav = d_eea[e];
            if (q == 0) {
                rows_s[e_loc] = r;
                diffs[e_loc * 3 + 0] = dx; diffs[e_loc * 3 + 1] = dy; diffs[e_loc * 3 + 2] = dz;
            }
#pragma unroll
            for (int jj = 0; jj < 8; jj++) {
                int ch = jj * 16 + q * 4;
                float4 av = *reinterpret_cast<const float4*>(&d_A[r * HID + ch]);
                float4 bv = *reinterpret_cast<const float4*>(&d_B[c * HID + ch]);
                float4 w1 = *reinterpret_cast<const float4*>(&wrs[ch]);
                float4 w2v = *reinterpret_cast<const float4*>(&wes[ch]);
                __half2 h01 = __floats2half2_rn(
                    silu_f(av.x + bv.x + radial * w1.x + eav * w2v.x),
                    silu_f(av.y + bv.y + radial * w1.y + eav * w2v.y));
                __half2 h23 = __floats2half2_rn(
                    silu_f(av.z + bv.z + radial * w1.z + eav * w2v.z),
                    silu_f(av.w + bv.w + radial * w1.w + eav * w2v.w));
                uint2 u;
                u.x = *reinterpret_cast<uint32_t*>(&h01);
                u.y = *reinterpret_cast<uint32_t*>(&h23);
                *reinterpret_cast<uint2*>(&tSh[e_loc * HSTR + ch]) = u;
            }
        }
        GBAR(barid, 128);

        // ---- MMA1: D1 = tS @ W2^T (fp16, K=16 per step) ----
        float acc[2][4][4];
#pragma unroll
        for (int i = 0; i < 2; i++)
#pragma unroll
            for (int j = 0; j < 4; j++)
#pragma unroll
                for (int e = 0; e < 4; e++) acc[i][j][e] = 0.0f;
#pragma unroll
        for (int kc = 0; kc < 8; kc++) {
            uint32_t a0[4], a1[4];
            ldsm_x4(a0, tSA + aOffH + kc * 32);
            ldsm_x4(a1, tSA + aOffH + 16 * (HSTR * 2) + kc * 32);
#pragma unroll
            for (int jp = 0; jp < 2; jp++) {
                uint32_t b4[4];
                ldsm_x4(b4, W2A + bOffH[jp] + kc * 32);
                mma_f16(acc[0][jp * 2 + 0], a0, b4 + 0);
                mma_f16(acc[1][jp * 2 + 0], a1, b4 + 0);
                mma_f16(acc[0][jp * 2 + 1], a0, b4 + 2);
                mma_f16(acc[1][jp * 2 + 1], a1, b4 + 2);
            }
        }

        // ---- epilogue1: m = silu(D1 + b2) -> tS (fp16) ----
#pragma unroll
        for (int i = 0; i < 2; i++) {
#pragma unroll
            for (int half = 0; half < 2; half++) {
                int rowl = i * 16 + half * 8 + (L >> 2);
#pragma unroll
                for (int j = 0; j < 4; j++) {
                    int c = nwg * 32 + j * 8 + (L & 3) * 2;
                    __half2 mh = __floats2half2_rn(
                        silu_f(acc[i][j][half * 2 + 0] + b2s[c]),
                        silu_f(acc[i][j][half * 2 + 1] + b2s[c + 1]));
                    *reinterpret_cast<__half2*>(&tSh[rowl * HSTR + c]) = mh;
                }
            }
        }
        GBAR(barid, 128);

        // ---- segmented magg scatter: one thread per channel over 32 sorted edges ----
        {
            int ch = gtid;
            float accm = 0.0f;
            int prev = rows_s[0];
#pragma unroll 4
            for (int el = 0; el < 32; el++) {
                int rn = rows_s[el];
                float mv = __half2float(tSh[el * HSTR + ch]);
                if (rn != prev) {
                    atomicAdd(&d_magg[prev * HID + ch], accm);
                    accm = 0.0f;
                    prev = rn;
                }
                accm += mv;
            }
            atomicAdd(&d_magg[prev * HID + ch], accm);
        }

        // ---- MMA2: D2 = mS @ Wc1^T ----
#pragma unroll
        for (int i = 0; i < 2; i++)
#pragma unroll
            for (int j = 0; j < 4; j++)
#pragma unroll
                for (int e = 0; e < 4; e++) acc[i][j][e] = 0.0f;
#pragma unroll
        for (int kc = 0; kc < 8; kc++) {
            uint32_t a0[4], a1[4];
            ldsm_x4(a0, tSA + aOffH + kc * 32);
            ldsm_x4(a1, tSA + aOffH + 16 * (HSTR * 2) + kc * 32);
#pragma unroll
            for (int jp = 0; jp < 2; jp++) {
                uint32_t b4[4];
                ldsm_x4(b4, Wc1A + bOffH[jp] + kc * 32);
                mma_f16(acc[0][jp * 2 + 0], a0, b4 + 0);
                mma_f16(acc[1][jp * 2 + 0], a1, b4 + 0);
                mma_f16(acc[0][jp * 2 + 1], a0, b4 + 2);
                mma_f16(acc[1][jp * 2 + 1], a1, b4 + 2);
            }
        }

        // ---- epilogue2: cw = sum_c silu(D2 + bc1)*wc2 ----
#pragma unroll
        for (int i = 0; i < 2; i++) {
#pragma unroll
            for (int half = 0; half < 2; half++) {
                float p = 0.0f;
#pragma unroll
                for (int j = 0; j < 4; j++) {
                    int c = nwg * 32 + j * 8 + (L & 3) * 2;
                    p += silu_f(acc[i][j][half * 2 + 0] + bc1s[c]) * wc2s[c];
                    p += silu_f(acc[i][j][half * 2 + 1] + bc1s[c + 1]) * wc2s[c + 1];
                }
                p += __shfl_xor_sync(0xffffffff, p, 1);
                p += __shfl_xor_sync(0xffffffff, p, 2);
                if ((L & 3) == 0) {
                    int rowl = i * 16 + half * 8 + (L >> 2);
                    cw_part[nwg * 32 + rowl] = p;
                }
            }
        }
        GBAR(barid, 128);
        if (gtid < 32) {
            int rn = rows_s[gtid];
            float cw = cw_part[gtid] + cw_part[32 + gtid] + cw_part[64 + gtid] + cw_part[96 + gtid];
            atomicAdd(&d_cagg[rn * 3 + 0], diffs[gtid * 3 + 0] * cw);
            atomicAdd(&d_cagg[rn * 3 + 1], diffs[gtid * 3 + 1] * cw);
            atomicAdd(&d_cagg[rn * 3 + 2], diffs[gtid * 3 + 2] * cw);
        }
        GBAR(barid, 128);
    }
}

// ---------------- coord update (deg from histogram) ----------------
__global__ void coord_kernel() {
    int n = blockIdx.x * blockDim.x + threadIdx.x;
    if (n < N_NODES) {
        float inv = 1.0f / fmaxf((float)d_cnt[n], 1.0f);
#pragma unroll
        for (int dd = 0; dd < 3; dd++) {
            d_coord[n * 3 + dd] += d_cagg[n * 3 + dd] * inv;
            d_cagg[n * 3 + dd] = 0.0f;
        }
    }
}

// ---------------- global mean pool ----------------
__global__ void pool_kernel(const int* __restrict__ batch) {
    int n0 = blockIdx.x * 512;
    int ch = threadIdx.x;
    if (n0 >= N_NODES) return;
    int nend = min(n0 + 512, N_NODES);
    int cur = batch[n0];
    float acc = 0.0f, cnt = 0.0f;
    for (int n = n0; n < nend; n++) {
        int g = batch[n];
        if (g != cur) {
            atomicAdd(&d_gsum[cur * HID + ch], acc);
            if (ch == 0) atomicAdd(&d_gcnt[cur], cnt);
            acc = 0.0f; cnt = 0.0f; cur = g;
        }
        acc += d_A[n * HID + ch];
        cnt += 1.0f;
    }
    atomicAdd(&d_gsum[cur * HID + ch], acc);
    if (ch == 0) atomicAdd(&d_gcnt[cur], cnt);
}

// ---------------- final fc ----------------
__global__ void fc_kernel(const float* __restrict__ fcw, const float* __restrict__ fcb,
                          float* __restrict__ out) {
    int g = blockIdx.x;
    int ch = threadIdx.x;
    float inv = 1.0f / fmaxf(d_gcnt[g], 1.0f);
    float acc = fcb[ch];
    for (int k = 0; k < HID; k++)
        acc += d_gsum[g * HID + k] * inv * fcw[k * OUT_DIM + ch];
    out[g * OUT_DIM + ch] = acc;
}

// ---------------- launch ----------------
#define GRID_G 296
#define GRID_F 148
#define GRID_E 148

extern "C" void kernel_launch(void* const* d_in, const int* in_sizes, int n_in,
                              void* d_out, int out_size) {
    const float* x = (const float*)d_in[0];
    const int* eidx = (const int*)d_in[1];
    const float* coord = (const float*)d_in[2];
    const float* ea = (const float*)d_in[3];
    const int* batch = (const int*)d_in[4];
    const float* emb_in_w = (const float*)d_in[5];
    const float* emb_in_b = (const float*)d_in[6];
    const float* edge_w1 = (const float*)d_in[7];
    const float* edge_b1 = (const float*)d_in[8];
    const float* edge_w2 = (const float*)d_in[9];
    const float* edge_b2 = (const float*)d_in[10];
    const float* node_w1 = (const float*)d_in[11];
    const float* node_b1 = (const float*)d_in[12];
    const float* node_w2 = (const float*)d_in[13];
    const float* node_b2 = (const float*)d_in[14];
    const float* coord_w1 = (const float*)d_in[15];
    const float* coord_b1 = (const float*)d_in[16];
    const float* coord_w2 = (const float*)d_in[17];
    const float* emb_out_w = (const float*)d_in[18];
    const float* emb_out_b = (const float*)d_in[19];
    const float* fc_w = (const float*)d_in[20];
    const float* fc_b = (const float*)d_in[21];
    float* out = (float*)d_out;

    const int* row = eidx;
    const int* col = eidx + N_EDGES;

    float *ph, *pA, *pB, *pT, *pmagg;
    cudaGetSymbolAddress((void**)&ph, d_h);
    cudaGetSymbolAddress((void**)&pA, d_A);
    cudaGetSymbolAddress((void**)&pB, d_B);
    cudaGetSymbolAddress((void**)&pT, d_T);
    cudaGetSymbolAddress((void**)&pmagg, d_magg);

    cudaFuncSetAttribute(edge_mma, cudaFuncAttributeMaxDynamicSharedMemorySize, EDGE_SMEM);
    cudaFuncSetAttribute(gemm_mma, cudaFuncAttributeMaxDynamicSharedMemorySize, GEMM_SMEM);
    cudaFuncSetAttribute(gemm_ab, cudaFuncAttributeMaxDynamicSharedMemorySize, AB_SMEM);
    cudaFuncSetAttribute(gemm_k256, cudaFuncAttributeMaxDynamicSharedMemorySize, K256_SMEM);

    // ---- pre-pass: counting sort of edges by destination row ----
    init_kernel<<<(N_NODES * HID + 255) / 256, 256>>>(coord);
    hist_kernel<<<(N_EDGES + 255) / 256, 256>>>(row);
    scan1_kernel<<<SCAN_B, 512>>>();
    scan2_kernel<<<1, 32>>>();
    scan3_kernel<<<(N_NODES + 255) / 256, 256>>>();
    scatter_kernel<<<(N_EDGES + 255) / 256, 256>>>(row, col, ea);
    emb_in_kernel<<<(N_NODES * HID + 255) / 256, 256>>>(x, emb_in_w, emb_in_b);

    for (int l = 0; l < N_LAYERS; l++) {
        const float* W1 = edge_w1 + l * 258 * HID;
        gemm_ab<<<GRID_F, 256, AB_SMEM>>>(ph, W1, W1 + 128 * HID, edge_b1 + l * HID, pA, pB);
        edge_mma<<<GRID_E, 512, EDGE_SMEM>>>(
            edge_w2 + l * HID * HID, edge_b2 + l * HID,
            coord_w1 + l * HID * HID, coord_b1 + l * HID, coord_w2 + l * HID,
            W1 + 256 * HID, W1 + 257 * HID);
        coord_kernel<<<(N_NODES + 255) / 256, 256>>>();
        gemm_k256<<<GRID_F, 256, K256_SMEM>>>(ph, pmagg, node_w1 + l * 256 * HID,
                                              node_b1 + l * HID, pT);
        gemm_mma<<<GRID_G, 256, GEMM_SMEM>>>(pT, node_w2 + l * HID * HID,
                                             node_b2 + l * HID, ph, GM_BIAS | GM_ACC);
    }

    gemm_mma<<<GRID_G, 256, GEMM_SMEM>>>(ph, emb_out_w, emb_out_b, pA, GM_BIAS);
    pool_kernel<<<(N_NODES + 511) / 512, 128>>>(batch);
    fc_kernel<<<N_GRAPHS, 256>>>(fc_w, fc_b, out);
}

// round 16
// speedup vs baseline: 2.6243x; 1.0275x over previous
#include <cuda_runtime.h>
#include <cuda_fp16.h>
#include <math.h>
#include <stdint.h>

#define N_NODES 50000
#define N_EDGES 600000
#define N_GRAPHS 64
#define HID 128
#define IN_DIM 16
#define OUT_DIM 256
#define N_LAYERS 3
#define NT_E32 18750         // 600000 / 32 exactly
#define NT_N 782             // ceil(50000/64)
#define SCAN_B 98            // ceil(50000/512)
#define HSTR 136             // half stride for K=128 fp16 tiles (272B)
#define KSTR 264             // half stride for K=256 fp16 tiles (528B)

// ---------------- device scratch ----------------
__device__ float d_h[N_NODES * HID];
__device__ float d_A[N_NODES * HID];
__device__ float d_B[N_NODES * HID];
__device__ float d_T[N_NODES * HID];
__device__ float d_magg[N_NODES * HID];
__device__ float d_cagg[N_NODES * 3];
__device__ float d_coord[N_NODES * 3];
__device__ float d_gsum[N_GRAPHS * HID];
__device__ float d_gcnt[N_GRAPHS];
// edge sort
__device__ int d_cnt[N_NODES];
__device__ int d_cur[N_NODES];
__device__ int d_base[N_NODES];
__device__ int d_bsum[SCAN_B];
__device__ int d_erow[N_EDGES];
__device__ int d_ecol[N_EDGES];
__device__ float d_eea[N_EDGES];

__device__ __forceinline__ float silu_f(float x) {
    float t;
    asm("tanh.approx.f32 %0, %1;" : "=f"(t) : "f"(x * 0.5f));
    return 0.5f * x * (1.0f + t);
}
__device__ __forceinline__ uint32_t smem_u32(const void* p) {
    uint32_t a;
    asm("{ .reg .u64 t; cvta.to.shared.u64 t, %1; cvt.u32.u64 %0, t; }" : "=r"(a) : "l"(p));
    return a;
}
__device__ __forceinline__ void ldsm_x4(uint32_t a[4], uint32_t addr) {
    asm volatile("ldmatrix.sync.aligned.m8n8.x4.shared.b16 {%0,%1,%2,%3}, [%4];"
        : "=r"(a[0]), "=r"(a[1]), "=r"(a[2]), "=r"(a[3]) : "r"(addr));
}
__device__ __forceinline__ void mma_f16(float d[4], const uint32_t a[4], const uint32_t b[2]) {
    asm volatile("mma.sync.aligned.m16n8k16.row.col.f32.f16.f16.f32 "
        "{%0,%1,%2,%3}, {%4,%5,%6,%7}, {%8,%9}, {%0,%1,%2,%3};"
        : "+f"(d[0]), "+f"(d[1]), "+f"(d[2]), "+f"(d[3])
        : "r"(a[0]), "r"(a[1]), "r"(a[2]), "r"(a[3]), "r"(b[0]), "r"(b[1]));
}
#define GBAR(id, cnt) asm volatile("bar.sync %0, %1;" :: "r"(id), "r"(cnt) : "memory")

// ---------------- init ----------------
__global__ void init_kernel(const float* __restrict__ coord_in) {
    int idx = blockIdx.x * blockDim.x + threadIdx.x;
    if (idx < N_NODES * HID) d_magg[idx] = 0.0f;
    if (idx < N_NODES * 3) { d_cagg[idx] = 0.0f; d_coord[idx] = coord_in[idx]; }
    if (idx < N_NODES) { d_cnt[idx] = 0; d_cur[idx] = 0; }
    if (idx < N_GRAPHS * HID) d_gsum[idx] = 0.0f;
    if (idx < N_GRAPHS) d_gcnt[idx] = 0.0f;
}

// ---------------- edge sort pre-pass ----------------
__global__ void hist_kernel(const int* __restrict__ row) {
    int e = blockIdx.x * blockDim.x + threadIdx.x;
    if (e < N_EDGES) atomicAdd(&d_cnt[row[e]], 1);
}
__global__ void scan1_kernel() {
    __shared__ int s[512];
    int tid = threadIdx.x;
    int i = blockIdx.x * 512 + tid;
    int v = (i < N_NODES) ? d_cnt[i] : 0;
    s[tid] = v;
    __syncthreads();
    for (int off = 1; off < 512; off <<= 1) {
        int t = (tid >= off) ? s[tid - off] : 0;
        __syncthreads();
        s[tid] += t;
        __syncthreads();
    }
    if (i < N_NODES) d_base[i] = s[tid] - v;
    if (tid == 511) d_bsum[blockIdx.x] = s[511];
}
__global__ void scan2_kernel() {
    if (threadIdx.x == 0) {
        int acc = 0;
        for (int b = 0; b < SCAN_B; b++) { int t = d_bsum[b]; d_bsum[b] = acc; acc += t; }
    }
}
__global__ void scan3_kernel() {
    int i = blockIdx.x * blockDim.x + threadIdx.x;
    if (i < N_NODES) d_base[i] += d_bsum[i >> 9];
}
__global__ void scatter_kernel(const int* __restrict__ row, const int* __restrict__ col,
                               const float* __restrict__ ea) {
    int e = blockIdx.x * blockDim.x + threadIdx.x;
    if (e < N_EDGES) {
        int r = row[e];
        int p = d_base[r] + atomicAdd(&d_cur[r], 1);
        d_erow[p] = r;
        d_ecol[p] = col[e];
        d_eea[p] = ea[e];
    }
}

__global__ void emb_in_kernel(const float* __restrict__ x,
                              const float* __restrict__ w,
                              const float* __restrict__ b) {
    int idx = blockIdx.x * blockDim.x + threadIdx.x;
    if (idx >= N_NODES * HID) return;
    int n = idx >> 7, ch = idx & 127;
    float acc = b[ch];
#pragma unroll
    for (int k = 0; k < IN_DIM; k++) acc += x[n * IN_DIM + k] * w[k * HID + ch];
    d_h[idx] = acc;
}

// store W[k][c] (row-major 128x128) transposed+fp16 into Wh[c][k] (HSTR halves stride)
__device__ __forceinline__ void load_w_trans_h(const float* __restrict__ W, __half* __restrict__ Wh,
                                               int tid, int nthreads) {
    for (int idx = tid; idx < 4096; idx += nthreads) {
        int k = idx >> 5, c0 = (idx & 31) * 4;
        float4 v = reinterpret_cast<const float4*>(W)[idx];
        Wh[(c0 + 0) * HSTR + k] = __float2half_rn(v.x);
        Wh[(c0 + 1) * HSTR + k] = __float2half_rn(v.y);
        Wh[(c0 + 2) * HSTR + k] = __float2half_rn(v.z);
        Wh[(c0 + 3) * HSTR + k] = __float2half_rn(v.w);
    }
}
__device__ __forceinline__ uint2 f4_to_h4(float4 v) {
    __half2 h01 = __floats2half2_rn(v.x, v.y);
    __half2 h23 = __floats2half2_rn(v.z, v.w);
    uint2 u;
    u.x = *reinterpret_cast<uint32_t*>(&h01);
    u.y = *reinterpret_cast<uint32_t*>(&h23);
    return u;
}

// ---------------- gemm_mma (fp16): Y = op(X@W (+bias) (+Y)) ----------------
// smem floats: Wh@0 (8704), Xs@8704 (4352), bs@13056 -> 13184 floats
#define GEMM_SMEM (13184 * 4)
#define GM_BIAS 1
#define GM_ACC 2
#define GM_SILU 4

__global__ void __launch_bounds__(256, 2)
gemm_mma(const float* __restrict__ X, const float* __restrict__ W,
         const float* __restrict__ bias, float* __restrict__ Y, int mode) {
    extern __shared__ float sm[];
    __half* Wh = reinterpret_cast<__half*>(sm);
    __half* Xh = reinterpret_cast<__half*>(sm + 8704);
    float* bs = sm + 13056;
    int tid = threadIdx.x;

    load_w_trans_h(W, Wh, tid, 256);
    if (tid < 128) bs[tid] = (mode & GM_BIAS) ? bias[tid] : 0.0f;
    __syncthreads();

    uint32_t XA = smem_u32(Xh), WA = smem_u32(Wh);
    int L = tid & 31, w = tid >> 5;
    int mw = w & 1, nwg = w >> 1;
    uint32_t aBase0 = XA + (uint32_t)(mw * 32 + (L & 15)) * (HSTR * 2) + (uint32_t)(L >> 4) * 16;
    uint32_t bOffH[2];
#pragma unroll
    for (int jp = 0; jp < 2; jp++)
        bOffH[jp] = WA + (uint32_t)(nwg * 32 + jp * 16 + (L >> 4) * 8 + (L & 7)) * (HSTR * 2)
                  + (uint32_t)((L >> 3) & 1) * 16;

    for (int tile = blockIdx.x; tile < NT_N; tile += gridDim.x) {
        int r0 = tile * 64;
        for (int idx = tid; idx < 2048; idx += 256) {
            int r = idx >> 5, k4 = (idx & 31) * 4;
            int gr = r0 + r;
            float4 v = make_float4(0.f, 0.f, 0.f, 0.f);
            if (gr < N_NODES) v = *reinterpret_cast<const float4*>(&X[gr * HID + k4]);
            *reinterpret_cast<uint2*>(&Xh[r * HSTR + k4]) = f4_to_h4(v);
        }
        __syncthreads();

        float acc[2][4][4];
#pragma unroll
        for (int i = 0; i < 2; i++)
#pragma unroll
            for (int j = 0; j < 4; j++)
#pragma unroll
                for (int e = 0; e < 4; e++) acc[i][j][e] = 0.0f;

#pragma unroll
        for (int kc = 0; kc < 8; kc++) {
            uint32_t a0[4], a1[4];
            ldsm_x4(a0, aBase0 + kc * 32);
            ldsm_x4(a1, aBase0 + 16 * (HSTR * 2) + kc * 32);
#pragma unroll
            for (int jp = 0; jp < 2; jp++) {
                uint32_t b4[4];
                ldsm_x4(b4, bOffH[jp] + kc * 32);
                mma_f16(acc[0][jp * 2 + 0], a0, b4 + 0);
                mma_f16(acc[1][jp * 2 + 0], a1, b4 + 0);
                mma_f16(acc[0][jp * 2 + 1], a0, b4 + 2);
                mma_f16(acc[1][jp * 2 + 1], a1, b4 + 2);
            }
        }

#pragma unroll
        for (int i = 0; i < 2; i++) {
#pragma unroll
            for (int half = 0; half < 2; half++) {
                int gr = r0 + mw * 32 + i * 16 + half * 8 + (L >> 2);
                if (gr < N_NODES) {
#pragma unroll
                    for (int j = 0; j < 4; j++) {
                        int c = nwg * 32 + j * 8 + (L & 3) * 2;
                        float2 res;
                        res.x = acc[i][j][half * 2 + 0] + bs[c];
                        res.y = acc[i][j][half * 2 + 1] + bs[c + 1];
                        float* yp = &Y[gr * HID + c];
                        if (mode & GM_ACC) {
                            float2 o = *reinterpret_cast<float2*>(yp);
                            res.x += o.x; res.y += o.y;
                        }
                        if (mode & GM_SILU) { res.x = silu_f(res.x); res.y = silu_f(res.y); }
                        *reinterpret_cast<float2*>(yp) = res;
                    }
                }
            }
        }
        __syncthreads();
    }
}

// ---------------- gemm_ab (fp16): Y1 = X@Wa + b, Y2 = X@Wb ----------------
// smem floats: Wh@0 (17408: 256 rows), Xs@17408 (4352), bs@21760 -> 21888 floats
#define AB_SMEM (21888 * 4)

__global__ void __launch_bounds__(256, 2)
gemm_ab(const float* __restrict__ X, const float* __restrict__ Wa, const float* __restrict__ Wb,
        const float* __restrict__ bias, float* __restrict__ Y1, float* __restrict__ Y2) {
    extern __shared__ float sm[];
    __half* Wh = reinterpret_cast<__half*>(sm);
    __half* Xh = reinterpret_cast<__half*>(sm + 17408);
    float* bs = sm + 21760;
    int tid = threadIdx.x;

    load_w_trans_h(Wa, Wh, tid, 256);
    load_w_trans_h(Wb, Wh + 128 * HSTR, tid, 256);
    if (tid < 128) bs[tid] = bias[tid];
    __syncthreads();

    uint32_t XA = smem_u32(Xh), WA = smem_u32(Wh);
    int L = tid & 31, w = tid >> 5;
    int mw = w & 1, nwg = w >> 1;
    uint32_t aBase0 = XA + (uint32_t)(mw * 32 + (L & 15)) * (HSTR * 2) + (uint32_t)(L >> 4) * 16;
    uint32_t bOffH[4];
#pragma unroll
    for (int jp = 0; jp < 4; jp++) {
        int base = (jp < 2) ? (nwg * 32 + jp * 16) : (128 + nwg * 32 + (jp - 2) * 16);
        bOffH[jp] = WA + (uint32_t)(base + (L >> 4) * 8 + (L & 7)) * (HSTR * 2)
                  + (uint32_t)((L >> 3) & 1) * 16;
    }

    for (int tile = blockIdx.x; tile < NT_N; tile += gridDim.x) {
        int r0 = tile * 64;
        for (int idx = tid; idx < 2048; idx += 256) {
            int r = idx >> 5, k4 = (idx & 31) * 4;
            int gr = r0 + r;
            float4 v = make_float4(0.f, 0.f, 0.f, 0.f);
            if (gr < N_NODES) v = *reinterpret_cast<const float4*>(&X[gr * HID + k4]);
            *reinterpret_cast<uint2*>(&Xh[r * HSTR + k4]) = f4_to_h4(v);
        }
        __syncthreads();

        float acc[2][8][4];
#pragma unroll
        for (int i = 0; i < 2; i++)
#pragma unroll
            for (int j = 0; j < 8; j++)
#pragma unroll
                for (int e = 0; e < 4; e++) acc[i][j][e] = 0.0f;

#pragma unroll
        for (int kc = 0; kc < 8; kc++) {
            uint32_t a0[4], a1[4];
            ldsm_x4(a0, aBase0 + kc * 32);
            ldsm_x4(a1, aBase0 + 16 * (HSTR * 2) + kc * 32);
#pragma unroll
            for (int jp = 0; jp < 4; jp++) {
                uint32_t b4[4];
                ldsm_x4(b4, bOffH[jp] + kc * 32);
                mma_f16(acc[0][jp * 2 + 0], a0, b4 + 0);
                mma_f16(acc[1][jp * 2 + 0], a1, b4 + 0);
                mma_f16(acc[0][jp * 2 + 1], a0, b4 + 2);
                mma_f16(acc[1][jp * 2 + 1], a1, b4 + 2);
            }
        }

#pragma unroll
        for (int i = 0; i < 2; i++) {
#pragma unroll
            for (int half = 0; half < 2; half++) {
                int gr = r0 + mw * 32 + i * 16 + half * 8 + (L >> 2);
                if (gr < N_NODES) {
#pragma unroll
                    for (int j = 0; j < 8; j++) {
                        int c = nwg * 32 + (j & 3) * 8 + (L & 3) * 2;
                        float2 res;
                        res.x = acc[i][j][half * 2 + 0];
                        res.y = acc[i][j][half * 2 + 1];
                        if (j < 4) {
                            res.x += bs[c]; res.y += bs[c + 1];
                            *reinterpret_cast<float2*>(&Y1[gr * HID + c]) = res;
                        } else {
                            *reinterpret_cast<float2*>(&Y2[gr * HID + c]) = res;
                        }
                    }
                }
            }
        }
        __syncthreads();
    }
}

// ---------------- gemm_k256 (fp16): Y = silu([X1, X2]@W + b), clears X2 ----------------
// smem floats: Wh@0 (16896: 128 x KSTR halves), Xs@16896 (8448), bs@25344 -> 25472 floats
#define K256_SMEM (25472 * 4)

__global__ void __launch_bounds__(256, 2)
gemm_k256(const float* __restrict__ X1, float* __restrict__ X2,
          const float* __restrict__ W, const float* __restrict__ bias, float* __restrict__ Y) {
    extern __shared__ float sm[];
    __half* Wh = reinterpret_cast<__half*>(sm);
    __half* Xh = reinterpret_cast<__half*>(sm + 16896);
    float* bs = sm + 25344;
    int tid = threadIdx.x;

    // W is [256 k][128 c]; transpose to Wh[c][k] stride KSTR
    for (int idx = tid; idx < 8192; idx += 256) {
        int k = idx >> 5, c0 = (idx & 31) * 4;
        float4 v = reinterpret_cast<const float4*>(W)[idx];
        Wh[(c0 + 0) * KSTR + k] = __float2half_rn(v.x);
        Wh[(c0 + 1) * KSTR + k] = __float2half_rn(v.y);
        Wh[(c0 + 2) * KSTR + k] = __float2half_rn(v.z);
        Wh[(c0 + 3) * KSTR + k] = __float2half_rn(v.w);
    }
    if (tid < 128) bs[tid] = bias[tid];
    __syncthreads();

    uint32_t XA = smem_u32(Xh), WA = smem_u32(Wh);
    int L = tid & 31, w = tid >> 5;
    int mw = w & 1, nwg = w >> 1;
    uint32_t aBase0 = XA + (uint32_t)(mw * 32 + (L & 15)) * (KSTR * 2) + (uint32_t)(L >> 4) * 16;
    uint32_t bOffH[2];
#pragma unroll
    for (int jp = 0; jp < 2; jp++)
        bOffH[jp] = WA + (uint32_t)(nwg * 32 + jp * 16 + (L >> 4) * 8 + (L & 7)) * (KSTR * 2)
                  + (uint32_t)((L >> 3) & 1) * 16;

    for (int tile = blockIdx.x; tile < NT_N; tile += gridDim.x) {
        int r0 = tile * 64;
        for (int idx = tid; idx < 2048; idx += 256) {
            int r = idx >> 5, k4 = (idx & 31) * 4;
            int gr = r0 + r;
            float4 v1 = make_float4(0.f, 0.f, 0.f, 0.f);
            float4 v2 = make_float4(0.f, 0.f, 0.f, 0.f);
            if (gr < N_NODES) {
                v1 = *reinterpret_cast<const float4*>(&X1[gr * HID + k4]);
                v2 = *reinterpret_cast<float4*>(&X2[gr * HID + k4]);
                *reinterpret_cast<float4*>(&X2[gr * HID + k4]) = make_float4(0.f, 0.f, 0.f, 0.f);
            }
            *reinterpret_cast<uint2*>(&Xh[r * KSTR + k4]) = f4_to_h4(v1);
            *reinterpret_cast<uint2*>(&Xh[r * KSTR + 128 + k4]) = f4_to_h4(v2);
        }
        __syncthreads();

        float acc[2][4][4];
#pragma unroll
        for (int i = 0; i < 2; i++)
#pragma unroll
            for (int j = 0; j < 4; j++)
#pragma unroll
                for (int e = 0; e < 4; e++) acc[i][j][e] = 0.0f;

#pragma unroll
        for (int kc = 0; kc < 16; kc++) {
            uint32_t a0[4], a1[4];
            ldsm_x4(a0, aBase0 + kc * 32);
            ldsm_x4(a1, aBase0 + 16 * (KSTR * 2) + kc * 32);
#pragma unroll
            for (int jp = 0; jp < 2; jp++) {
                uint32_t b4[4];
                ldsm_x4(b4, bOffH[jp] + kc * 32);
                mma_f16(acc[0][jp * 2 + 0], a0, b4 + 0);
                mma_f16(acc[1][jp * 2 + 0], a1, b4 + 0);
                mma_f16(acc[0][jp * 2 + 1], a0, b4 + 2);
                mma_f16(acc[1][jp * 2 + 1], a1, b4 + 2);
            }
        }

#pragma unroll
        for (int i = 0; i < 2; i++) {
#pragma unroll
            for (int half = 0; half < 2; half++) {
                int gr = r0 + mw * 32 + i * 16 + half * 8 + (L >> 2);
                if (gr < N_NODES) {
#pragma unroll
                    for (int j = 0; j < 4; j++) {
                        int c = nwg * 32 + j * 8 + (L & 3) * 2;
                        float2 res;
                        res.x = silu_f(acc[i][j][half * 2 + 0] + bs[c]);
                        res.y = silu_f(acc[i][j][half * 2 + 1] + bs[c + 1]);
                        *reinterpret_cast<float2*>(&Y[gr * HID + c]) = res;
                    }
                }
            }
        }
        __syncthreads();
    }
}

// ---------------- edge kernel: fp16 MMA, 4 x 128-thread groups ----------------
#define EDGE_SMEM (27776 * 4)

__global__ void __launch_bounds__(512, 1)
edge_mma(const float* __restrict__ W2, const float* __restrict__ b2,
         const float* __restrict__ Wc1, const float* __restrict__ bc1,
         const float* __restrict__ wc2,
         const float* __restrict__ wr, const float* __restrict__ we) {
    extern __shared__ float sm[];
    __half* W2h = reinterpret_cast<__half*>(sm);
    __half* Wc1h = reinterpret_cast<__half*>(sm + 8704);
    float* b2s = sm + 26112;
    float* bc1s = sm + 26240;
    float* wc2s = sm + 26368;
    float* wrs = sm + 26496;
    float* wes = sm + 26624;

    int tid = threadIdx.x;
    load_w_trans_h(W2, W2h, tid, 512);
    load_w_trans_h(Wc1, Wc1h, tid, 512);
    if (tid < 128) {
        b2s[tid] = b2[tid]; bc1s[tid] = bc1[tid]; wc2s[tid] = wc2[tid];
        wrs[tid] = wr[tid]; wes[tid] = we[tid];
    }
    __syncthreads();

    int g = tid >> 7;
    int gtid = tid & 127;
    int barid = 1 + g;

    __half* tSh = reinterpret_cast<__half*>(sm + 17408) + g * (32 * HSTR);
    float* diffs = sm + 26752 + g * 96;
    float* cw_part = sm + 27136 + g * 128;
    int* rows_s = (int*)(sm + 27648) + g * 32;

    uint32_t tSA = smem_u32(tSh);
    uint32_t W2A = smem_u32(W2h), Wc1A = smem_u32(Wc1h);
    int L = gtid & 31, w = gtid >> 5;
    int nwg = w;
    uint32_t aOffH = (uint32_t)(L & 15) * (HSTR * 2) + (uint32_t)(L >> 4) * 16;
    uint32_t bOffH[2];
#pragma unroll
    for (int jp = 0; jp < 2; jp++)
        bOffH[jp] = (uint32_t)((nwg * 32 + jp * 16 + (L >> 4) * 8 + (L & 7))) * (HSTR * 2)
                  + (uint32_t)((L >> 3) & 1) * 16;

    int e_loc = gtid >> 2, q = gtid & 3;

    for (int tile = blockIdx.x * 4 + g; tile < NT_E32; tile += gridDim.x * 4) {
        int e0 = tile * 32;
        {
            int e = e0 + e_loc;
            int r = d_erow[e], c = d_ecol[e];
            float dx = d_coord[r * 3 + 0] - d_coord[c * 3 + 0];
            float dy = d_coord[r * 3 + 1] - d_coord[c * 3 + 1];
            float dz = d_coord[r * 3 + 2] - d_coord[c * 3 + 2];
            float radial = dx * dx + dy * dy + dz * dz;
            float eav = d_eea[e];
            if (q == 0) {
                rows_s[e_loc] = r;
                diffs[e_loc * 3 + 0] = dx; diffs[e_loc * 3 + 1] = dy; diffs[e_loc * 3 + 2] = dz;
            }
#pragma unroll
            for (int jj = 0; jj < 8; jj++) {
                int ch = jj * 16 + q * 4;
                float4 av = *reinterpret_cast<const float4*>(&d_A[r * HID + ch]);
                float4 bv = *reinterpret_cast<const float4*>(&d_B[c * HID + ch]);
                float4 w1 = *reinterpret_cast<const float4*>(&wrs[ch]);
                float4 w2v = *reinterpret_cast<const float4*>(&wes[ch]);
                float4 t;
                t.x = silu_f(av.x + bv.x + radial * w1.x + eav * w2v.x);
                t.y = silu_f(av.y + bv.y + radial * w1.y + eav * w2v.y);
                t.z = silu_f(av.z + bv.z + radial * w1.z + eav * w2v.z);
                t.w = silu_f(av.w + bv.w + radial * w1.w + eav * w2v.w);
                *reinterpret_cast<uint2*>(&tSh[e_loc * HSTR + ch]) = f4_to_h4(t);
            }
        }
        GBAR(barid, 128);

        // ---- MMA1 ----
        float acc[2][4][4];
#pragma unroll
        for (int i = 0; i < 2; i++)
#pragma unroll
            for (int j = 0; j < 4; j++)
#pragma unroll
                for (int e = 0; e < 4; e++) acc[i][j][e] = 0.0f;
#pragma unroll
        for (int kc = 0; kc < 8; kc++) {
            uint32_t a0[4], a1[4];
            ldsm_x4(a0, tSA + aOffH + kc * 32);
            ldsm_x4(a1, tSA + aOffH + 16 * (HSTR * 2) + kc * 32);
#pragma unroll
            for (int jp = 0; jp < 2; jp++) {
                uint32_t b4[4];
                ldsm_x4(b4, W2A + bOffH[jp] + kc * 32);
                mma_f16(acc[0][jp * 2 + 0], a0, b4 + 0);
                mma_f16(acc[1][jp * 2 + 0], a1, b4 + 0);
                mma_f16(acc[0][jp * 2 + 1], a0, b4 + 2);
                mma_f16(acc[1][jp * 2 + 1], a1, b4 + 2);
            }
        }

        // ---- epilogue1 ----
#pragma unroll
        for (int i = 0; i < 2; i++) {
#pragma unroll
            for (int half = 0; half < 2; half++) {
                int rowl = i * 16 + half * 8 + (L >> 2);
#pragma unroll
                for (int j = 0; j < 4; j++) {
                    int c = nwg * 32 + j * 8 + (L & 3) * 2;
                    __half2 mh = __floats2half2_rn(
                        silu_f(acc[i][j][half * 2 + 0] + b2s[c]),
                        silu_f(acc[i][j][half * 2 + 1] + b2s[c + 1]));
                    *reinterpret_cast<__half2*>(&tSh[rowl * HSTR + c]) = mh;
                }
            }
        }
        GBAR(barid, 128);

        // ---- segmented magg scatter ----
        {
            int ch = gtid;
            float accm = 0.0f;
            int prev = rows_s[0];
#pragma unroll 4
            for (int el = 0; el < 32; el++) {
                int rn = rows_s[el];
                float mv = __half2float(tSh[el * HSTR + ch]);
                if (rn != prev) {
                    atomicAdd(&d_magg[prev * HID + ch], accm);
                    accm = 0.0f;
                    prev = rn;
                }
                accm += mv;
            }
            atomicAdd(&d_magg[prev * HID + ch], accm);
        }

        // ---- MMA2 ----
#pragma unroll
        for (int i = 0; i < 2; i++)
#pragma unroll
            for (int j = 0; j < 4; j++)
#pragma unroll
                for (int e = 0; e < 4; e++) acc[i][j][e] = 0.0f;
#pragma unroll
        for (int kc = 0; kc < 8; kc++) {
            uint32_t a0[4], a1[4];
            ldsm_x4(a0, tSA + aOffH + kc * 32);
            ldsm_x4(a1, tSA + aOffH + 16 * (HSTR * 2) + kc * 32);
#pragma unroll
            for (int jp = 0; jp < 2; jp++) {
                uint32_t b4[4];
                ldsm_x4(b4, Wc1A + bOffH[jp] + kc * 32);
                mma_f16(acc[0][jp * 2 + 0], a0, b4 + 0);
                mma_f16(acc[1][jp * 2 + 0], a1, b4 + 0);
                mma_f16(acc[0][jp * 2 + 1], a0, b4 + 2);
                mma_f16(acc[1][jp * 2 + 1], a1, b4 + 2);
            }
        }

        // ---- epilogue2 ----
#pragma unroll
        for (int i = 0; i < 2; i++) {
#pragma unroll
            for (int half = 0; half < 2; half++) {
                float p = 0.0f;
#pragma unroll
                for (int j = 0; j < 4; j++) {
                    int c = nwg * 32 + j * 8 + (L & 3) * 2;
                    p += silu_f(acc[i][j][half * 2 + 0] + bc1s[c]) * wc2s[c];
                    p += silu_f(acc[i][j][half * 2 + 1] + bc1s[c + 1]) * wc2s[c + 1];
                }
                p += __shfl_xor_sync(0xffffffff, p, 1);
                p += __shfl_xor_sync(0xffffffff, p, 2);
                if ((L & 3) == 0) {
                    int rowl = i * 16 + half * 8 + (L >> 2);
                    cw_part[nwg * 32 + rowl] = p;
                }
            }
        }
        GBAR(barid, 128);
        if (gtid < 32) {
            int rn = rows_s[gtid];
            float cw = cw_part[gtid] + cw_part[32 + gtid] + cw_part[64 + gtid] + cw_part[96 + gtid];
            atomicAdd(&d_cagg[rn * 3 + 0], diffs[gtid * 3 + 0] * cw);
            atomicAdd(&d_cagg[rn * 3 + 1], diffs[gtid * 3 + 1] * cw);
            atomicAdd(&d_cagg[rn * 3 + 2], diffs[gtid * 3 + 2] * cw);
        }
        GBAR(barid, 128);
    }
}

// ---------------- coord update ----------------
__global__ void coord_kernel() {
    int n = blockIdx.x * blockDim.x + threadIdx.x;
    if (n < N_NODES) {
        float inv = 1.0f / fmaxf((float)d_cnt[n], 1.0f);
#pragma unroll
        for (int dd = 0; dd < 3; dd++) {
            d_coord[n * 3 + dd] += d_cagg[n * 3 + dd] * inv;
            d_cagg[n * 3 + dd] = 0.0f;
        }
    }
}

// ---------------- global mean pool ----------------
__global__ void pool_kernel(const int* __restrict__ batch) {
    int n0 = blockIdx.x * 512;
    int ch = threadIdx.x;
    if (n0 >= N_NODES) return;
    int nend = min(n0 + 512, N_NODES);
    int cur = batch[n0];
    float acc = 0.0f, cnt = 0.0f;
    for (int n = n0; n < nend; n++) {
        int g = batch[n];
        if (g != cur) {
            atomicAdd(&d_gsum[cur * HID + ch], acc);
            if (ch == 0) atomicAdd(&d_gcnt[cur], cnt);
            acc = 0.0f; cnt = 0.0f; cur = g;
        }
        acc += d_A[n * HID + ch];
        cnt += 1.0f;
    }
    atomicAdd(&d_gsum[cur * HID + ch], acc);
    if (ch == 0) atomicAdd(&d_gcnt[cur], cnt);
}

// ---------------- final fc ----------------
__global__ void fc_kernel(const float* __restrict__ fcw, const float* __restrict__ fcb,
                          float* __restrict__ out) {
    int g = blockIdx.x;
    int ch = threadIdx.x;
    float inv = 1.0f / fmaxf(d_gcnt[g], 1.0f);
    float acc = fcb[ch];
    for (int k = 0; k < HID; k++)
        acc += d_gsum[g * HID + k] * inv * fcw[k * OUT_DIM + ch];
    out[g * OUT_DIM + ch] = acc;
}

// ---------------- launch ----------------
#define GRID_G 296
#define GRID_E 148

extern "C" void kernel_launch(void* const* d_in, const int* in_sizes, int n_in,
                              void* d_out, int out_size) {
    const float* x = (const float*)d_in[0];
    const int* eidx = (const int*)d_in[1];
    const float* coord = (const float*)d_in[2];
    const float* ea = (const float*)d_in[3];
    const int* batch = (const int*)d_in[4];
    const float* emb_in_w = (const float*)d_in[5];
    const float* emb_in_b = (const float*)d_in[6];
    const float* edge_w1 = (const float*)d_in[7];
    const float* edge_b1 = (const float*)d_in[8];
    const float* edge_w2 = (const float*)d_in[9];
    const float* edge_b2 = (const float*)d_in[10];
    const float* node_w1 = (const float*)d_in[11];
    const float* node_b1 = (const float*)d_in[12];
    const float* node_w2 = (const float*)d_in[13];
    const float* node_b2 = (const float*)d_in[14];
    const float* coord_w1 = (const float*)d_in[15];
    const float* coord_b1 = (const float*)d_in[16];
    const float* coord_w2 = (const float*)d_in[17];
    const float* emb_out_w = (const float*)d_in[18];
    const float* emb_out_b = (const float*)d_in[19];
    const float* fc_w = (const float*)d_in[20];
    const float* fc_b = (const float*)d_in[21];
    float* out = (float*)d_out;

    const int* row = eidx;
    const int* col = eidx + N_EDGES;

    float *ph, *pA, *pB, *pT, *pmagg;
    cudaGetSymbolAddress((void**)&ph, d_h);
    cudaGetSymbolAddress((void**)&pA, d_A);
    cudaGetSymbolAddress((void**)&pB, d_B);
    cudaGetSymbolAddress((void**)&pT, d_T);
    cudaGetSymbolAddress((void**)&pmagg, d_magg);

    cudaFuncSetAttribute(edge_mma, cudaFuncAttributeMaxDynamicSharedMemorySize, EDGE_SMEM);
    cudaFuncSetAttribute(gemm_mma, cudaFuncAttributeMaxDynamicSharedMemorySize, GEMM_SMEM);
    cudaFuncSetAttribute(gemm_ab, cudaFuncAttributeMaxDynamicSharedMemorySize, AB_SMEM);
    cudaFuncSetAttribute(gemm_k256, cudaFuncAttributeMaxDynamicSharedMemorySize, K256_SMEM);

    // ---- pre-pass: counting sort of edges by destination row ----
    init_kernel<<<(N_NODES * HID + 255) / 256, 256>>>(coord);
    hist_kernel<<<(N_EDGES + 255) / 256, 256>>>(row);
    scan1_kernel<<<SCAN_B, 512>>>();
    scan2_kernel<<<1, 32>>>();
    scan3_kernel<<<(N_NODES + 255) / 256, 256>>>();
    scatter_kernel<<<(N_EDGES + 255) / 256, 256>>>(row, col, ea);
    emb_in_kernel<<<(N_NODES * HID + 255) / 256, 256>>>(x, emb_in_w, emb_in_b);

    for (int l = 0; l < N_LAYERS; l++) {
        const float* W1 = edge_w1 + l * 258 * HID;
        gemm_ab<<<GRID_G, 256, AB_SMEM>>>(ph, W1, W1 + 128 * HID, edge_b1 + l * HID, pA, pB);
        edge_mma<<<GRID_E, 512, EDGE_SMEM>>>(
            edge_w2 + l * HID * HID, edge_b2 + l * HID,
            coord_w1 + l * HID * HID, coord_b1 + l * HID, coord_w2 + l * HID,
            W1 + 256 * HID, W1 + 257 * HID);
        coord_kernel<<<(N_NODES + 255) / 256, 256>>>();
        gemm_k256<<<GRID_G, 256, K256_SMEM>>>(ph, pmagg, node_w1 + l * 256 * HID,
                                              node_b1 + l * HID, pT);
        gemm_mma<<<GRID_G, 256, GEMM_SMEM>>>(pT, node_w2 + l * HID * HID,
                                             node_b2 + l * HID, ph, GM_BIAS | GM_ACC);
    }

    gemm_mma<<<GRID_G, 256, GEMM_SMEM>>>(ph, emb_out_w, emb_out_b, pA, GM_BIAS);
    pool_kernel<<<(N_NODES + 511) / 512, 128>>>(batch);
    fc_kernel<<<N_GRAPHS, 256>>>(fc_w, fc_b, out);
}

// round 17
// speedup vs baseline: 2.8279x; 1.0776x over previous
#include <cuda_runtime.h>
#include <cuda_fp16.h>
#include <math.h>
#include <stdint.h>

#define N_NODES 50000
#define N_EDGES 600000
#define N_GRAPHS 64
#define HID 128
#define IN_DIM 16
#define OUT_DIM 256
#define N_LAYERS 3
#define NT_E32 18750         // 600000 / 32 exactly
#define NT_N 782             // ceil(50000/64)
#define SCAN_B 98            // ceil(50000/512)
#define HSTR 136             // half stride for K=128 fp16 tiles (272B)
#define KSTR 264             // half stride for K=256 fp16 tiles (528B)

// ---------------- device scratch ----------------
__device__ float d_h[N_NODES * HID];
__device__ __half d_Ah[N_NODES * HID];
__device__ __half d_Bh[N_NODES * HID];
__device__ __half d_Th[N_NODES * HID];
__device__ float d_magg[N_NODES * HID];   // also reused as emb_out fp32 result
__device__ float d_cagg[N_NODES * 3];
__device__ float d_coord[N_NODES * 3];
__device__ float d_gsum[N_GRAPHS * HID];
__device__ float d_gcnt[N_GRAPHS];
// edge sort
__device__ int d_cnt[N_NODES];
__device__ int d_cur[N_NODES];
__device__ int d_base[N_NODES];
__device__ int d_bsum[SCAN_B];
__device__ int d_erow[N_EDGES];
__device__ int d_ecol[N_EDGES];
__device__ float d_eea[N_EDGES];

__device__ __forceinline__ float silu_f(float x) {
    float t;
    asm("tanh.approx.f32 %0, %1;" : "=f"(t) : "f"(x * 0.5f));
    return 0.5f * x * (1.0f + t);
}
__device__ __forceinline__ uint32_t smem_u32(const void* p) {
    uint32_t a;
    asm("{ .reg .u64 t; cvta.to.shared.u64 t, %1; cvt.u32.u64 %0, t; }" : "=r"(a) : "l"(p));
    return a;
}
__device__ __forceinline__ void ldsm_x4(uint32_t a[4], uint32_t addr) {
    asm volatile("ldmatrix.sync.aligned.m8n8.x4.shared.b16 {%0,%1,%2,%3}, [%4];"
        : "=r"(a[0]), "=r"(a[1]), "=r"(a[2]), "=r"(a[3]) : "r"(addr));
}
__device__ __forceinline__ void mma_f16(float d[4], const uint32_t a[4], const uint32_t b[2]) {
    asm volatile("mma.sync.aligned.m16n8k16.row.col.f32.f16.f16.f32 "
        "{%0,%1,%2,%3}, {%4,%5,%6,%7}, {%8,%9}, {%0,%1,%2,%3};"
        : "+f"(d[0]), "+f"(d[1]), "+f"(d[2]), "+f"(d[3])
        : "r"(a[0]), "r"(a[1]), "r"(a[2]), "r"(a[3]), "r"(b[0]), "r"(b[1]));
}
#define GBAR(id, cnt) asm volatile("bar.sync %0, %1;" :: "r"(id), "r"(cnt) : "memory")

// ---------------- init ----------------
__global__ void init_kernel(const float* __restrict__ coord_in) {
    int idx = blockIdx.x * blockDim.x + threadIdx.x;
    if (idx < N_NODES * HID) d_magg[idx] = 0.0f;
    if (idx < N_NODES * 3) { d_cagg[idx] = 0.0f; d_coord[idx] = coord_in[idx]; }
    if (idx < N_NODES) { d_cnt[idx] = 0; d_cur[idx] = 0; }
    if (idx < N_GRAPHS * HID) d_gsum[idx] = 0.0f;
    if (idx < N_GRAPHS) d_gcnt[idx] = 0.0f;
}

// ---------------- edge sort pre-pass ----------------
__global__ void hist_kernel(const int* __restrict__ row) {
    int e = blockIdx.x * blockDim.x + threadIdx.x;
    if (e < N_EDGES) atomicAdd(&d_cnt[row[e]], 1);
}
__global__ void scan1_kernel() {
    __shared__ int s[512];
    int tid = threadIdx.x;
    int i = blockIdx.x * 512 + tid;
    int v = (i < N_NODES) ? d_cnt[i] : 0;
    s[tid] = v;
    __syncthreads();
    for (int off = 1; off < 512; off <<= 1) {
        int t = (tid >= off) ? s[tid - off] : 0;
        __syncthreads();
        s[tid] += t;
        __syncthreads();
    }
    if (i < N_NODES) d_base[i] = s[tid] - v;
    if (tid == 511) d_bsum[blockIdx.x] = s[511];
}
__global__ void scan2_kernel() {
    if (threadIdx.x == 0) {
        int acc = 0;
        for (int b = 0; b < SCAN_B; b++) { int t = d_bsum[b]; d_bsum[b] = acc; acc += t; }
    }
}
__global__ void scan3_kernel() {
    int i = blockIdx.x * blockDim.x + threadIdx.x;
    if (i < N_NODES) d_base[i] += d_bsum[i >> 9];
}
__global__ void scatter_kernel(const int* __restrict__ row, const int* __restrict__ col,
                               const float* __restrict__ ea) {
    int e = blockIdx.x * blockDim.x + threadIdx.x;
    if (e < N_EDGES) {
        int r = row[e];
        int p = d_base[r] + atomicAdd(&d_cur[r], 1);
        d_erow[p] = r;
        d_ecol[p] = col[e];
        d_eea[p] = ea[e];
    }
}

__global__ void emb_in_kernel(const float* __restrict__ x,
                              const float* __restrict__ w,
                              const float* __restrict__ b) {
    int idx = blockIdx.x * blockDim.x + threadIdx.x;
    if (idx >= N_NODES * HID) return;
    int n = idx >> 7, ch = idx & 127;
    float acc = b[ch];
#pragma unroll
    for (int k = 0; k < IN_DIM; k++) acc += x[n * IN_DIM + k] * w[k * HID + ch];
    d_h[idx] = acc;
}

// store W[k][c] (row-major 128x128) transposed+fp16 into Wh[c][k] (HSTR halves stride)
__device__ __forceinline__ void load_w_trans_h(const float* __restrict__ W, __half* __restrict__ Wh,
                                               int tid, int nthreads) {
    for (int idx = tid; idx < 4096; idx += nthreads) {
        int k = idx >> 5, c0 = (idx & 31) * 4;
        float4 v = reinterpret_cast<const float4*>(W)[idx];
        Wh[(c0 + 0) * HSTR + k] = __float2half_rn(v.x);
        Wh[(c0 + 1) * HSTR + k] = __float2half_rn(v.y);
        Wh[(c0 + 2) * HSTR + k] = __float2half_rn(v.z);
        Wh[(c0 + 3) * HSTR + k] = __float2half_rn(v.w);
    }
}
__device__ __forceinline__ uint2 f4_to_h4(float4 v) {
    __half2 h01 = __floats2half2_rn(v.x, v.y);
    __half2 h23 = __floats2half2_rn(v.z, v.w);
    uint2 u;
    u.x = *reinterpret_cast<uint32_t*>(&h01);
    u.y = *reinterpret_cast<uint32_t*>(&h23);
    return u;
}
__device__ __forceinline__ float2 h2f(uint32_t u) {
    return __half22float2(*reinterpret_cast<__half2*>(&u));
}

// ---------------- gemm_mma (fp16): Y(fp32) = op(X@W (+bias) (+Y)) ----------------
// X is fp32 unless GM_XHALF (then raw fp16, copied bit-exact into tile)
#define GEMM_SMEM (13184 * 4)
#define GM_BIAS 1
#define GM_ACC 2
#define GM_SILU 4
#define GM_XHALF 8

__global__ void __launch_bounds__(256, 2)
gemm_mma(const void* __restrict__ X, const float* __restrict__ W,
         const float* __restrict__ bias, float* __restrict__ Y, int mode) {
    extern __shared__ float sm[];
    __half* Wh = reinterpret_cast<__half*>(sm);
    __half* Xh = reinterpret_cast<__half*>(sm + 8704);
    float* bs = sm + 13056;
    int tid = threadIdx.x;

    load_w_trans_h(W, Wh, tid, 256);
    if (tid < 128) bs[tid] = (mode & GM_BIAS) ? bias[tid] : 0.0f;
    __syncthreads();

    uint32_t XA = smem_u32(Xh), WA = smem_u32(Wh);
    int L = tid & 31, w = tid >> 5;
    int mw = w & 1, nwg = w >> 1;
    uint32_t aBase0 = XA + (uint32_t)(mw * 32 + (L & 15)) * (HSTR * 2) + (uint32_t)(L >> 4) * 16;
    uint32_t bOffH[2];
#pragma unroll
    for (int jp = 0; jp < 2; jp++)
        bOffH[jp] = WA + (uint32_t)(nwg * 32 + jp * 16 + (L >> 4) * 8 + (L & 7)) * (HSTR * 2)
                  + (uint32_t)((L >> 3) & 1) * 16;

    for (int tile = blockIdx.x; tile < NT_N; tile += gridDim.x) {
        int r0 = tile * 64;
        if (mode & GM_XHALF) {
            const __half* Xg = (const __half*)X;
            for (int idx = tid; idx < 2048; idx += 256) {
                int r = idx >> 5, k4 = (idx & 31) * 4;
                int gr = r0 + r;
                uint2 u = make_uint2(0u, 0u);
                if (gr < N_NODES) u = *reinterpret_cast<const uint2*>(&Xg[gr * HID + k4]);
                *reinterpret_cast<uint2*>(&Xh[r * HSTR + k4]) = u;
            }
        } else {
            const float* Xg = (const float*)X;
            for (int idx = tid; idx < 2048; idx += 256) {
                int r = idx >> 5, k4 = (idx & 31) * 4;
                int gr = r0 + r;
                float4 v = make_float4(0.f, 0.f, 0.f, 0.f);
                if (gr < N_NODES) v = *reinterpret_cast<const float4*>(&Xg[gr * HID + k4]);
                *reinterpret_cast<uint2*>(&Xh[r * HSTR + k4]) = f4_to_h4(v);
            }
        }
        __syncthreads();

        float acc[2][4][4];
#pragma unroll
        for (int i = 0; i < 2; i++)
#pragma unroll
            for (int j = 0; j < 4; j++)
#pragma unroll
                for (int e = 0; e < 4; e++) acc[i][j][e] = 0.0f;

#pragma unroll
        for (int kc = 0; kc < 8; kc++) {
            uint32_t a0[4], a1[4];
            ldsm_x4(a0, aBase0 + kc * 32);
            ldsm_x4(a1, aBase0 + 16 * (HSTR * 2) + kc * 32);
#pragma unroll
            for (int jp = 0; jp < 2; jp++) {
                uint32_t b4[4];
                ldsm_x4(b4, bOffH[jp] + kc * 32);
                mma_f16(acc[0][jp * 2 + 0], a0, b4 + 0);
                mma_f16(acc[1][jp * 2 + 0], a1, b4 + 0);
                mma_f16(acc[0][jp * 2 + 1], a0, b4 + 2);
                mma_f16(acc[1][jp * 2 + 1], a1, b4 + 2);
            }
        }

#pragma unroll
        for (int i = 0; i < 2; i++) {
#pragma unroll
            for (int half = 0; half < 2; half++) {
                int gr = r0 + mw * 32 + i * 16 + half * 8 + (L >> 2);
                if (gr < N_NODES) {
#pragma unroll
                    for (int j = 0; j < 4; j++) {
                        int c = nwg * 32 + j * 8 + (L & 3) * 2;
                        float2 res;
                        res.x = acc[i][j][half * 2 + 0] + bs[c];
                        res.y = acc[i][j][half * 2 + 1] + bs[c + 1];
                        float* yp = &Y[gr * HID + c];
                        if (mode & GM_ACC) {
                            float2 o = *reinterpret_cast<float2*>(yp);
                            res.x += o.x; res.y += o.y;
                        }
                        if (mode & GM_SILU) { res.x = silu_f(res.x); res.y = silu_f(res.y); }
                        *reinterpret_cast<float2*>(yp) = res;
                    }
                }
            }
        }
        __syncthreads();
    }
}

// ---------------- gemm_ab (fp16): Y1h = X@Wa + b, Y2h = X@Wb (fp16 outputs) ----------------
#define AB_SMEM (21888 * 4)

__global__ void __launch_bounds__(256, 2)
gemm_ab(const float* __restrict__ X, const float* __restrict__ Wa, const float* __restrict__ Wb,
        const float* __restrict__ bias, __half* __restrict__ Y1, __half* __restrict__ Y2) {
    extern __shared__ float sm[];
    __half* Wh = reinterpret_cast<__half*>(sm);
    __half* Xh = reinterpret_cast<__half*>(sm + 17408);
    float* bs = sm + 21760;
    int tid = threadIdx.x;

    load_w_trans_h(Wa, Wh, tid, 256);
    load_w_trans_h(Wb, Wh + 128 * HSTR, tid, 256);
    if (tid < 128) bs[tid] = bias[tid];
    __syncthreads();

    uint32_t XA = smem_u32(Xh), WA = smem_u32(Wh);
    int L = tid & 31, w = tid >> 5;
    int mw = w & 1, nwg = w >> 1;
    uint32_t aBase0 = XA + (uint32_t)(mw * 32 + (L & 15)) * (HSTR * 2) + (uint32_t)(L >> 4) * 16;
    uint32_t bOffH[4];
#pragma unroll
    for (int jp = 0; jp < 4; jp++) {
        int base = (jp < 2) ? (nwg * 32 + jp * 16) : (128 + nwg * 32 + (jp - 2) * 16);
        bOffH[jp] = WA + (uint32_t)(base + (L >> 4) * 8 + (L & 7)) * (HSTR * 2)
                  + (uint32_t)((L >> 3) & 1) * 16;
    }

    for (int tile = blockIdx.x; tile < NT_N; tile += gridDim.x) {
        int r0 = tile * 64;
        for (int idx = tid; idx < 2048; idx += 256) {
            int r = idx >> 5, k4 = (idx & 31) * 4;
            int gr = r0 + r;
            float4 v = make_float4(0.f, 0.f, 0.f, 0.f);
            if (gr < N_NODES) v = *reinterpret_cast<const float4*>(&X[gr * HID + k4]);
            *reinterpret_cast<uint2*>(&Xh[r * HSTR + k4]) = f4_to_h4(v);
        }
        __syncthreads();

        float acc[2][8][4];
#pragma unroll
        for (int i = 0; i < 2; i++)
#pragma unroll
            for (int j = 0; j < 8; j++)
#pragma unroll
                for (int e = 0; e < 4; e++) acc[i][j][e] = 0.0f;

#pragma unroll
        for (int kc = 0; kc < 8; kc++) {
            uint32_t a0[4], a1[4];
            ldsm_x4(a0, aBase0 + kc * 32);
            ldsm_x4(a1, aBase0 + 16 * (HSTR * 2) + kc * 32);
#pragma unroll
            for (int jp = 0; jp < 4; jp++) {
                uint32_t b4[4];
                ldsm_x4(b4, bOffH[jp] + kc * 32);
                mma_f16(acc[0][jp * 2 + 0], a0, b4 + 0);
                mma_f16(acc[1][jp * 2 + 0], a1, b4 + 0);
                mma_f16(acc[0][jp * 2 + 1], a0, b4 + 2);
                mma_f16(acc[1][jp * 2 + 1], a1, b4 + 2);
            }
        }

#pragma unroll
        for (int i = 0; i < 2; i++) {
#pragma unroll
            for (int half = 0; half < 2; half++) {
                int gr = r0 + mw * 32 + i * 16 + half * 8 + (L >> 2);
                if (gr < N_NODES) {
#pragma unroll
                    for (int j = 0; j < 8; j++) {
                        int c = nwg * 32 + (j & 3) * 8 + (L & 3) * 2;
                        float rx = acc[i][j][half * 2 + 0];
                        float ry = acc[i][j][half * 2 + 1];
                        if (j < 4) {
                            __half2 hv = __floats2half2_rn(rx + bs[c], ry + bs[c + 1]);
                            *reinterpret_cast<__half2*>(&Y1[gr * HID + c]) = hv;
                        } else {
                            __half2 hv = __floats2half2_rn(rx, ry);
                            *reinterpret_cast<__half2*>(&Y2[gr * HID + c]) = hv;
                        }
                    }
                }
            }
        }
        __syncthreads();
    }
}

// ---------------- gemm_k256 (fp16): Yh = silu([X1, X2]@W + b), clears X2 ----------------
#define K256_SMEM (25472 * 4)

__global__ void __launch_bounds__(256, 2)
gemm_k256(const float* __restrict__ X1, float* __restrict__ X2,
          const float* __restrict__ W, const float* __restrict__ bias, __half* __restrict__ Y) {
    extern __shared__ float sm[];
    __half* Wh = reinterpret_cast<__half*>(sm);
    __half* Xh = reinterpret_cast<__half*>(sm + 16896);
    float* bs = sm + 25344;
    int tid = threadIdx.x;

    for (int idx = tid; idx < 8192; idx += 256) {
        int k = idx >> 5, c0 = (idx & 31) * 4;
        float4 v = reinterpret_cast<const float4*>(W)[idx];
        Wh[(c0 + 0) * KSTR + k] = __float2half_rn(v.x);
        Wh[(c0 + 1) * KSTR + k] = __float2half_rn(v.y);
        Wh[(c0 + 2) * KSTR + k] = __float2half_rn(v.z);
        Wh[(c0 + 3) * KSTR + k] = __float2half_rn(v.w);
    }
    if (tid < 128) bs[tid] = bias[tid];
    __syncthreads();

    uint32_t XA = smem_u32(Xh), WA = smem_u32(Wh);
    int L = tid & 31, w = tid >> 5;
    int mw = w & 1, nwg = w >> 1;
    uint32_t aBase0 = XA + (uint32_t)(mw * 32 + (L & 15)) * (KSTR * 2) + (uint32_t)(L >> 4) * 16;
    uint32_t bOffH[2];
#pragma unroll
    for (int jp = 0; jp < 2; jp++)
        bOffH[jp] = WA + (uint32_t)(nwg * 32 + jp * 16 + (L >> 4) * 8 + (L & 7)) * (KSTR * 2)
                  + (uint32_t)((L >> 3) & 1) * 16;

    for (int tile = blockIdx.x; tile < NT_N; tile += gridDim.x) {
        int r0 = tile * 64;
        for (int idx = tid; idx < 2048; idx += 256) {
            int r = idx >> 5, k4 = (idx & 31) * 4;
            int gr = r0 + r;
            float4 v1 = make_float4(0.f, 0.f, 0.f, 0.f);
            float4 v2 = make_float4(0.f, 0.f, 0.f, 0.f);
            if (gr < N_NODES) {
                v1 = *reinterpret_cast<const float4*>(&X1[gr * HID + k4]);
                v2 = *reinterpret_cast<float4*>(&X2[gr * HID + k4]);
                *reinterpret_cast<float4*>(&X2[gr * HID + k4]) = make_float4(0.f, 0.f, 0.f, 0.f);
            }
            *reinterpret_cast<uint2*>(&Xh[r * KSTR + k4]) = f4_to_h4(v1);
            *reinterpret_cast<uint2*>(&Xh[r * KSTR + 128 + k4]) = f4_to_h4(v2);
        }
        __syncthreads();

        float acc[2][4][4];
#pragma unroll
        for (int i = 0; i < 2; i++)
#pragma unroll
            for (int j = 0; j < 4; j++)
#pragma unroll
                for (int e = 0; e < 4; e++) acc[i][j][e] = 0.0f;

#pragma unroll
        for (int kc = 0; kc < 16; kc++) {
            uint32_t a0[4], a1[4];
            ldsm_x4(a0, aBase0 + kc * 32);
            ldsm_x4(a1, aBase0 + 16 * (KSTR * 2) + kc * 32);
#pragma unroll
            for (int jp = 0; jp < 2; jp++) {
                uint32_t b4[4];
                ldsm_x4(b4, bOffH[jp] + kc * 32);
                mma_f16(acc[0][jp * 2 + 0], a0, b4 + 0);
                mma_f16(acc[1][jp * 2 + 0], a1, b4 + 0);
                mma_f16(acc[0][jp * 2 + 1], a0, b4 + 2);
                mma_f16(acc[1][jp * 2 + 1], a1, b4 + 2);
            }
        }

#pragma unroll
        for (int i = 0; i < 2; i++) {
#pragma unroll
            for (int half = 0; half < 2; half++) {
                int gr = r0 + mw * 32 + i * 16 + half * 8 + (L >> 2);
                if (gr < N_NODES) {
#pragma unroll
                    for (int j = 0; j < 4; j++) {
                        int c = nwg * 32 + j * 8 + (L & 3) * 2;
                        __half2 hv = __floats2half2_rn(
                            silu_f(acc[i][j][half * 2 + 0] + bs[c]),
                            silu_f(acc[i][j][half * 2 + 1] + bs[c + 1]));
                        *reinterpret_cast<__half2*>(&Y[gr * HID + c]) = hv;
                    }
                }
            }
        }
        __syncthreads();
    }
}

// ---------------- edge kernel: fp16 MMA, 4 x 128-thread groups ----------------
#define EDGE_SMEM (27776 * 4)

__global__ void __launch_bounds__(512, 1)
edge_mma(const float* __restrict__ W2, const float* __restrict__ b2,
         const float* __restrict__ Wc1, const float* __restrict__ bc1,
         const float* __restrict__ wc2,
         const float* __restrict__ wr, const float* __restrict__ we) {
    extern __shared__ float sm[];
    __half* W2h = reinterpret_cast<__half*>(sm);
    __half* Wc1h = reinterpret_cast<__half*>(sm + 8704);
    float* b2s = sm + 26112;
    float* bc1s = sm + 26240;
    float* wc2s = sm + 26368;
    float* wrs = sm + 26496;
    float* wes = sm + 26624;

    int tid = threadIdx.x;
    load_w_trans_h(W2, W2h, tid, 512);
    load_w_trans_h(Wc1, Wc1h, tid, 512);
    if (tid < 128) {
        b2s[tid] = b2[tid]; bc1s[tid] = bc1[tid]; wc2s[tid] = wc2[tid];
        wrs[tid] = wr[tid]; wes[tid] = we[tid];
    }
    __syncthreads();

    int g = tid >> 7;
    int gtid = tid & 127;
    int barid = 1 + g;

    __half* tSh = reinterpret_cast<__half*>(sm + 17408) + g * (32 * HSTR);
    float* diffs = sm + 26752 + g * 96;
    float* cw_part = sm + 27136 + g * 128;
    int* rows_s = (int*)(sm + 27648) + g * 32;

    uint32_t tSA = smem_u32(tSh);
    uint32_t W2A = smem_u32(W2h), Wc1A = smem_u32(Wc1h);
    int L = gtid & 31, w = gtid >> 5;
    int nwg = w;
    uint32_t aOffH = (uint32_t)(L & 15) * (HSTR * 2) + (uint32_t)(L >> 4) * 16;
    uint32_t bOffH[2];
#pragma unroll
    for (int jp = 0; jp < 2; jp++)
        bOffH[jp] = (uint32_t)((nwg * 32 + jp * 16 + (L >> 4) * 8 + (L & 7))) * (HSTR * 2)
                  + (uint32_t)((L >> 3) & 1) * 16;

    int e_loc = gtid >> 2, q = gtid & 3;

    for (int tile = blockIdx.x * 4 + g; tile < NT_E32; tile += gridDim.x * 4) {
        int e0 = tile * 32;
        {
            int e = e0 + e_loc;
            int r = d_erow[e], c = d_ecol[e];
            float dx = d_coord[r * 3 + 0] - d_coord[c * 3 + 0];
            float dy = d_coord[r * 3 + 1] - d_coord[c * 3 + 1];
            float dz = d_coord[r * 3 + 2] - d_coord[c * 3 + 2];
            float radial = dx * dx + dy * dy + dz * dz;
            float eav = d_eea[e];
            if (q == 0) {
                rows_s[e_loc] = r;
                diffs[e_loc * 3 + 0] = dx; diffs[e_loc * 3 + 1] = dy; diffs[e_loc * 3 + 2] = dz;
            }
#pragma unroll
            for (int jj = 0; jj < 8; jj++) {
                int ch = jj * 16 + q * 4;
                uint2 ua = *reinterpret_cast<const uint2*>(&d_Ah[r * HID + ch]);
                uint2 ub = *reinterpret_cast<const uint2*>(&d_Bh[c * HID + ch]);
                float2 a01 = h2f(ua.x), a23 = h2f(ua.y);
                float2 b01 = h2f(ub.x), b23 = h2f(ub.y);
                float4 w1 = *reinterpret_cast<const float4*>(&wrs[ch]);
                float4 w2v = *reinterpret_cast<const float4*>(&wes[ch]);
                float4 t;
                t.x = silu_f(a01.x + b01.x + radial * w1.x + eav * w2v.x);
                t.y = silu_f(a01.y + b01.y + radial * w1.y + eav * w2v.y);
                t.z = silu_f(a23.x + b23.x + radial * w1.z + eav * w2v.z);
                t.w = silu_f(a23.y + b23.y + radial * w1.w + eav * w2v.w);
                *reinterpret_cast<uint2*>(&tSh[e_loc * HSTR + ch]) = f4_to_h4(t);
            }
        }
        GBAR(barid, 128);

        // ---- MMA1 ----
        float acc[2][4][4];
#pragma unroll
        for (int i = 0; i < 2; i++)
#pragma unroll
            for (int j = 0; j < 4; j++)
#pragma unroll
                for (int e = 0; e < 4; e++) acc[i][j][e] = 0.0f;
#pragma unroll
        for (int kc = 0; kc < 8; kc++) {
            uint32_t a0[4], a1[4];
            ldsm_x4(a0, tSA + aOffH + kc * 32);
            ldsm_x4(a1, tSA + aOffH + 16 * (HSTR * 2) + kc * 32);
#pragma unroll
            for (int jp = 0; jp < 2; jp++) {
                uint32_t b4[4];
                ldsm_x4(b4, W2A + bOffH[jp] + kc * 32);
                mma_f16(acc[0][jp * 2 + 0], a0, b4 + 0);
                mma_f16(acc[1][jp * 2 + 0], a1, b4 + 0);
                mma_f16(acc[0][jp * 2 + 1], a0, b4 + 2);
                mma_f16(acc[1][jp * 2 + 1], a1, b4 + 2);
            }
        }

        // ---- epilogue1 ----
#pragma unroll
        for (int i = 0; i < 2; i++) {
#pragma unroll
            for (int half = 0; half < 2; half++) {
                int rowl = i * 16 + half * 8 + (L >> 2);
#pragma unroll
                for (int j = 0; j < 4; j++) {
                    int c = nwg * 32 + j * 8 + (L & 3) * 2;
                    __half2 mh = __floats2half2_rn(
                        silu_f(acc[i][j][half * 2 + 0] + b2s[c]),
                        silu_f(acc[i][j][half * 2 + 1] + b2s[c + 1]));
                    *reinterpret_cast<__half2*>(&tSh[rowl * HSTR + c]) = mh;
                }
            }
        }
        GBAR(barid, 128);

        // ---- segmented magg scatter ----
        {
            int ch = gtid;
            float accm = 0.0f;
            int prev = rows_s[0];
#pragma unroll 4
            for (int el = 0; el < 32; el++) {
                int rn = rows_s[el];
                float mv = __half2float(tSh[el * HSTR + ch]);
                if (rn != prev) {
                    atomicAdd(&d_magg[prev * HID + ch], accm);
                    accm = 0.0f;
                    prev = rn;
                }
                accm += mv;
            }
            atomicAdd(&d_magg[prev * HID + ch], accm);
        }

        // ---- MMA2 ----
#pragma unroll
        for (int i = 0; i < 2; i++)
#pragma unroll
            for (int j = 0; j < 4; j++)
#pragma unroll
                for (int e = 0; e < 4; e++) acc[i][j][e] = 0.0f;
#pragma unroll
        for (int kc = 0; kc < 8; kc++) {
            uint32_t a0[4], a1[4];
            ldsm_x4(a0, tSA + aOffH + kc * 32);
            ldsm_x4(a1, tSA + aOffH + 16 * (HSTR * 2) + kc * 32);
#pragma unroll
            for (int jp = 0; jp < 2; jp++) {
                uint32_t b4[4];
                ldsm_x4(b4, Wc1A + bOffH[jp] + kc * 32);
                mma_f16(acc[0][jp * 2 + 0], a0, b4 + 0);
                mma_f16(acc[1][jp * 2 + 0], a1, b4 + 0);
                mma_f16(acc[0][jp * 2 + 1], a0, b4 + 2);
                mma_f16(acc[1][jp * 2 + 1], a1, b4 + 2);
            }
        }

        // ---- epilogue2 ----
#pragma unroll
        for (int i = 0; i < 2; i++) {
#pragma unroll
            for (int half = 0; half < 2; half++) {
                float p = 0.0f;
#pragma unroll
                for (int j = 0; j < 4; j++) {
                    int c = nwg * 32 + j * 8 + (L & 3) * 2;
                    p += silu_f(acc[i][j][half * 2 + 0] + bc1s[c]) * wc2s[c];
                    p += silu_f(acc[i][j][half * 2 + 1] + bc1s[c + 1]) * wc2s[c + 1];
                }
                p += __shfl_xor_sync(0xffffffff, p, 1);
                p += __shfl_xor_sync(0xffffffff, p, 2);
                if ((L & 3) == 0) {
                    int rowl = i * 16 + half * 8 + (L >> 2);
                    cw_part[nwg * 32 + rowl] = p;
                }
            }
        }
        GBAR(barid, 128);
        if (gtid < 32) {
            int rn = rows_s[gtid];
            float cw = cw_part[gtid] + cw_part[32 + gtid] + cw_part[64 + gtid] + cw_part[96 + gtid];
            atomicAdd(&d_cagg[rn * 3 + 0], diffs[gtid * 3 + 0] * cw);
            atomicAdd(&d_cagg[rn * 3 + 1], diffs[gtid * 3 + 1] * cw);
            atomicAdd(&d_cagg[rn * 3 + 2], diffs[gtid * 3 + 2] * cw);
        }
        GBAR(barid, 128);
    }
}

// ---------------- coord update ----------------
__global__ void coord_kernel() {
    int n = blockIdx.x * blockDim.x + threadIdx.x;
    if (n < N_NODES) {
        float inv = 1.0f / fmaxf((float)d_cnt[n], 1.0f);
#pragma unroll
        for (int dd = 0; dd < 3; dd++) {
            d_coord[n * 3 + dd] += d_cagg[n * 3 + dd] * inv;
            d_cagg[n * 3 + dd] = 0.0f;
        }
    }
}

// ---------------- global mean pool (reads emb_out result in d_magg) ----------------
__global__ void pool_kernel(const int* __restrict__ batch) {
    int n0 = blockIdx.x * 512;
    int ch = threadIdx.x;
    if (n0 >= N_NODES) return;
    int nend = min(n0 + 512, N_NODES);
    int cur = batch[n0];
    float acc = 0.0f, cnt = 0.0f;
    for (int n = n0; n < nend; n++) {
        int g = batch[n];
        if (g != cur) {
            atomicAdd(&d_gsum[cur * HID + ch], acc);
            if (ch == 0) atomicAdd(&d_gcnt[cur], cnt);
            acc = 0.0f; cnt = 0.0f; cur = g;
        }
        acc += d_magg[n * HID + ch];
        cnt += 1.0f;
    }
    atomicAdd(&d_gsum[cur * HID + ch], acc);
    if (ch == 0) atomicAdd(&d_gcnt[cur], cnt);
}

// ---------------- final fc ----------------
__global__ void fc_kernel(const float* __restrict__ fcw, const float* __restrict__ fcb,
                          float* __restrict__ out) {
    int g = blockIdx.x;
    int ch = threadIdx.x;
    float inv = 1.0f / fmaxf(d_gcnt[g], 1.0f);
    float acc = fcb[ch];
    for (int k = 0; k < HID; k++)
        acc += d_gsum[g * HID + k] * inv * fcw[k * OUT_DIM + ch];
    out[g * OUT_DIM + ch] = acc;
}

// ---------------- launch ----------------
#define GRID_G 296
#define GRID_E 148

extern "C" void kernel_launch(void* const* d_in, const int* in_sizes, int n_in,
                              void* d_out, int out_size) {
    const float* x = (const float*)d_in[0];
    const int* eidx = (const int*)d_in[1];
    const float* coord = (const float*)d_in[2];
    const float* ea = (const float*)d_in[3];
    const int* batch = (const int*)d_in[4];
    const float* emb_in_w = (const float*)d_in[5];
    const float* emb_in_b = (const float*)d_in[6];
    const float* edge_w1 = (const float*)d_in[7];
    const float* edge_b1 = (const float*)d_in[8];
    const float* edge_w2 = (const float*)d_in[9];
    const float* edge_b2 = (const float*)d_in[10];
    const float* node_w1 = (const float*)d_in[11];
    const float* node_b1 = (const float*)d_in[12];
    const float* node_w2 = (const float*)d_in[13];
    const float* node_b2 = (const float*)d_in[14];
    const float* coord_w1 = (const float*)d_in[15];
    const float* coord_b1 = (const float*)d_in[16];
    const float* coord_w2 = (const float*)d_in[17];
    const float* emb_out_w = (const float*)d_in[18];
    const float* emb_out_b = (const float*)d_in[19];
    const float* fc_w = (const float*)d_in[20];
    const float* fc_b = (const float*)d_in[21];
    float* out = (float*)d_out;

    const int* row = eidx;
    const int* col = eidx + N_EDGES;

    float *ph, *pmagg;
    __half *pAh, *pBh, *pTh;
    cudaGetSymbolAddress((void**)&ph, d_h);
    cudaGetSymbolAddress((void**)&pAh, d_Ah);
    cudaGetSymbolAddress((void**)&pBh, d_Bh);
    cudaGetSymbolAddress((void**)&pTh, d_Th);
    cudaGetSymbolAddress((void**)&pmagg, d_magg);

    cudaFuncSetAttribute(edge_mma, cudaFuncAttributeMaxDynamicSharedMemorySize, EDGE_SMEM);
    cudaFuncSetAttribute(gemm_mma, cudaFuncAttributeMaxDynamicSharedMemorySize, GEMM_SMEM);
    cudaFuncSetAttribute(gemm_ab, cudaFuncAttributeMaxDynamicSharedMemorySize, AB_SMEM);
    cudaFuncSetAttribute(gemm_k256, cudaFuncAttributeMaxDynamicSharedMemorySize, K256_SMEM);

    // ---- pre-pass: counting sort of edges by destination row ----
    init_kernel<<<(N_NODES * HID + 255) / 256, 256>>>(coord);
    hist_kernel<<<(N_EDGES + 255) / 256, 256>>>(row);
    scan1_kernel<<<SCAN_B, 512>>>();
    scan2_kernel<<<1, 32>>>();
    scan3_kernel<<<(N_NODES + 255) / 256, 256>>>();
    scatter_kernel<<<(N_EDGES + 255) / 256, 256>>>(row, col, ea);
    emb_in_kernel<<<(N_NODES * HID + 255) / 256, 256>>>(x, emb_in_w, emb_in_b);

    for (int l = 0; l < N_LAYERS; l++) {
        const float* W1 = edge_w1 + l * 258 * HID;
        gemm_ab<<<GRID_G, 256, AB_SMEM>>>(ph, W1, W1 + 128 * HID, edge_b1 + l * HID, pAh, pBh);
        edge_mma<<<GRID_E, 512, EDGE_SMEM>>>(
            edge_w2 + l * HID * HID, edge_b2 + l * HID,
            coord_w1 + l * HID * HID, coord_b1 + l * HID, coord_w2 + l * HID,
            W1 + 256 * HID, W1 + 257 * HID);
        coord_kernel<<<(N_NODES + 255) / 256, 256>>>();
        gemm_k256<<<GRID_G, 256, K256_SMEM>>>(ph, pmagg, node_w1 + l * 256 * HID,
                                              node_b1 + l * HID, pTh);
        gemm_mma<<<GRID_G, 256, GEMM_SMEM>>>(pTh, node_w2 + l * HID * HID,
                                             node_b2 + l * HID, ph,
                                             GM_BIAS | GM_ACC | GM_XHALF);
    }

    // emb_out result -> d_magg (fp32, free after last k256 cleared it)
    gemm_mma<<<GRID_G, 256, GEMM_SMEM>>>(ph, emb_out_w, emb_out_b, pmagg, GM_BIAS);
    pool_kernel<<<(N_NODES + 511) / 512, 128>>>(batch);
    fc_kernel<<<N_GRAPHS, 256>>>(fc_w, fc_b, out);
}